// round 1
// baseline (speedup 1.0000x reference)
#include <cuda_runtime.h>
#include <cuda_bf16.h>
#include <math.h>
#include <float.h>

// Problem constants
#define BATCH 2
#define SEQ   2048
#define TOK   (BATCH*SEQ)        // 4096
#define EMB   1024
#define HEADS 16
#define HD    64
#define FF    4096

// -------------------- scratch (device globals; no allocation) --------------------
__device__ float g_h  [TOK*EMB];   // LN output (reused ln1/ln2)
__device__ float g_q  [TOK*EMB];
__device__ float g_k  [TOK*EMB];
__device__ float g_v  [TOK*EMB];
__device__ float g_ctx[TOK*EMB];
__device__ float g_x1 [TOK*EMB];   // x + attn_out
__device__ float g_mid[TOK*FF];    // FFN intermediate

// -------------------- block reduce --------------------
__device__ __forceinline__ float block_reduce_sum(float v, float* sbuf) {
    #pragma unroll
    for (int o = 16; o > 0; o >>= 1) v += __shfl_xor_sync(0xffffffffu, v, o);
    int w = threadIdx.x >> 5;
    if ((threadIdx.x & 31) == 0) sbuf[w] = v;
    __syncthreads();
    if (threadIdx.x < 32) {
        float t = (threadIdx.x < 8) ? sbuf[threadIdx.x] : 0.0f;
        #pragma unroll
        for (int o = 4; o > 0; o >>= 1) t += __shfl_xor_sync(0xffffffffu, t, o);
        if (threadIdx.x == 0) sbuf[0] = t;
    }
    __syncthreads();
    float r = sbuf[0];
    __syncthreads();
    return r;
}

// -------------------- LayerNorm: one block per token row --------------------
__global__ __launch_bounds__(256) void ln_kernel(
    const float* __restrict__ X, const float* __restrict__ scale,
    const float* __restrict__ shift, float* __restrict__ Y)
{
    __shared__ float sbuf[8];
    const int row = blockIdx.x;
    const float* x = X + (size_t)row * EMB;
    float* y = Y + (size_t)row * EMB;
    const int c0 = threadIdx.x * 4;

    float4 xv = *(const float4*)(x + c0);
    float s = xv.x + xv.y + xv.z + xv.w;
    float mean = block_reduce_sum(s, sbuf) * (1.0f / EMB);

    float dx = xv.x - mean, dy = xv.y - mean, dz = xv.z - mean, dw = xv.w - mean;
    float sq = dx*dx + dy*dy + dz*dz + dw*dw;
    float var = block_reduce_sum(sq, sbuf) * (1.0f / EMB);
    float rstd = rsqrtf(var + 1e-5f);

    float4 sc = *(const float4*)(scale + c0);
    float4 sh = *(const float4*)(shift + c0);
    float4 out;
    out.x = sc.x * dx * rstd + sh.x;
    out.y = sc.y * dy * rstd + sh.y;
    out.z = sc.z * dz * rstd + sh.z;
    out.w = sc.w * dw * rstd + sh.w;
    *(float4*)(y + c0) = out;
}

// -------------------- SGEMM 128x128x8, 256 threads, 8x8 per thread --------------------
// EPI: 0 = plain, 1 = bias + residual, 2 = bias + GELU(tanh)
template<int EPI>
__global__ __launch_bounds__(256) void sgemm_kernel(
    const float* __restrict__ A, const float* __restrict__ B,
    const float* __restrict__ bias, const float* __restrict__ res,
    float* __restrict__ C, int M, int N, int K)
{
    __shared__ float As[8][128];
    __shared__ float Bs[8][128];

    const int tid = threadIdx.x;
    const int bm = blockIdx.y, bn = blockIdx.x;

    // A tile load coords: 128 rows x 8 cols, float4 per thread
    const int a_r = tid >> 1;
    const int a_c = (tid & 1) * 4;
    // B tile load coords: 8 rows x 128 cols, float4 per thread
    const int b_r = tid >> 5;
    const int b_c = (tid & 31) * 4;

    const float* Ag = A + (size_t)(bm * 128 + a_r) * K + a_c;
    const float* Bg = B + (size_t)b_r * N + bn * 128 + b_c;

    const int tx = tid & 15;   // col group
    const int ty = tid >> 4;   // row group

    float acc[8][8];
    #pragma unroll
    for (int i = 0; i < 8; i++)
        #pragma unroll
        for (int j = 0; j < 8; j++) acc[i][j] = 0.0f;

    for (int k0 = 0; k0 < K; k0 += 8) {
        float4 av = *(const float4*)(Ag + k0);
        float4 bv = *(const float4*)(Bg + (size_t)k0 * N);
        As[a_c + 0][a_r] = av.x;
        As[a_c + 1][a_r] = av.y;
        As[a_c + 2][a_r] = av.z;
        As[a_c + 3][a_r] = av.w;
        *(float4*)&Bs[b_r][b_c] = bv;
        __syncthreads();

        #pragma unroll
        for (int kk = 0; kk < 8; kk++) {
            float a[8], b[8];
            float4 a0 = *(const float4*)&As[kk][ty * 8];
            float4 a1 = *(const float4*)&As[kk][ty * 8 + 4];
            float4 b0 = *(const float4*)&Bs[kk][tx * 8];
            float4 b1 = *(const float4*)&Bs[kk][tx * 8 + 4];
            a[0]=a0.x; a[1]=a0.y; a[2]=a0.z; a[3]=a0.w;
            a[4]=a1.x; a[5]=a1.y; a[6]=a1.z; a[7]=a1.w;
            b[0]=b0.x; b[1]=b0.y; b[2]=b0.z; b[3]=b0.w;
            b[4]=b1.x; b[5]=b1.y; b[6]=b1.z; b[7]=b1.w;
            #pragma unroll
            for (int i = 0; i < 8; i++)
                #pragma unroll
                for (int j = 0; j < 8; j++)
                    acc[i][j] = fmaf(a[i], b[j], acc[i][j]);
        }
        __syncthreads();
    }

    const int crow0 = bm * 128 + ty * 8;
    const int ccol0 = bn * 128 + tx * 8;
    #pragma unroll
    for (int i = 0; i < 8; i++) {
        const size_t roff = (size_t)(crow0 + i) * N + ccol0;
        #pragma unroll
        for (int j = 0; j < 8; j++) {
            float v = acc[i][j];
            if (EPI == 1) {
                v += bias[ccol0 + j] + res[roff + j];
            } else if (EPI == 2) {
                v += bias[ccol0 + j];
                const float cg = 0.7978845608028654f;
                float t = tanhf(cg * (v + 0.044715f * v * v * v));
                v = 0.5f * v * (1.0f + t);
            }
            C[roff + j] = v;
        }
    }
}

// -------------------- causal flash attention, fp32 --------------------
// grid: (SEQ/64, HEADS, BATCH), 256 threads. BR=BC=64, HD=64.
// smem: Qs[64][65], KPs[64][65] (K tile, then reused for P), Vs[64][64]
#define ATTN_SMEM ((64*65*2 + 64*64) * sizeof(float))

__global__ __launch_bounds__(256) void attn_kernel(
    const float* __restrict__ Q, const float* __restrict__ Kg,
    const float* __restrict__ Vg, float* __restrict__ O)
{
    extern __shared__ float sm[];
    float* Qs  = sm;               // 64*65
    float* KPs = sm + 64 * 65;     // 64*65
    float* Vs  = sm + 2 * 64 * 65; // 64*64

    const int qb = blockIdx.x;         // query block 0..31
    const int h  = blockIdx.y;
    const int b  = blockIdx.z;
    const int tid = threadIdx.x;
    const int tx = tid & 15;           // key-col / dim group (4 each)
    const int ty = tid >> 4;           // query-row group (4 each)

    const size_t base = (size_t)b * SEQ * EMB + (size_t)h * HD;

    // load Q tile (64 rows x 64 dims)
    for (int i = tid; i < 64 * 16; i += 256) {
        int r = i >> 4, c4 = (i & 15) * 4;
        float4 v = *(const float4*)(Q + base + (size_t)(qb * 64 + r) * EMB + c4);
        Qs[r * 65 + c4 + 0] = v.x;
        Qs[r * 65 + c4 + 1] = v.y;
        Qs[r * 65 + c4 + 2] = v.z;
        Qs[r * 65 + c4 + 3] = v.w;
    }

    float m_r[4], l_r[4], o[4][4];
    #pragma unroll
    for (int i = 0; i < 4; i++) {
        m_r[i] = -FLT_MAX; l_r[i] = 0.0f;
        #pragma unroll
        for (int j = 0; j < 4; j++) o[i][j] = 0.0f;
    }

    for (int jb = 0; jb <= qb; jb++) {
        // load K tile (padded) and V tile
        for (int i = tid; i < 64 * 16; i += 256) {
            int r = i >> 4, c4 = (i & 15) * 4;
            float4 kv = *(const float4*)(Kg + base + (size_t)(jb * 64 + r) * EMB + c4);
            KPs[r * 65 + c4 + 0] = kv.x;
            KPs[r * 65 + c4 + 1] = kv.y;
            KPs[r * 65 + c4 + 2] = kv.z;
            KPs[r * 65 + c4 + 3] = kv.w;
            float4 vv = *(const float4*)(Vg + base + (size_t)(jb * 64 + r) * EMB + c4);
            *(float4*)&Vs[r * 64 + c4] = vv;
        }
        __syncthreads();

        // S = Q @ K^T  (each thread: 4 rows x 4 cols)
        float s[4][4];
        #pragma unroll
        for (int i = 0; i < 4; i++)
            #pragma unroll
            for (int j = 0; j < 4; j++) s[i][j] = 0.0f;

        #pragma unroll 4
        for (int d = 0; d < 64; d++) {
            float a[4], bk[4];
            #pragma unroll
            for (int i = 0; i < 4; i++) a[i]  = Qs[(ty * 4 + i) * 65 + d];
            #pragma unroll
            for (int j = 0; j < 4; j++) bk[j] = KPs[(tx * 4 + j) * 65 + d];
            #pragma unroll
            for (int i = 0; i < 4; i++)
                #pragma unroll
                for (int j = 0; j < 4; j++)
                    s[i][j] = fmaf(a[i], bk[j], s[i][j]);
        }

        // scale + causal mask
        #pragma unroll
        for (int i = 0; i < 4; i++)
            #pragma unroll
            for (int j = 0; j < 4; j++) {
                s[i][j] *= 0.125f;   // 1/sqrt(64)
                if (jb == qb) {
                    int qg = qb * 64 + ty * 4 + i;
                    int kg = jb * 64 + tx * 4 + j;
                    if (kg > qg) s[i][j] = -1e30f;
                }
            }

        __syncthreads();   // everyone done reading K before P overwrites KPs

        // online softmax per query row
        float p[4][4];
        #pragma unroll
        for (int i = 0; i < 4; i++) {
            float rm = fmaxf(fmaxf(s[i][0], s[i][1]), fmaxf(s[i][2], s[i][3]));
            #pragma unroll
            for (int off = 8; off > 0; off >>= 1)
                rm = fmaxf(rm, __shfl_xor_sync(0xffffffffu, rm, off));
            float mnew = fmaxf(m_r[i], rm);
            float alpha = expf(m_r[i] - mnew);
            float rs = 0.0f;
            #pragma unroll
            for (int j = 0; j < 4; j++) {
                p[i][j] = expf(s[i][j] - mnew);
                rs += p[i][j];
            }
            #pragma unroll
            for (int off = 8; off > 0; off >>= 1)
                rs += __shfl_xor_sync(0xffffffffu, rs, off);
            l_r[i] = l_r[i] * alpha + rs;
            m_r[i] = mnew;
            #pragma unroll
            for (int j = 0; j < 4; j++) o[i][j] *= alpha;
        }

        // stash P into KPs
        #pragma unroll
        for (int i = 0; i < 4; i++)
            #pragma unroll
            for (int j = 0; j < 4; j++)
                KPs[(ty * 4 + i) * 65 + tx * 4 + j] = p[i][j];
        __syncthreads();

        // O += P @ V
        #pragma unroll 4
        for (int c = 0; c < 64; c++) {
            float pv[4], vv[4];
            #pragma unroll
            for (int i = 0; i < 4; i++) pv[i] = KPs[(ty * 4 + i) * 65 + c];
            #pragma unroll
            for (int j = 0; j < 4; j++) vv[j] = Vs[c * 64 + tx * 4 + j];
            #pragma unroll
            for (int i = 0; i < 4; i++)
                #pragma unroll
                for (int j = 0; j < 4; j++)
                    o[i][j] = fmaf(pv[i], vv[j], o[i][j]);
        }
        __syncthreads();   // before next iteration reloads K/V
    }

    // write O / l
    #pragma unroll
    for (int i = 0; i < 4; i++) {
        float inv_l = 1.0f / l_r[i];
        const size_t roff = base + (size_t)(qb * 64 + ty * 4 + i) * EMB + tx * 4;
        #pragma unroll
        for (int j = 0; j < 4; j++)
            O[roff + j] = o[i][j] * inv_l;
    }
}

// -------------------- host launch --------------------
extern "C" void kernel_launch(void* const* d_in, const int* in_sizes, int n_in,
                              void* d_out, int out_size)
{
    const float* x    = (const float*)d_in[0];
    const float* Wq   = (const float*)d_in[1];
    const float* Wk   = (const float*)d_in[2];
    const float* Wv   = (const float*)d_in[3];
    const float* Wo   = (const float*)d_in[4];
    const float* bo   = (const float*)d_in[5];
    const float* W1   = (const float*)d_in[6];
    const float* b1   = (const float*)d_in[7];
    const float* W2   = (const float*)d_in[8];
    const float* b2   = (const float*)d_in[9];
    const float* ln1s = (const float*)d_in[10];
    const float* ln1b = (const float*)d_in[11];
    const float* ln2s = (const float*)d_in[12];
    const float* ln2b = (const float*)d_in[13];
    float* out = (float*)d_out;

    float *h, *q, *k, *v, *ctx, *x1, *mid;
    cudaGetSymbolAddress((void**)&h,   g_h);
    cudaGetSymbolAddress((void**)&q,   g_q);
    cudaGetSymbolAddress((void**)&k,   g_k);
    cudaGetSymbolAddress((void**)&v,   g_v);
    cudaGetSymbolAddress((void**)&ctx, g_ctx);
    cudaGetSymbolAddress((void**)&x1,  g_x1);
    cudaGetSymbolAddress((void**)&mid, g_mid);

    cudaFuncSetAttribute(attn_kernel, cudaFuncAttributeMaxDynamicSharedMemorySize,
                         (int)ATTN_SMEM);

    // 1) LN1
    ln_kernel<<<TOK, 256>>>(x, ln1s, ln1b, h);

    // 2) Q, K, V projections
    sgemm_kernel<0><<<dim3(EMB/128, TOK/128), 256>>>(h, Wq, nullptr, nullptr, q, TOK, EMB, EMB);
    sgemm_kernel<0><<<dim3(EMB/128, TOK/128), 256>>>(h, Wk, nullptr, nullptr, k, TOK, EMB, EMB);
    sgemm_kernel<0><<<dim3(EMB/128, TOK/128), 256>>>(h, Wv, nullptr, nullptr, v, TOK, EMB, EMB);

    // 3) causal attention
    attn_kernel<<<dim3(SEQ/64, HEADS, BATCH), 256, ATTN_SMEM>>>(q, k, v, ctx);

    // 4) output proj + bias + residual
    sgemm_kernel<1><<<dim3(EMB/128, TOK/128), 256>>>(ctx, Wo, bo, x, x1, TOK, EMB, EMB);

    // 5) LN2
    ln_kernel<<<TOK, 256>>>(x1, ln2s, ln2b, h);

    // 6) FFN up + GELU
    sgemm_kernel<2><<<dim3(FF/128, TOK/128), 256>>>(h, W1, b1, nullptr, mid, TOK, FF, EMB);

    // 7) FFN down + bias + residual -> final output
    sgemm_kernel<1><<<dim3(EMB/128, TOK/128), 256>>>(mid, W2, b2, x1, out, TOK, EMB, FF);
}

// round 4
// speedup vs baseline: 1.5662x; 1.5662x over previous
#include <cuda_runtime.h>
#include <cuda_bf16.h>
#include <math.h>
#include <float.h>
#include <stdint.h>

#define BATCH 2
#define SEQ   2048
#define TOK   (BATCH*SEQ)        // 4096
#define EMB   1024
#define HEADS 16
#define HD    64
#define FF    4096

typedef __nv_bfloat16 bf16;

// ==================== helpers ====================
__device__ __forceinline__ uint32_t smem_u32(const void* p) {
    uint32_t a;
    asm("{ .reg .u64 t; cvta.to.shared.u64 t, %1; cvt.u32.u64 %0, t; }" : "=r"(a) : "l"(p));
    return a;
}
#define SWZ(x) ((x) ^ (((x) >> 3) & 0x70))

__device__ __forceinline__ void ldsm_x4(uint32_t addr, uint32_t r[4]) {
    asm volatile("ldmatrix.sync.aligned.m8n8.x4.shared.b16 {%0,%1,%2,%3}, [%4];"
                 : "=r"(r[0]), "=r"(r[1]), "=r"(r[2]), "=r"(r[3]) : "r"(addr));
}
// NON-transposed x2: B tile stored [N][K] (K contiguous) already matches the
// mma.row.col B fragment (consecutive k in-register, n = t/4).
__device__ __forceinline__ void ldsm_x2(uint32_t addr, uint32_t r[2]) {
    asm volatile("ldmatrix.sync.aligned.m8n8.x2.shared.b16 {%0,%1}, [%2];"
                 : "=r"(r[0]), "=r"(r[1]) : "r"(addr));
}
__device__ __forceinline__ void mma_bf16(float c[4], const uint32_t a[4], const uint32_t b[2]) {
    asm volatile("mma.sync.aligned.m16n8k16.row.col.f32.bf16.bf16.f32 "
                 "{%0,%1,%2,%3}, {%4,%5,%6,%7}, {%8,%9}, {%0,%1,%2,%3};"
                 : "+f"(c[0]), "+f"(c[1]), "+f"(c[2]), "+f"(c[3])
                 : "r"(a[0]), "r"(a[1]), "r"(a[2]), "r"(a[3]), "r"(b[0]), "r"(b[1]));
}

__device__ __forceinline__ void split_bf16(float v, bf16& h, bf16& l) {
    h = __float2bfloat16(v);
    l = __float2bfloat16(v - __bfloat162float(h));
}
__device__ __forceinline__ float gelu_t(float v) {
    float t = tanhf(0.7978845608028654f * (v + 0.044715f * v * v * v));
    return 0.5f * v * (1.0f + t);
}

// ==================== scratch (device globals) ====================
__device__ bf16  g_hhi[TOK*EMB], g_hlo[TOK*EMB];
__device__ float g_q[TOK*EMB], g_k[TOK*EMB], g_v[TOK*EMB];
__device__ bf16  g_chi[TOK*EMB], g_clo[TOK*EMB];
__device__ float g_x1[TOK*EMB];
__device__ bf16  g_mhi[TOK*FF], g_mlo[TOK*FF];
__device__ bf16  g_wq_h[EMB*EMB], g_wq_l[EMB*EMB];
__device__ bf16  g_wk_h[EMB*EMB], g_wk_l[EMB*EMB];
__device__ bf16  g_wv_h[EMB*EMB], g_wv_l[EMB*EMB];
__device__ bf16  g_wo_h[EMB*EMB], g_wo_l[EMB*EMB];
__device__ bf16  g_w1_h[EMB*FF],  g_w1_l[EMB*FF];   // [N=FF][K=EMB]
__device__ bf16  g_w2_h[FF*EMB],  g_w2_l[FF*EMB];   // [N=EMB][K=FF]

// ==================== transpose + split: W[K][N] -> T{hi,lo}[N][K] ====================
__global__ __launch_bounds__(256) void transpose_split_kernel(
    const float* __restrict__ W, bf16* __restrict__ Th, bf16* __restrict__ Tl, int K, int N)
{
    __shared__ float t[32][33];
    int tx = threadIdx.x & 31, ty = threadIdx.x >> 5;   // 32 x 8
    int k0 = blockIdx.y * 32, n0 = blockIdx.x * 32;
    #pragma unroll
    for (int i = 0; i < 4; i++)
        t[ty + i*8][tx] = W[(size_t)(k0 + ty + i*8) * N + n0 + tx];
    __syncthreads();
    #pragma unroll
    for (int i = 0; i < 4; i++) {
        float v = t[tx][ty + i*8];
        bf16 h, l; split_bf16(v, h, l);
        size_t o = (size_t)(n0 + ty + i*8) * K + k0 + tx;
        Th[o] = h; Tl[o] = l;
    }
}

// ==================== block reduce ====================
__device__ __forceinline__ float block_reduce_sum(float v, float* sbuf) {
    #pragma unroll
    for (int o = 16; o > 0; o >>= 1) v += __shfl_xor_sync(0xffffffffu, v, o);
    int w = threadIdx.x >> 5;
    if ((threadIdx.x & 31) == 0) sbuf[w] = v;
    __syncthreads();
    if (threadIdx.x < 32) {
        float t = (threadIdx.x < 8) ? sbuf[threadIdx.x] : 0.0f;
        #pragma unroll
        for (int o = 4; o > 0; o >>= 1) t += __shfl_xor_sync(0xffffffffu, t, o);
        if (threadIdx.x == 0) sbuf[0] = t;
    }
    __syncthreads();
    float r = sbuf[0];
    __syncthreads();
    return r;
}

// ==================== LayerNorm -> bf16 hi/lo ====================
__global__ __launch_bounds__(256) void ln_split_kernel(
    const float* __restrict__ X, const float* __restrict__ scale,
    const float* __restrict__ shift, bf16* __restrict__ Yh, bf16* __restrict__ Yl)
{
    __shared__ float sbuf[8];
    const int row = blockIdx.x;
    const float* x = X + (size_t)row * EMB;
    const int c0 = threadIdx.x * 4;

    float4 xv = *(const float4*)(x + c0);
    float s = xv.x + xv.y + xv.z + xv.w;
    float mean = block_reduce_sum(s, sbuf) * (1.0f / EMB);
    float dx = xv.x - mean, dy = xv.y - mean, dz = xv.z - mean, dw = xv.w - mean;
    float var = block_reduce_sum(dx*dx + dy*dy + dz*dz + dw*dw, sbuf) * (1.0f / EMB);
    float rstd = rsqrtf(var + 1e-5f);

    float4 sc = *(const float4*)(scale + c0);
    float4 sh = *(const float4*)(shift + c0);
    float o0 = sc.x * dx * rstd + sh.x;
    float o1 = sc.y * dy * rstd + sh.y;
    float o2 = sc.z * dz * rstd + sh.z;
    float o3 = sc.w * dw * rstd + sh.w;
    bf16 h0,l0,h1,l1,h2,l2,h3,l3;
    split_bf16(o0,h0,l0); split_bf16(o1,h1,l1); split_bf16(o2,h2,l2); split_bf16(o3,h3,l3);
    size_t o = (size_t)row * EMB + c0;
    *(__nv_bfloat162*)(Yh + o)     = __nv_bfloat162(h0, h1);
    *(__nv_bfloat162*)(Yh + o + 2) = __nv_bfloat162(h2, h3);
    *(__nv_bfloat162*)(Yl + o)     = __nv_bfloat162(l0, l1);
    *(__nv_bfloat162*)(Yl + o + 2) = __nv_bfloat162(l2, l3);
}

// ==================== mma.sync split-bf16 GEMM ====================
// C[M][N] = (Ahi+Alo)[M][K] @ (Bhi+Blo)[N][K]^T (K-major operands)
// 3 passes: hi*hi + hi*lo + lo*hi. fp32 accumulate.
// CTA tile 128x128, K-chunk 64. 8 warps: 2(M) x 4(N), warp tile 64x32.
// EPI: 0 plain fp32; 1 +bias+res fp32; 2 +bias, GELU -> bf16 hi/lo
#define GEMM_SMEM 65536

template<int EPI>
__global__ __launch_bounds__(256)
void gemm_kernel(
    const bf16* __restrict__ Ahi, const bf16* __restrict__ Alo,
    const bf16* __restrict__ Bhi, const bf16* __restrict__ Blo,
    const float* __restrict__ bias, const float* __restrict__ res,
    float* __restrict__ C, bf16* __restrict__ Chi, bf16* __restrict__ Clo,
    int M, int N, int K)
{
    extern __shared__ char smraw[];
    const uint32_t sbase = smem_u32(smraw);
    const int tid = threadIdx.x;
    const int bm = blockIdx.y, bn = blockIdx.x;

    const int w = tid >> 5, lane = tid & 31;
    const int wm = w & 1, wn = w >> 1;           // warp tile: rows wm*64, cols wn*32

    // ldmatrix per-thread address components
    const int rowA = (lane & 7) + ((lane >> 3) & 1) * 8;   // row within m16 frag
    const int chA  = (lane >> 4) & 1;                      // k-chunk select (16B units)
    const int tt   = lane & 15;
    const int rowB = tt & 7;                               // row (n) within n8 frag
    const int chB  = tt >> 3;                              // k-halve select

    float acc[4][4][4];
    #pragma unroll
    for (int i = 0; i < 4; i++)
        #pragma unroll
        for (int j = 0; j < 4; j++)
            #pragma unroll
            for (int q = 0; q < 4; q++) acc[i][j][q] = 0.0f;

    const int nchunk = K >> 6;
    for (int c = 0; c < nchunk; ++c) {
        __syncthreads();
        // stage 4 tiles (Ahi,Alo rows=M-slab; Bhi,Blo rows=N-slab): 128 rows x 64 bf16, SW128
        #pragma unroll
        for (int tl = 0; tl < 4; ++tl) {
            const bf16* src = (tl == 0) ? Ahi : (tl == 1) ? Alo : (tl == 2) ? Bhi : Blo;
            const int rbase = (tl < 2) ? bm * 128 : bn * 128;
            #pragma unroll
            for (int j = 0; j < 4; ++j) {
                int idx = tid + j * 256;          // 0..1023
                int r = idx >> 3, seg = idx & 7;
                uint4 v = *(const uint4*)(src + (size_t)(rbase + r) * K + c * 64 + seg * 8);
                *(uint4*)(smraw + tl * 16384 + SWZ((uint32_t)(r * 128 + seg * 16))) = v;
            }
        }
        __syncthreads();

        #pragma unroll
        for (int ks = 0; ks < 4; ++ks) {
            uint32_t ah[4][4], al[4][4], bh[4][2], bl[4][2];
            // A-hi frags (4 m16 tiles)
            #pragma unroll
            for (int mi = 0; mi < 4; ++mi) {
                uint32_t off = (uint32_t)((wm * 64 + mi * 16 + rowA) * 128 + (ks * 2 + chA) * 16);
                ldsm_x4(sbase + SWZ(off), ah[mi]);
            }
            // B-hi frags (4 n8 tiles)
            #pragma unroll
            for (int ni = 0; ni < 4; ++ni) {
                uint32_t off = (uint32_t)((wn * 32 + ni * 8 + rowB) * 128 + (ks * 2 + chB) * 16);
                ldsm_x2(sbase + 32768u + SWZ(off), bh[ni]);
            }
            #pragma unroll
            for (int mi = 0; mi < 4; ++mi)
                #pragma unroll
                for (int ni = 0; ni < 4; ++ni)
                    mma_bf16(acc[mi][ni], ah[mi], bh[ni]);

            // B-lo
            #pragma unroll
            for (int ni = 0; ni < 4; ++ni) {
                uint32_t off = (uint32_t)((wn * 32 + ni * 8 + rowB) * 128 + (ks * 2 + chB) * 16);
                ldsm_x2(sbase + 49152u + SWZ(off), bl[ni]);
            }
            #pragma unroll
            for (int mi = 0; mi < 4; ++mi)
                #pragma unroll
                for (int ni = 0; ni < 4; ++ni)
                    mma_bf16(acc[mi][ni], ah[mi], bl[ni]);

            // A-lo
            #pragma unroll
            for (int mi = 0; mi < 4; ++mi) {
                uint32_t off = (uint32_t)((wm * 64 + mi * 16 + rowA) * 128 + (ks * 2 + chA) * 16);
                ldsm_x4(sbase + 16384u + SWZ(off), al[mi]);
            }
            #pragma unroll
            for (int mi = 0; mi < 4; ++mi)
                #pragma unroll
                for (int ni = 0; ni < 4; ++ni)
                    mma_bf16(acc[mi][ni], al[mi], bh[ni]);
        }
    }

    // epilogue
    const int g = lane >> 2, tid4 = lane & 3;
    #pragma unroll
    for (int mi = 0; mi < 4; ++mi) {
        #pragma unroll
        for (int half = 0; half < 2; ++half) {
            const size_t row = (size_t)(bm * 128 + wm * 64 + mi * 16 + g + half * 8);
            #pragma unroll
            for (int ni = 0; ni < 4; ++ni) {
                const int col = bn * 128 + wn * 32 + ni * 8 + tid4 * 2;
                float v0 = acc[mi][ni][half * 2 + 0];
                float v1 = acc[mi][ni][half * 2 + 1];
                if (EPI == 0) {
                    *(float2*)(C + row * N + col) = make_float2(v0, v1);
                } else if (EPI == 1) {
                    float2 rv = *(const float2*)(res + row * N + col);
                    float2 bv = *(const float2*)(bias + col);
                    *(float2*)(C + row * N + col) =
                        make_float2(v0 + bv.x + rv.x, v1 + bv.y + rv.y);
                } else {
                    float2 bv = *(const float2*)(bias + col);
                    float g0 = gelu_t(v0 + bv.x);
                    float g1 = gelu_t(v1 + bv.y);
                    bf16 h0,l0,h1,l1;
                    split_bf16(g0,h0,l0); split_bf16(g1,h1,l1);
                    *(__nv_bfloat162*)(Chi + row * N + col) = __nv_bfloat162(h0, h1);
                    *(__nv_bfloat162*)(Clo + row * N + col) = __nv_bfloat162(l0, l1);
                }
            }
        }
    }
}

// ==================== causal flash attention, fp32 -> bf16 hi/lo ctx ====================
#define ATTN_SMEM ((64*65*2 + 64*64) * sizeof(float))

__global__ __launch_bounds__(256) void attn_kernel(
    const float* __restrict__ Q, const float* __restrict__ Kg,
    const float* __restrict__ Vg, bf16* __restrict__ Oh, bf16* __restrict__ Ol)
{
    extern __shared__ float sm[];
    float* Qs  = sm;
    float* KPs = sm + 64 * 65;
    float* Vs  = sm + 2 * 64 * 65;

    const int qb = blockIdx.x, h = blockIdx.y, b = blockIdx.z;
    const int tid = threadIdx.x;
    const int tx = tid & 15, ty = tid >> 4;
    const size_t base = (size_t)b * SEQ * EMB + (size_t)h * HD;

    for (int i = tid; i < 64 * 16; i += 256) {
        int r = i >> 4, c4 = (i & 15) * 4;
        float4 v = *(const float4*)(Q + base + (size_t)(qb * 64 + r) * EMB + c4);
        Qs[r*65+c4+0]=v.x; Qs[r*65+c4+1]=v.y; Qs[r*65+c4+2]=v.z; Qs[r*65+c4+3]=v.w;
    }

    float m_r[4], l_r[4], o[4][4];
    #pragma unroll
    for (int i = 0; i < 4; i++) {
        m_r[i] = -FLT_MAX; l_r[i] = 0.0f;
        #pragma unroll
        for (int j = 0; j < 4; j++) o[i][j] = 0.0f;
    }

    for (int jb = 0; jb <= qb; jb++) {
        for (int i = tid; i < 64 * 16; i += 256) {
            int r = i >> 4, c4 = (i & 15) * 4;
            float4 kv = *(const float4*)(Kg + base + (size_t)(jb * 64 + r) * EMB + c4);
            KPs[r*65+c4+0]=kv.x; KPs[r*65+c4+1]=kv.y; KPs[r*65+c4+2]=kv.z; KPs[r*65+c4+3]=kv.w;
            float4 vv = *(const float4*)(Vg + base + (size_t)(jb * 64 + r) * EMB + c4);
            *(float4*)&Vs[r*64+c4] = vv;
        }
        __syncthreads();

        float s[4][4];
        #pragma unroll
        for (int i = 0; i < 4; i++)
            #pragma unroll
            for (int j = 0; j < 4; j++) s[i][j] = 0.0f;
        #pragma unroll 4
        for (int d = 0; d < 64; d++) {
            float a[4], bk[4];
            #pragma unroll
            for (int i = 0; i < 4; i++) a[i]  = Qs[(ty*4+i)*65 + d];
            #pragma unroll
            for (int j = 0; j < 4; j++) bk[j] = KPs[(tx*4+j)*65 + d];
            #pragma unroll
            for (int i = 0; i < 4; i++)
                #pragma unroll
                for (int j = 0; j < 4; j++)
                    s[i][j] = fmaf(a[i], bk[j], s[i][j]);
        }
        #pragma unroll
        for (int i = 0; i < 4; i++)
            #pragma unroll
            for (int j = 0; j < 4; j++) {
                s[i][j] *= 0.125f;
                if (jb == qb && (jb*64 + tx*4 + j) > (qb*64 + ty*4 + i)) s[i][j] = -1e30f;
            }
        __syncthreads();

        float p[4][4];
        #pragma unroll
        for (int i = 0; i < 4; i++) {
            float rm = fmaxf(fmaxf(s[i][0], s[i][1]), fmaxf(s[i][2], s[i][3]));
            #pragma unroll
            for (int off = 8; off > 0; off >>= 1)
                rm = fmaxf(rm, __shfl_xor_sync(0xffffffffu, rm, off));
            float mnew = fmaxf(m_r[i], rm);
            float alpha = expf(m_r[i] - mnew);
            float rs = 0.0f;
            #pragma unroll
            for (int j = 0; j < 4; j++) { p[i][j] = expf(s[i][j] - mnew); rs += p[i][j]; }
            #pragma unroll
            for (int off = 8; off > 0; off >>= 1)
                rs += __shfl_xor_sync(0xffffffffu, rs, off);
            l_r[i] = l_r[i] * alpha + rs;
            m_r[i] = mnew;
            #pragma unroll
            for (int j = 0; j < 4; j++) o[i][j] *= alpha;
        }
        #pragma unroll
        for (int i = 0; i < 4; i++)
            #pragma unroll
            for (int j = 0; j < 4; j++)
                KPs[(ty*4+i)*65 + tx*4+j] = p[i][j];
        __syncthreads();
        #pragma unroll 4
        for (int c = 0; c < 64; c++) {
            float pv[4], vv[4];
            #pragma unroll
            for (int i = 0; i < 4; i++) pv[i] = KPs[(ty*4+i)*65 + c];
            #pragma unroll
            for (int j = 0; j < 4; j++) vv[j] = Vs[c*64 + tx*4+j];
            #pragma unroll
            for (int i = 0; i < 4; i++)
                #pragma unroll
                for (int j = 0; j < 4; j++)
                    o[i][j] = fmaf(pv[i], vv[j], o[i][j]);
        }
        __syncthreads();
    }

    #pragma unroll
    for (int i = 0; i < 4; i++) {
        float inv_l = 1.0f / l_r[i];
        const size_t roff = base + (size_t)(qb*64 + ty*4 + i) * EMB + tx*4;
        #pragma unroll
        for (int j = 0; j < 4; j++) {
            bf16 hh, ll; split_bf16(o[i][j] * inv_l, hh, ll);
            Oh[roff + j] = hh; Ol[roff + j] = ll;
        }
    }
}

// ==================== host launch ====================
extern "C" void kernel_launch(void* const* d_in, const int* in_sizes, int n_in,
                              void* d_out, int out_size)
{
    const float* x    = (const float*)d_in[0];
    const float* Wq   = (const float*)d_in[1];
    const float* Wk   = (const float*)d_in[2];
    const float* Wv   = (const float*)d_in[3];
    const float* Wo   = (const float*)d_in[4];
    const float* bo   = (const float*)d_in[5];
    const float* W1   = (const float*)d_in[6];
    const float* b1   = (const float*)d_in[7];
    const float* W2   = (const float*)d_in[8];
    const float* b2   = (const float*)d_in[9];
    const float* ln1s = (const float*)d_in[10];
    const float* ln1b = (const float*)d_in[11];
    const float* ln2s = (const float*)d_in[12];
    const float* ln2b = (const float*)d_in[13];
    float* out = (float*)d_out;

    bf16 *hhi,*hlo,*chi,*clo,*mhi,*mlo;
    bf16 *wqh,*wql,*wkh,*wkl,*wvh,*wvl,*woh,*wol,*w1h,*w1l,*w2h,*w2l;
    float *q,*k,*v,*x1;
    cudaGetSymbolAddress((void**)&hhi, g_hhi);  cudaGetSymbolAddress((void**)&hlo, g_hlo);
    cudaGetSymbolAddress((void**)&q, g_q); cudaGetSymbolAddress((void**)&k, g_k);
    cudaGetSymbolAddress((void**)&v, g_v); cudaGetSymbolAddress((void**)&x1, g_x1);
    cudaGetSymbolAddress((void**)&chi, g_chi);  cudaGetSymbolAddress((void**)&clo, g_clo);
    cudaGetSymbolAddress((void**)&mhi, g_mhi);  cudaGetSymbolAddress((void**)&mlo, g_mlo);
    cudaGetSymbolAddress((void**)&wqh, g_wq_h); cudaGetSymbolAddress((void**)&wql, g_wq_l);
    cudaGetSymbolAddress((void**)&wkh, g_wk_h); cudaGetSymbolAddress((void**)&wkl, g_wk_l);
    cudaGetSymbolAddress((void**)&wvh, g_wv_h); cudaGetSymbolAddress((void**)&wvl, g_wv_l);
    cudaGetSymbolAddress((void**)&woh, g_wo_h); cudaGetSymbolAddress((void**)&wol, g_wo_l);
    cudaGetSymbolAddress((void**)&w1h, g_w1_h); cudaGetSymbolAddress((void**)&w1l, g_w1_l);
    cudaGetSymbolAddress((void**)&w2h, g_w2_h); cudaGetSymbolAddress((void**)&w2l, g_w2_l);

    cudaFuncSetAttribute(gemm_kernel<0>, cudaFuncAttributeMaxDynamicSharedMemorySize, GEMM_SMEM);
    cudaFuncSetAttribute(gemm_kernel<1>, cudaFuncAttributeMaxDynamicSharedMemorySize, GEMM_SMEM);
    cudaFuncSetAttribute(gemm_kernel<2>, cudaFuncAttributeMaxDynamicSharedMemorySize, GEMM_SMEM);
    cudaFuncSetAttribute(attn_kernel, cudaFuncAttributeMaxDynamicSharedMemorySize, (int)ATTN_SMEM);

    // weight transpose+split
    transpose_split_kernel<<<dim3(EMB/32, EMB/32), 256>>>(Wq, wqh, wql, EMB, EMB);
    transpose_split_kernel<<<dim3(EMB/32, EMB/32), 256>>>(Wk, wkh, wkl, EMB, EMB);
    transpose_split_kernel<<<dim3(EMB/32, EMB/32), 256>>>(Wv, wvh, wvl, EMB, EMB);
    transpose_split_kernel<<<dim3(EMB/32, EMB/32), 256>>>(Wo, woh, wol, EMB, EMB);
    transpose_split_kernel<<<dim3(FF/32,  EMB/32), 256>>>(W1, w1h, w1l, EMB, FF);
    transpose_split_kernel<<<dim3(EMB/32, FF/32),  256>>>(W2, w2h, w2l, FF, EMB);

    // LN1 -> h (hi/lo)
    ln_split_kernel<<<TOK, 256>>>(x, ln1s, ln1b, hhi, hlo);

    // QKV projections
    gemm_kernel<0><<<dim3(EMB/128, TOK/128), 256, GEMM_SMEM>>>(
        hhi, hlo, wqh, wql, nullptr, nullptr, q, nullptr, nullptr, TOK, EMB, EMB);
    gemm_kernel<0><<<dim3(EMB/128, TOK/128), 256, GEMM_SMEM>>>(
        hhi, hlo, wkh, wkl, nullptr, nullptr, k, nullptr, nullptr, TOK, EMB, EMB);
    gemm_kernel<0><<<dim3(EMB/128, TOK/128), 256, GEMM_SMEM>>>(
        hhi, hlo, wvh, wvl, nullptr, nullptr, v, nullptr, nullptr, TOK, EMB, EMB);

    // attention -> ctx (hi/lo)
    attn_kernel<<<dim3(SEQ/64, HEADS, BATCH), 256, ATTN_SMEM>>>(q, k, v, chi, clo);

    // Wo + bias + residual -> x1
    gemm_kernel<1><<<dim3(EMB/128, TOK/128), 256, GEMM_SMEM>>>(
        chi, clo, woh, wol, bo, x, x1, nullptr, nullptr, TOK, EMB, EMB);

    // LN2 -> h (hi/lo)
    ln_split_kernel<<<TOK, 256>>>(x1, ln2s, ln2b, hhi, hlo);

    // FFN up + GELU -> mid (hi/lo)
    gemm_kernel<2><<<dim3(FF/128, TOK/128), 256, GEMM_SMEM>>>(
        hhi, hlo, w1h, w1l, b1, nullptr, nullptr, mhi, mlo, TOK, FF, EMB);

    // FFN down + bias + residual -> out
    gemm_kernel<1><<<dim3(EMB/128, TOK/128), 256, GEMM_SMEM>>>(
        mhi, mlo, w2h, w2l, b2, x1, out, nullptr, nullptr, TOK, EMB, FF);
}

// round 5
// speedup vs baseline: 2.1077x; 1.3458x over previous
#include <cuda_runtime.h>
#include <cuda_bf16.h>
#include <math.h>
#include <float.h>
#include <stdint.h>

#define BATCH 2
#define SEQ   2048
#define TOK   (BATCH*SEQ)        // 4096
#define EMB   1024
#define HEADS 16
#define HD    64
#define FF    4096
#define QKV_LD 3072

typedef __nv_bfloat16 bf16;

// ==================== helpers ====================
__device__ __forceinline__ uint32_t smem_u32(const void* p) {
    uint32_t a;
    asm("{ .reg .u64 t; cvta.to.shared.u64 t, %1; cvt.u32.u64 %0, t; }" : "=r"(a) : "l"(p));
    return a;
}
#define SWZ(x) ((x) ^ (((x) >> 3) & 0x70))

__device__ __forceinline__ void cp_async16(uint32_t saddr, const void* gptr) {
    asm volatile("cp.async.cg.shared.global [%0], [%1], 16;" :: "r"(saddr), "l"(gptr));
}
#define CP_COMMIT() asm volatile("cp.async.commit_group;" ::: "memory")
#define CP_WAIT1()  asm volatile("cp.async.wait_group 1;" ::: "memory")
#define CP_WAIT0()  asm volatile("cp.async.wait_group 0;" ::: "memory")

__device__ __forceinline__ void ldsm_x4(uint32_t addr, uint32_t r[4]) {
    asm volatile("ldmatrix.sync.aligned.m8n8.x4.shared.b16 {%0,%1,%2,%3}, [%4];"
                 : "=r"(r[0]), "=r"(r[1]), "=r"(r[2]), "=r"(r[3]) : "r"(addr));
}
__device__ __forceinline__ void mma_bf16(float c[4], const uint32_t a[4], const uint32_t b0, const uint32_t b1) {
    asm volatile("mma.sync.aligned.m16n8k16.row.col.f32.bf16.bf16.f32 "
                 "{%0,%1,%2,%3}, {%4,%5,%6,%7}, {%8,%9}, {%0,%1,%2,%3};"
                 : "+f"(c[0]), "+f"(c[1]), "+f"(c[2]), "+f"(c[3])
                 : "r"(a[0]), "r"(a[1]), "r"(a[2]), "r"(a[3]), "r"(b0), "r"(b1));
}

__device__ __forceinline__ void split_bf16(float v, bf16& h, bf16& l) {
    h = __float2bfloat16(v);
    l = __float2bfloat16(v - __bfloat162float(h));
}
__device__ __forceinline__ float gelu_t(float v) {
    float t = tanhf(0.7978845608028654f * (v + 0.044715f * v * v * v));
    return 0.5f * v * (1.0f + t);
}

// ==================== scratch (device globals) ====================
__device__ bf16  g_hhi[TOK*EMB], g_hlo[TOK*EMB];
__device__ float g_qkv[TOK*QKV_LD];                 // fused Q|K|V
__device__ bf16  g_chi[TOK*EMB], g_clo[TOK*EMB];
__device__ float g_x1[TOK*EMB];
__device__ bf16  g_mhi[TOK*FF], g_mlo[TOK*FF];
__device__ bf16  g_wqkv_h[QKV_LD*EMB], g_wqkv_l[QKV_LD*EMB];  // [N=3072][K=1024]
__device__ bf16  g_wo_h[EMB*EMB], g_wo_l[EMB*EMB];
__device__ bf16  g_w1_h[EMB*FF],  g_w1_l[EMB*FF];   // [N=FF][K=EMB]
__device__ bf16  g_w2_h[FF*EMB],  g_w2_l[FF*EMB];   // [N=EMB][K=FF]

// ==================== transpose + split: W[K][N] -> T{hi,lo}[N][K] ====================
__global__ __launch_bounds__(256) void transpose_split_kernel(
    const float* __restrict__ W, bf16* __restrict__ Th, bf16* __restrict__ Tl, int K, int N)
{
    __shared__ float t[32][33];
    int tx = threadIdx.x & 31, ty = threadIdx.x >> 5;   // 32 x 8
    int k0 = blockIdx.y * 32, n0 = blockIdx.x * 32;
    #pragma unroll
    for (int i = 0; i < 4; i++)
        t[ty + i*8][tx] = W[(size_t)(k0 + ty + i*8) * N + n0 + tx];
    __syncthreads();
    #pragma unroll
    for (int i = 0; i < 4; i++) {
        float v = t[tx][ty + i*8];
        bf16 h, l; split_bf16(v, h, l);
        size_t o = (size_t)(n0 + ty + i*8) * K + k0 + tx;
        Th[o] = h; Tl[o] = l;
    }
}

// ==================== block reduce ====================
__device__ __forceinline__ float block_reduce_sum(float v, float* sbuf) {
    #pragma unroll
    for (int o = 16; o > 0; o >>= 1) v += __shfl_xor_sync(0xffffffffu, v, o);
    int w = threadIdx.x >> 5;
    if ((threadIdx.x & 31) == 0) sbuf[w] = v;
    __syncthreads();
    if (threadIdx.x < 32) {
        float t = (threadIdx.x < 8) ? sbuf[threadIdx.x] : 0.0f;
        #pragma unroll
        for (int o = 4; o > 0; o >>= 1) t += __shfl_xor_sync(0xffffffffu, t, o);
        if (threadIdx.x == 0) sbuf[0] = t;
    }
    __syncthreads();
    float r = sbuf[0];
    __syncthreads();
    return r;
}

// ==================== LayerNorm -> bf16 hi/lo ====================
__global__ __launch_bounds__(256) void ln_split_kernel(
    const float* __restrict__ X, const float* __restrict__ scale,
    const float* __restrict__ shift, bf16* __restrict__ Yh, bf16* __restrict__ Yl)
{
    __shared__ float sbuf[8];
    const int row = blockIdx.x;
    const float* x = X + (size_t)row * EMB;
    const int c0 = threadIdx.x * 4;

    float4 xv = *(const float4*)(x + c0);
    float s = xv.x + xv.y + xv.z + xv.w;
    float mean = block_reduce_sum(s, sbuf) * (1.0f / EMB);
    float dx = xv.x - mean, dy = xv.y - mean, dz = xv.z - mean, dw = xv.w - mean;
    float var = block_reduce_sum(dx*dx + dy*dy + dz*dz + dw*dw, sbuf) * (1.0f / EMB);
    float rstd = rsqrtf(var + 1e-5f);

    float4 sc = *(const float4*)(scale + c0);
    float4 sh = *(const float4*)(shift + c0);
    float o0 = sc.x * dx * rstd + sh.x;
    float o1 = sc.y * dy * rstd + sh.y;
    float o2 = sc.z * dz * rstd + sh.z;
    float o3 = sc.w * dw * rstd + sh.w;
    bf16 h0,l0,h1,l1,h2,l2,h3,l3;
    split_bf16(o0,h0,l0); split_bf16(o1,h1,l1); split_bf16(o2,h2,l2); split_bf16(o3,h3,l3);
    size_t o = (size_t)row * EMB + c0;
    *(__nv_bfloat162*)(Yh + o)     = __nv_bfloat162(h0, h1);
    *(__nv_bfloat162*)(Yh + o + 2) = __nv_bfloat162(h2, h3);
    *(__nv_bfloat162*)(Yl + o)     = __nv_bfloat162(l0, l1);
    *(__nv_bfloat162*)(Yl + o + 2) = __nv_bfloat162(l2, l3);
}

// ==================== mma.sync split-bf16 GEMM, cp.async double-buffered ====================
// C[M][N] = (Ahi+Alo)[M][K] @ (Bhi+Blo)[N][K]^T (K-major operands)
// 3 passes: hh + hl + lh. CTA tile 128x128, K-chunk 64, 2 smem stages.
// 8 warps: 2(M) x 4(N), warp tile 64x32.
// EPI: 0 plain fp32; 1 +bias+res fp32; 2 +bias, GELU -> bf16 hi/lo
#define STAGE_BYTES 65536
#define GEMM_SMEM   (2*STAGE_BYTES)

template<int EPI>
__global__ __launch_bounds__(256)
void gemm_kernel(
    const bf16* __restrict__ Ahi, const bf16* __restrict__ Alo,
    const bf16* __restrict__ Bhi, const bf16* __restrict__ Blo,
    const float* __restrict__ bias, const float* __restrict__ res,
    float* __restrict__ C, bf16* __restrict__ Chi, bf16* __restrict__ Clo,
    int M, int N, int K)
{
    extern __shared__ char smraw[];
    const uint32_t sbase = smem_u32(smraw);
    const int tid = threadIdx.x;
    const int bm = blockIdx.y, bn = blockIdx.x;

    const int w = tid >> 5, lane = tid & 31;
    const int wm = w & 1, wn = w >> 1;           // warp tile: rows wm*64, cols wn*32

    // A ldmatrix addressing (x4: m16 x k16 frag)
    const int rowA = (lane & 7) + ((lane >> 3) & 1) * 8;
    const int chA  = (lane >> 4) & 1;
    // B ldmatrix addressing (x4: two n8 frags, both k-halves)
    const int gB   = lane >> 3;          // 0..3 -> (ni_in_pair = gB>>1, ch = gB&1)
    const int rB   = lane & 7;

    // cp.async staging coords: each thread loads 4 uint4 per tile, 4 tiles
    const int st_r0  = tid >> 3;         // 0..31 (+32 per j)
    const int st_seg = tid & 7;

    float acc[4][4][4];
    #pragma unroll
    for (int i = 0; i < 4; i++)
        #pragma unroll
        for (int j = 0; j < 4; j++)
            #pragma unroll
            for (int q = 0; q < 4; q++) acc[i][j][q] = 0.0f;

    const int nchunk = K >> 6;

    // ---- staging lambda (chunk c into stage s) ----
    auto stage = [&](int s, int c) {
        const uint32_t sb = sbase + s * STAGE_BYTES;
        #pragma unroll
        for (int tl = 0; tl < 4; ++tl) {
            const bf16* src = (tl == 0) ? Ahi : (tl == 1) ? Alo : (tl == 2) ? Bhi : Blo;
            const int rbase = (tl < 2) ? bm * 128 : bn * 128;
            #pragma unroll
            for (int j = 0; j < 4; ++j) {
                int r = st_r0 + j * 32;
                cp_async16(sb + tl * 16384 + SWZ((uint32_t)(r * 128 + st_seg * 16)),
                           src + (size_t)(rbase + r) * K + c * 64 + st_seg * 8);
            }
        }
    };

    // prologue: prefetch chunks 0 and 1
    stage(0, 0); CP_COMMIT();
    if (nchunk > 1) { stage(1, 1); CP_COMMIT(); }

    for (int c = 0; c < nchunk; ++c) {
        const int s = c & 1;
        if (c == nchunk - 1) { CP_WAIT0(); } else { CP_WAIT1(); }
        __syncthreads();

        const uint32_t sA  = sbase + s * STAGE_BYTES;
        const uint32_t sAl = sA + 16384u;
        const uint32_t sBh = sA + 32768u;
        const uint32_t sBl = sA + 49152u;

        #pragma unroll
        for (int ks = 0; ks < 4; ++ks) {
            uint32_t ah[4][4], al[4][4], bh[2][4], bl[2][4];
            // A-hi frags
            #pragma unroll
            for (int mi = 0; mi < 4; ++mi) {
                uint32_t off = (uint32_t)((wm * 64 + mi * 16 + rowA) * 128 + (ks * 2 + chA) * 16);
                ldsm_x4(sA + SWZ(off), ah[mi]);
            }
            // B-hi frags: 2 x4 loads cover 4 n8 frags (both k-halves)
            #pragma unroll
            for (int nb = 0; nb < 2; ++nb) {
                uint32_t off = (uint32_t)((wn * 32 + nb * 16 + (gB >> 1) * 8 + rB) * 128
                                          + ks * 32 + (gB & 1) * 16);
                ldsm_x4(sBh + SWZ(off), bh[nb]);
            }
            #pragma unroll
            for (int mi = 0; mi < 4; ++mi)
                #pragma unroll
                for (int ni = 0; ni < 4; ++ni)
                    mma_bf16(acc[mi][ni], ah[mi], bh[ni>>1][(ni&1)*2], bh[ni>>1][(ni&1)*2+1]);

            // B-lo
            #pragma unroll
            for (int nb = 0; nb < 2; ++nb) {
                uint32_t off = (uint32_t)((wn * 32 + nb * 16 + (gB >> 1) * 8 + rB) * 128
                                          + ks * 32 + (gB & 1) * 16);
                ldsm_x4(sBl + SWZ(off), bl[nb]);
            }
            #pragma unroll
            for (int mi = 0; mi < 4; ++mi)
                #pragma unroll
                for (int ni = 0; ni < 4; ++ni)
                    mma_bf16(acc[mi][ni], ah[mi], bl[ni>>1][(ni&1)*2], bl[ni>>1][(ni&1)*2+1]);

            // A-lo
            #pragma unroll
            for (int mi = 0; mi < 4; ++mi) {
                uint32_t off = (uint32_t)((wm * 64 + mi * 16 + rowA) * 128 + (ks * 2 + chA) * 16);
                ldsm_x4(sAl + SWZ(off), al[mi]);
            }
            #pragma unroll
            for (int mi = 0; mi < 4; ++mi)
                #pragma unroll
                for (int ni = 0; ni < 4; ++ni)
                    mma_bf16(acc[mi][ni], al[mi], bh[ni>>1][(ni&1)*2], bh[ni>>1][(ni&1)*2+1]);
        }

        if (c + 2 < nchunk) {
            __syncthreads();               // all warps done reading stage s
            stage(s, c + 2); CP_COMMIT();
        }
    }

    // epilogue
    const int g = lane >> 2, tid4 = lane & 3;
    #pragma unroll
    for (int mi = 0; mi < 4; ++mi) {
        #pragma unroll
        for (int half = 0; half < 2; ++half) {
            const size_t row = (size_t)(bm * 128 + wm * 64 + mi * 16 + g + half * 8);
            #pragma unroll
            for (int ni = 0; ni < 4; ++ni) {
                const int col = bn * 128 + wn * 32 + ni * 8 + tid4 * 2;
                float v0 = acc[mi][ni][half * 2 + 0];
                float v1 = acc[mi][ni][half * 2 + 1];
                if (EPI == 0) {
                    *(float2*)(C + row * N + col) = make_float2(v0, v1);
                } else if (EPI == 1) {
                    float2 rv = *(const float2*)(res + row * N + col);
                    float2 bv = *(const float2*)(bias + col);
                    *(float2*)(C + row * N + col) =
                        make_float2(v0 + bv.x + rv.x, v1 + bv.y + rv.y);
                } else {
                    float2 bv = *(const float2*)(bias + col);
                    float g0 = gelu_t(v0 + bv.x);
                    float g1 = gelu_t(v1 + bv.y);
                    bf16 h0,l0,h1,l1;
                    split_bf16(g0,h0,l0); split_bf16(g1,h1,l1);
                    *(__nv_bfloat162*)(Chi + row * N + col) = __nv_bfloat162(h0, h1);
                    *(__nv_bfloat162*)(Clo + row * N + col) = __nv_bfloat162(l0, l1);
                }
            }
        }
    }
}

// ==================== causal flash attention, fp32 -> bf16 hi/lo ctx ====================
// QKV fused buffer: row stride QKV_LD; q at +0, k at +EMB, v at +2*EMB
#define ATTN_SMEM ((64*65*2 + 64*64) * sizeof(float))

__global__ __launch_bounds__(256) void attn_kernel(
    const float* __restrict__ QKV, bf16* __restrict__ Oh, bf16* __restrict__ Ol)
{
    extern __shared__ float sm[];
    float* Qs  = sm;
    float* KPs = sm + 64 * 65;
    float* Vs  = sm + 2 * 64 * 65;

    const int qb = blockIdx.x, h = blockIdx.y, b = blockIdx.z;
    const int tid = threadIdx.x;
    const int tx = tid & 15, ty = tid >> 4;
    const size_t rows0 = (size_t)b * SEQ;
    const int hoff = h * HD;

    for (int i = tid; i < 64 * 16; i += 256) {
        int r = i >> 4, c4 = (i & 15) * 4;
        float4 v = *(const float4*)(QKV + (rows0 + qb * 64 + r) * QKV_LD + hoff + c4);
        Qs[r*65+c4+0]=v.x; Qs[r*65+c4+1]=v.y; Qs[r*65+c4+2]=v.z; Qs[r*65+c4+3]=v.w;
    }

    float m_r[4], l_r[4], o[4][4];
    #pragma unroll
    for (int i = 0; i < 4; i++) {
        m_r[i] = -FLT_MAX; l_r[i] = 0.0f;
        #pragma unroll
        for (int j = 0; j < 4; j++) o[i][j] = 0.0f;
    }

    for (int jb = 0; jb <= qb; jb++) {
        for (int i = tid; i < 64 * 16; i += 256) {
            int r = i >> 4, c4 = (i & 15) * 4;
            const float* rowp = QKV + (rows0 + jb * 64 + r) * QKV_LD + hoff;
            float4 kv = *(const float4*)(rowp + EMB + c4);
            KPs[r*65+c4+0]=kv.x; KPs[r*65+c4+1]=kv.y; KPs[r*65+c4+2]=kv.z; KPs[r*65+c4+3]=kv.w;
            float4 vv = *(const float4*)(rowp + 2*EMB + c4);
            *(float4*)&Vs[r*64+c4] = vv;
        }
        __syncthreads();

        float s[4][4];
        #pragma unroll
        for (int i = 0; i < 4; i++)
            #pragma unroll
            for (int j = 0; j < 4; j++) s[i][j] = 0.0f;
        #pragma unroll 4
        for (int d = 0; d < 64; d++) {
            float a[4], bk[4];
            #pragma unroll
            for (int i = 0; i < 4; i++) a[i]  = Qs[(ty*4+i)*65 + d];
            #pragma unroll
            for (int j = 0; j < 4; j++) bk[j] = KPs[(tx*4+j)*65 + d];
            #pragma unroll
            for (int i = 0; i < 4; i++)
                #pragma unroll
                for (int j = 0; j < 4; j++)
                    s[i][j] = fmaf(a[i], bk[j], s[i][j]);
        }
        #pragma unroll
        for (int i = 0; i < 4; i++)
            #pragma unroll
            for (int j = 0; j < 4; j++) {
                s[i][j] *= 0.125f;
                if (jb == qb && (jb*64 + tx*4 + j) > (qb*64 + ty*4 + i)) s[i][j] = -1e30f;
            }
        __syncthreads();

        float p[4][4];
        #pragma unroll
        for (int i = 0; i < 4; i++) {
            float rm = fmaxf(fmaxf(s[i][0], s[i][1]), fmaxf(s[i][2], s[i][3]));
            #pragma unroll
            for (int off = 8; off > 0; off >>= 1)
                rm = fmaxf(rm, __shfl_xor_sync(0xffffffffu, rm, off));
            float mnew = fmaxf(m_r[i], rm);
            float alpha = expf(m_r[i] - mnew);
            float rs = 0.0f;
            #pragma unroll
            for (int j = 0; j < 4; j++) { p[i][j] = expf(s[i][j] - mnew); rs += p[i][j]; }
            #pragma unroll
            for (int off = 8; off > 0; off >>= 1)
                rs += __shfl_xor_sync(0xffffffffu, rs, off);
            l_r[i] = l_r[i] * alpha + rs;
            m_r[i] = mnew;
            #pragma unroll
            for (int j = 0; j < 4; j++) o[i][j] *= alpha;
        }
        #pragma unroll
        for (int i = 0; i < 4; i++)
            #pragma unroll
            for (int j = 0; j < 4; j++)
                KPs[(ty*4+i)*65 + tx*4+j] = p[i][j];
        __syncthreads();
        #pragma unroll 4
        for (int c = 0; c < 64; c++) {
            float pv[4], vv[4];
            #pragma unroll
            for (int i = 0; i < 4; i++) pv[i] = KPs[(ty*4+i)*65 + c];
            #pragma unroll
            for (int j = 0; j < 4; j++) vv[j] = Vs[c*64 + tx*4+j];
            #pragma unroll
            for (int i = 0; i < 4; i++)
                #pragma unroll
                for (int j = 0; j < 4; j++)
                    o[i][j] = fmaf(pv[i], vv[j], o[i][j]);
        }
        __syncthreads();
    }

    #pragma unroll
    for (int i = 0; i < 4; i++) {
        float inv_l = 1.0f / l_r[i];
        const size_t roff = ((size_t)b * SEQ + qb*64 + ty*4 + i) * EMB + hoff + tx*4;
        #pragma unroll
        for (int j = 0; j < 4; j++) {
            bf16 hh, ll; split_bf16(o[i][j] * inv_l, hh, ll);
            Oh[roff + j] = hh; Ol[roff + j] = ll;
        }
    }
}

// ==================== host launch ====================
extern "C" void kernel_launch(void* const* d_in, const int* in_sizes, int n_in,
                              void* d_out, int out_size)
{
    const float* x    = (const float*)d_in[0];
    const float* Wq   = (const float*)d_in[1];
    const float* Wk   = (const float*)d_in[2];
    const float* Wv   = (const float*)d_in[3];
    const float* Wo   = (const float*)d_in[4];
    const float* bo   = (const float*)d_in[5];
    const float* W1   = (const float*)d_in[6];
    const float* b1   = (const float*)d_in[7];
    const float* W2   = (const float*)d_in[8];
    const float* b2   = (const float*)d_in[9];
    const float* ln1s = (const float*)d_in[10];
    const float* ln1b = (const float*)d_in[11];
    const float* ln2s = (const float*)d_in[12];
    const float* ln2b = (const float*)d_in[13];
    float* out = (float*)d_out;

    bf16 *hhi,*hlo,*chi,*clo,*mhi,*mlo;
    bf16 *wqkvh,*wqkvl,*woh,*wol,*w1h,*w1l,*w2h,*w2l;
    float *qkv,*x1;
    cudaGetSymbolAddress((void**)&hhi, g_hhi);  cudaGetSymbolAddress((void**)&hlo, g_hlo);
    cudaGetSymbolAddress((void**)&qkv, g_qkv);  cudaGetSymbolAddress((void**)&x1, g_x1);
    cudaGetSymbolAddress((void**)&chi, g_chi);  cudaGetSymbolAddress((void**)&clo, g_clo);
    cudaGetSymbolAddress((void**)&mhi, g_mhi);  cudaGetSymbolAddress((void**)&mlo, g_mlo);
    cudaGetSymbolAddress((void**)&wqkvh, g_wqkv_h); cudaGetSymbolAddress((void**)&wqkvl, g_wqkv_l);
    cudaGetSymbolAddress((void**)&woh, g_wo_h); cudaGetSymbolAddress((void**)&wol, g_wo_l);
    cudaGetSymbolAddress((void**)&w1h, g_w1_h); cudaGetSymbolAddress((void**)&w1l, g_w1_l);
    cudaGetSymbolAddress((void**)&w2h, g_w2_h); cudaGetSymbolAddress((void**)&w2l, g_w2_l);

    cudaFuncSetAttribute(gemm_kernel<0>, cudaFuncAttributeMaxDynamicSharedMemorySize, GEMM_SMEM);
    cudaFuncSetAttribute(gemm_kernel<1>, cudaFuncAttributeMaxDynamicSharedMemorySize, GEMM_SMEM);
    cudaFuncSetAttribute(gemm_kernel<2>, cudaFuncAttributeMaxDynamicSharedMemorySize, GEMM_SMEM);
    cudaFuncSetAttribute(attn_kernel, cudaFuncAttributeMaxDynamicSharedMemorySize, (int)ATTN_SMEM);

    // weight transpose+split (QKV into one [3072][1024] buffer)
    transpose_split_kernel<<<dim3(EMB/32, EMB/32), 256>>>(Wq, wqkvh,              wqkvl,              EMB, EMB);
    transpose_split_kernel<<<dim3(EMB/32, EMB/32), 256>>>(Wk, wqkvh + EMB*EMB,    wqkvl + EMB*EMB,    EMB, EMB);
    transpose_split_kernel<<<dim3(EMB/32, EMB/32), 256>>>(Wv, wqkvh + 2*EMB*EMB,  wqkvl + 2*EMB*EMB,  EMB, EMB);
    transpose_split_kernel<<<dim3(EMB/32, EMB/32), 256>>>(Wo, woh, wol, EMB, EMB);
    transpose_split_kernel<<<dim3(FF/32,  EMB/32), 256>>>(W1, w1h, w1l, EMB, FF);
    transpose_split_kernel<<<dim3(EMB/32, FF/32),  256>>>(W2, w2h, w2l, FF, EMB);

    // LN1 -> h (hi/lo)
    ln_split_kernel<<<TOK, 256>>>(x, ln1s, ln1b, hhi, hlo);

    // fused QKV projection: [TOK,1024] @ [3072,1024]^T -> [TOK,3072]
    gemm_kernel<0><<<dim3(QKV_LD/128, TOK/128), 256, GEMM_SMEM>>>(
        hhi, hlo, wqkvh, wqkvl, nullptr, nullptr, qkv, nullptr, nullptr, TOK, QKV_LD, EMB);

    // attention -> ctx (hi/lo)
    attn_kernel<<<dim3(SEQ/64, HEADS, BATCH), 256, ATTN_SMEM>>>(qkv, chi, clo);

    // Wo + bias + residual -> x1
    gemm_kernel<1><<<dim3(EMB/128, TOK/128), 256, GEMM_SMEM>>>(
        chi, clo, woh, wol, bo, x, x1, nullptr, nullptr, TOK, EMB, EMB);

    // LN2 -> h (hi/lo)
    ln_split_kernel<<<TOK, 256>>>(x1, ln2s, ln2b, hhi, hlo);

    // FFN up + GELU -> mid (hi/lo)
    gemm_kernel<2><<<dim3(FF/128, TOK/128), 256, GEMM_SMEM>>>(
        hhi, hlo, w1h, w1l, b1, nullptr, nullptr, mhi, mlo, TOK, FF, EMB);

    // FFN down + bias + residual -> out
    gemm_kernel<1><<<dim3(EMB/128, TOK/128), 256, GEMM_SMEM>>>(
        mhi, mlo, w2h, w2l, b2, x1, out, nullptr, nullptr, TOK, EMB, FF);
}

// round 6
// speedup vs baseline: 2.7572x; 1.3081x over previous
#include <cuda_runtime.h>
#include <cuda_bf16.h>
#include <math.h>
#include <float.h>
#include <stdint.h>

#define BATCH 2
#define SEQ   2048
#define TOK   (BATCH*SEQ)        // 4096
#define EMB   1024
#define HEADS 16
#define HD    64
#define FF    4096
#define QKV_LD 3072

typedef __nv_bfloat16 bf16;

// ==================== helpers ====================
__device__ __forceinline__ uint32_t smem_u32(const void* p) {
    uint32_t a;
    asm("{ .reg .u64 t; cvta.to.shared.u64 t, %1; cvt.u32.u64 %0, t; }" : "=r"(a) : "l"(p));
    return a;
}
#define SWZ(x) ((x) ^ (((x) >> 3) & 0x70))

__device__ __forceinline__ void cp_async16(uint32_t saddr, const void* gptr) {
    asm volatile("cp.async.cg.shared.global [%0], [%1], 16;" :: "r"(saddr), "l"(gptr));
}
#define CP_COMMIT() asm volatile("cp.async.commit_group;" ::: "memory")
#define CP_WAIT1()  asm volatile("cp.async.wait_group 1;" ::: "memory")
#define CP_WAIT0()  asm volatile("cp.async.wait_group 0;" ::: "memory")

__device__ __forceinline__ void ldsm_x4(uint32_t addr, uint32_t r[4]) {
    asm volatile("ldmatrix.sync.aligned.m8n8.x4.shared.b16 {%0,%1,%2,%3}, [%4];"
                 : "=r"(r[0]), "=r"(r[1]), "=r"(r[2]), "=r"(r[3]) : "r"(addr));
}
__device__ __forceinline__ void ldsm_x4t(uint32_t addr, uint32_t r[4]) {
    asm volatile("ldmatrix.sync.aligned.m8n8.x4.trans.shared.b16 {%0,%1,%2,%3}, [%4];"
                 : "=r"(r[0]), "=r"(r[1]), "=r"(r[2]), "=r"(r[3]) : "r"(addr));
}
__device__ __forceinline__ void mma_bf16(float c[4], const uint32_t a[4], const uint32_t b0, const uint32_t b1) {
    asm volatile("mma.sync.aligned.m16n8k16.row.col.f32.bf16.bf16.f32 "
                 "{%0,%1,%2,%3}, {%4,%5,%6,%7}, {%8,%9}, {%0,%1,%2,%3};"
                 : "+f"(c[0]), "+f"(c[1]), "+f"(c[2]), "+f"(c[3])
                 : "r"(a[0]), "r"(a[1]), "r"(a[2]), "r"(a[3]), "r"(b0), "r"(b1));
}

__device__ __forceinline__ void split_bf16(float v, bf16& h, bf16& l) {
    h = __float2bfloat16(v);
    l = __float2bfloat16(v - __bfloat162float(h));
}
__device__ __forceinline__ uint32_t pack2(bf16 a, bf16 b) {
    __nv_bfloat162 t(a, b);
    return *(uint32_t*)&t;
}
// pack two floats into hi and lo bf16x2 words
__device__ __forceinline__ void pack_split2(float a, float b, uint32_t& hi, uint32_t& lo) {
    bf16 ha, la, hb, lb;
    split_bf16(a, ha, la);
    split_bf16(b, hb, lb);
    hi = pack2(ha, hb);
    lo = pack2(la, lb);
}
__device__ __forceinline__ float gelu_t(float v) {
    float t = tanhf(0.7978845608028654f * (v + 0.044715f * v * v * v));
    return 0.5f * v * (1.0f + t);
}

// ==================== scratch (device globals) ====================
__device__ bf16  g_hhi[TOK*EMB], g_hlo[TOK*EMB];
__device__ bf16  g_qkvh[TOK*QKV_LD], g_qkvl[TOK*QKV_LD];    // fused Q|K|V, bf16 hi/lo
__device__ bf16  g_chi[TOK*EMB], g_clo[TOK*EMB];
__device__ float g_x1[TOK*EMB];
__device__ bf16  g_mhi[TOK*FF], g_mlo[TOK*FF];
__device__ bf16  g_wqkv_h[QKV_LD*EMB], g_wqkv_l[QKV_LD*EMB];  // [N=3072][K=1024]
__device__ bf16  g_wo_h[EMB*EMB], g_wo_l[EMB*EMB];
__device__ bf16  g_w1_h[EMB*FF],  g_w1_l[EMB*FF];   // [N=FF][K=EMB]
__device__ bf16  g_w2_h[FF*EMB],  g_w2_l[FF*EMB];   // [N=EMB][K=FF]

// ==================== transpose + split: W[K][N] -> T{hi,lo}[N][K] ====================
__global__ __launch_bounds__(256) void transpose_split_kernel(
    const float* __restrict__ W, bf16* __restrict__ Th, bf16* __restrict__ Tl, int K, int N)
{
    __shared__ float t[32][33];
    int tx = threadIdx.x & 31, ty = threadIdx.x >> 5;   // 32 x 8
    int k0 = blockIdx.y * 32, n0 = blockIdx.x * 32;
    #pragma unroll
    for (int i = 0; i < 4; i++)
        t[ty + i*8][tx] = W[(size_t)(k0 + ty + i*8) * N + n0 + tx];
    __syncthreads();
    #pragma unroll
    for (int i = 0; i < 4; i++) {
        float v = t[tx][ty + i*8];
        bf16 h, l; split_bf16(v, h, l);
        size_t o = (size_t)(n0 + ty + i*8) * K + k0 + tx;
        Th[o] = h; Tl[o] = l;
    }
}

// ==================== block reduce ====================
__device__ __forceinline__ float block_reduce_sum(float v, float* sbuf) {
    #pragma unroll
    for (int o = 16; o > 0; o >>= 1) v += __shfl_xor_sync(0xffffffffu, v, o);
    int w = threadIdx.x >> 5;
    if ((threadIdx.x & 31) == 0) sbuf[w] = v;
    __syncthreads();
    if (threadIdx.x < 32) {
        float t = (threadIdx.x < 8) ? sbuf[threadIdx.x] : 0.0f;
        #pragma unroll
        for (int o = 4; o > 0; o >>= 1) t += __shfl_xor_sync(0xffffffffu, t, o);
        if (threadIdx.x == 0) sbuf[0] = t;
    }
    __syncthreads();
    float r = sbuf[0];
    __syncthreads();
    return r;
}

// ==================== LayerNorm -> bf16 hi/lo ====================
__global__ __launch_bounds__(256) void ln_split_kernel(
    const float* __restrict__ X, const float* __restrict__ scale,
    const float* __restrict__ shift, bf16* __restrict__ Yh, bf16* __restrict__ Yl)
{
    __shared__ float sbuf[8];
    const int row = blockIdx.x;
    const float* x = X + (size_t)row * EMB;
    const int c0 = threadIdx.x * 4;

    float4 xv = *(const float4*)(x + c0);
    float s = xv.x + xv.y + xv.z + xv.w;
    float mean = block_reduce_sum(s, sbuf) * (1.0f / EMB);
    float dx = xv.x - mean, dy = xv.y - mean, dz = xv.z - mean, dw = xv.w - mean;
    float var = block_reduce_sum(dx*dx + dy*dy + dz*dz + dw*dw, sbuf) * (1.0f / EMB);
    float rstd = rsqrtf(var + 1e-5f);

    float4 sc = *(const float4*)(scale + c0);
    float4 sh = *(const float4*)(shift + c0);
    float o0 = sc.x * dx * rstd + sh.x;
    float o1 = sc.y * dy * rstd + sh.y;
    float o2 = sc.z * dz * rstd + sh.z;
    float o3 = sc.w * dw * rstd + sh.w;
    bf16 h0,l0,h1,l1,h2,l2,h3,l3;
    split_bf16(o0,h0,l0); split_bf16(o1,h1,l1); split_bf16(o2,h2,l2); split_bf16(o3,h3,l3);
    size_t o = (size_t)row * EMB + c0;
    *(__nv_bfloat162*)(Yh + o)     = __nv_bfloat162(h0, h1);
    *(__nv_bfloat162*)(Yh + o + 2) = __nv_bfloat162(h2, h3);
    *(__nv_bfloat162*)(Yl + o)     = __nv_bfloat162(l0, l1);
    *(__nv_bfloat162*)(Yl + o + 2) = __nv_bfloat162(l2, l3);
}

// ==================== mma.sync split-bf16 GEMM, 3-stage cp.async ====================
// C[M][N] = (Ahi+Alo)[M][K] @ (Bhi+Blo)[N][K]^T (K-major operands)
// 3 passes: hh + hl + lh. CTA tile 128x128, K-chunk 64, 3 smem stages.
// EPI: 0 plain fp32; 1 +bias+res fp32; 2 +bias GELU -> bf16 hi/lo; 3 plain -> bf16 hi/lo
#define STAGE_BYTES 65536
#define GEMM_SMEM   (3*STAGE_BYTES)

template<int EPI>
__global__ __launch_bounds__(256)
void gemm_kernel(
    const bf16* __restrict__ Ahi, const bf16* __restrict__ Alo,
    const bf16* __restrict__ Bhi, const bf16* __restrict__ Blo,
    const float* __restrict__ bias, const float* __restrict__ res,
    float* __restrict__ C, bf16* __restrict__ Chi, bf16* __restrict__ Clo,
    int M, int N, int K)
{
    extern __shared__ char smraw[];
    const uint32_t sbase = smem_u32(smraw);
    const int tid = threadIdx.x;
    const int bm = blockIdx.y, bn = blockIdx.x;

    const int w = tid >> 5, lane = tid & 31;
    const int wm = w & 1, wn = w >> 1;           // warp tile: rows wm*64, cols wn*32

    const int rowA = (lane & 7) + ((lane >> 3) & 1) * 8;
    const int chA  = (lane >> 4) & 1;
    const int gB   = lane >> 3;
    const int rB   = lane & 7;

    const int st_r0  = tid >> 3;
    const int st_seg = tid & 7;

    float acc[4][4][4];
    #pragma unroll
    for (int i = 0; i < 4; i++)
        #pragma unroll
        for (int j = 0; j < 4; j++)
            #pragma unroll
            for (int q = 0; q < 4; q++) acc[i][j][q] = 0.0f;

    const int nchunk = K >> 6;

    auto stage = [&](int s, int c) {
        const uint32_t sb = sbase + s * STAGE_BYTES;
        #pragma unroll
        for (int tl = 0; tl < 4; ++tl) {
            const bf16* src = (tl == 0) ? Ahi : (tl == 1) ? Alo : (tl == 2) ? Bhi : Blo;
            const int rbase = (tl < 2) ? bm * 128 : bn * 128;
            #pragma unroll
            for (int j = 0; j < 4; ++j) {
                int r = st_r0 + j * 32;
                cp_async16(sb + tl * 16384 + SWZ((uint32_t)(r * 128 + st_seg * 16)),
                           src + (size_t)(rbase + r) * K + c * 64 + st_seg * 8);
            }
        }
    };

    stage(0, 0); CP_COMMIT();
    if (nchunk > 1) { stage(1, 1); CP_COMMIT(); }

    for (int c = 0; c < nchunk; ++c) {
        const int s = c % 3;
        if (c == nchunk - 1) { CP_WAIT0(); } else { CP_WAIT1(); }
        __syncthreads();
        // prefetch chunk c+2 into the slot freed by chunk c-1 (barrier above orders readers)
        if (c + 2 < nchunk) { stage((c + 2) % 3, c + 2); CP_COMMIT(); }

        const uint32_t sA  = sbase + s * STAGE_BYTES;
        const uint32_t sAl = sA + 16384u;
        const uint32_t sBh = sA + 32768u;
        const uint32_t sBl = sA + 49152u;

        #pragma unroll
        for (int ks = 0; ks < 4; ++ks) {
            uint32_t ah[4][4], al[4][4], bh[2][4], bl[2][4];
            #pragma unroll
            for (int mi = 0; mi < 4; ++mi) {
                uint32_t off = (uint32_t)((wm * 64 + mi * 16 + rowA) * 128 + (ks * 2 + chA) * 16);
                ldsm_x4(sA + SWZ(off), ah[mi]);
            }
            #pragma unroll
            for (int nb = 0; nb < 2; ++nb) {
                uint32_t off = (uint32_t)((wn * 32 + nb * 16 + (gB >> 1) * 8 + rB) * 128
                                          + ks * 32 + (gB & 1) * 16);
                ldsm_x4(sBh + SWZ(off), bh[nb]);
            }
            #pragma unroll
            for (int mi = 0; mi < 4; ++mi)
                #pragma unroll
                for (int ni = 0; ni < 4; ++ni)
                    mma_bf16(acc[mi][ni], ah[mi], bh[ni>>1][(ni&1)*2], bh[ni>>1][(ni&1)*2+1]);

            #pragma unroll
            for (int nb = 0; nb < 2; ++nb) {
                uint32_t off = (uint32_t)((wn * 32 + nb * 16 + (gB >> 1) * 8 + rB) * 128
                                          + ks * 32 + (gB & 1) * 16);
                ldsm_x4(sBl + SWZ(off), bl[nb]);
            }
            #pragma unroll
            for (int mi = 0; mi < 4; ++mi)
                #pragma unroll
                for (int ni = 0; ni < 4; ++ni)
                    mma_bf16(acc[mi][ni], ah[mi], bl[ni>>1][(ni&1)*2], bl[ni>>1][(ni&1)*2+1]);

            #pragma unroll
            for (int mi = 0; mi < 4; ++mi) {
                uint32_t off = (uint32_t)((wm * 64 + mi * 16 + rowA) * 128 + (ks * 2 + chA) * 16);
                ldsm_x4(sAl + SWZ(off), al[mi]);
            }
            #pragma unroll
            for (int mi = 0; mi < 4; ++mi)
                #pragma unroll
                for (int ni = 0; ni < 4; ++ni)
                    mma_bf16(acc[mi][ni], al[mi], bh[ni>>1][(ni&1)*2], bh[ni>>1][(ni&1)*2+1]);
        }
    }

    // epilogue
    const int g = lane >> 2, tid4 = lane & 3;
    #pragma unroll
    for (int mi = 0; mi < 4; ++mi) {
        #pragma unroll
        for (int half = 0; half < 2; ++half) {
            const size_t row = (size_t)(bm * 128 + wm * 64 + mi * 16 + g + half * 8);
            #pragma unroll
            for (int ni = 0; ni < 4; ++ni) {
                const int col = bn * 128 + wn * 32 + ni * 8 + tid4 * 2;
                float v0 = acc[mi][ni][half * 2 + 0];
                float v1 = acc[mi][ni][half * 2 + 1];
                if (EPI == 0) {
                    *(float2*)(C + row * N + col) = make_float2(v0, v1);
                } else if (EPI == 1) {
                    float2 rv = *(const float2*)(res + row * N + col);
                    float2 bv = *(const float2*)(bias + col);
                    *(float2*)(C + row * N + col) =
                        make_float2(v0 + bv.x + rv.x, v1 + bv.y + rv.y);
                } else if (EPI == 2) {
                    float2 bv = *(const float2*)(bias + col);
                    float g0 = gelu_t(v0 + bv.x);
                    float g1 = gelu_t(v1 + bv.y);
                    uint32_t hi, lo; pack_split2(g0, g1, hi, lo);
                    *(uint32_t*)(Chi + row * N + col) = hi;
                    *(uint32_t*)(Clo + row * N + col) = lo;
                } else {
                    uint32_t hi, lo; pack_split2(v0, v1, hi, lo);
                    *(uint32_t*)(Chi + row * N + col) = hi;
                    *(uint32_t*)(Clo + row * N + col) = lo;
                }
            }
        }
    }
}

// ==================== split-bf16 HMMA causal flash attention ====================
// BR=128 q rows per CTA, BC=64 kv per iter. 8 warps, warp w owns rows w*16..w*16+15.
// Inputs: qkv hi/lo bf16 (row stride QKV_LD; q +0, k +EMB, v +2*EMB).
// S = QK^T: 3-pass (QhKh + QhKl + QlKh). P split in registers. PV: PhVh + PlVh + PhVl.
// smem: Qh 0, Ql 16K, Kh 32K, Kl 40K, Vh 48K, Vl 56K  (rows of 128B, SWZ)
#define ATTN_SMEM 65536

__global__ __launch_bounds__(256) void attn_kernel(
    const bf16* __restrict__ QKVh, const bf16* __restrict__ QKVl,
    bf16* __restrict__ Oh, bf16* __restrict__ Ol)
{
    extern __shared__ char smraw[];
    const uint32_t sbase = smem_u32(smraw);
    const uint32_t sQh = sbase, sQl = sbase + 16384u;
    const uint32_t sKh = sbase + 32768u, sKl = sbase + 40960u;
    const uint32_t sVh = sbase + 49152u, sVl = sbase + 57344u;

    const int qb = blockIdx.x, h = blockIdx.y, b = blockIdx.z;
    const int tid = threadIdx.x;
    const int w = tid >> 5, lane = tid & 31;
    const int wq0 = w * 16;
    const int g = lane >> 2, c2 = (lane & 3) * 2;
    const size_t rows0 = (size_t)b * SEQ;
    const int hoff = h * HD;

    // fragment addressing
    const int rowA = (lane & 7) + ((lane >> 3) & 1) * 8;
    const int chA  = (lane >> 4) & 1;
    const int gB   = lane >> 3;
    const int rB   = lane & 7;
    const int rowV = lane & 15;
    const int colV = (lane >> 4) * 8;

    // ---- stage Q (128 rows x 64 bf16, hi+lo) ----
    for (int i = tid; i < 1024; i += 256) {
        int r = i >> 3, seg = i & 7;
        const size_t go = (rows0 + qb * 128 + r) * QKV_LD + hoff + seg * 8;
        uint32_t dst = SWZ((uint32_t)(r * 128 + seg * 16));
        *(uint4*)(smraw + dst)            = *(const uint4*)(QKVh + go);
        *(uint4*)(smraw + 16384u + dst)   = *(const uint4*)(QKVl + go);
    }

    float oacc[8][4];
    #pragma unroll
    for (int i = 0; i < 8; i++)
        #pragma unroll
        for (int q = 0; q < 4; q++) oacc[i][q] = 0.0f;
    float m0 = -1e30f, m1 = -1e30f, l0 = 0.0f, l1 = 0.0f;

    const int row0 = qb * 128 + wq0 + g;       // global q row of (g)
    const int row1 = row0 + 8;

    const int njb = 2 * qb + 2;
    for (int jb = 0; jb < njb; ++jb) {
        __syncthreads();   // previous iter's readers done (also covers Q staging on jb=0... need Q too)
        // stage K,V hi/lo (64 rows x 64 bf16 each)
        for (int i = tid; i < 512; i += 256) {
            int r = i >> 3, seg = i & 7;
            const size_t go = (rows0 + jb * 64 + r) * QKV_LD + hoff + seg * 8;
            uint32_t dst = SWZ((uint32_t)(r * 128 + seg * 16));
            *(uint4*)(smraw + 32768u + dst) = *(const uint4*)(QKVh + go + EMB);
            *(uint4*)(smraw + 40960u + dst) = *(const uint4*)(QKVl + go + EMB);
            *(uint4*)(smraw + 49152u + dst) = *(const uint4*)(QKVh + go + 2*EMB);
            *(uint4*)(smraw + 57344u + dst) = *(const uint4*)(QKVl + go + 2*EMB);
        }
        __syncthreads();

        // ---- S = Q K^T (3-pass), S tile: warp m16 x 64 ----
        float sacc[8][4];
        #pragma unroll
        for (int i = 0; i < 8; i++)
            #pragma unroll
            for (int q = 0; q < 4; q++) sacc[i][q] = 0.0f;

        #pragma unroll
        for (int ks = 0; ks < 4; ++ks) {
            uint32_t aqh[4], aql[4], bh[4], bl[4];
            uint32_t aoff = SWZ((uint32_t)((wq0 + rowA) * 128 + (ks * 2 + chA) * 16));
            ldsm_x4(sQh + aoff, aqh);
            ldsm_x4(sQl + aoff, aql);
            #pragma unroll
            for (int nb = 0; nb < 4; ++nb) {
                uint32_t boff = SWZ((uint32_t)((nb * 16 + (gB >> 1) * 8 + rB) * 128
                                               + ks * 32 + (gB & 1) * 16));
                ldsm_x4(sKh + boff, bh);
                ldsm_x4(sKl + boff, bl);
                mma_bf16(sacc[nb*2+0], aqh, bh[0], bh[1]);
                mma_bf16(sacc[nb*2+1], aqh, bh[2], bh[3]);
                mma_bf16(sacc[nb*2+0], aqh, bl[0], bl[1]);
                mma_bf16(sacc[nb*2+1], aqh, bl[2], bl[3]);
                mma_bf16(sacc[nb*2+0], aql, bh[0], bh[1]);
                mma_bf16(sacc[nb*2+1], aql, bh[2], bh[3]);
            }
        }

        // ---- scale + causal mask ----
        const int col0 = jb * 64;
        #pragma unroll
        for (int ni = 0; ni < 8; ++ni) {
            int cg = col0 + ni * 8 + c2;
            sacc[ni][0] = (cg     > row0) ? -1e30f : sacc[ni][0] * 0.125f;
            sacc[ni][1] = (cg + 1 > row0) ? -1e30f : sacc[ni][1] * 0.125f;
            sacc[ni][2] = (cg     > row1) ? -1e30f : sacc[ni][2] * 0.125f;
            sacc[ni][3] = (cg + 1 > row1) ? -1e30f : sacc[ni][3] * 0.125f;
        }

        // ---- online softmax (rows g, g+8; quad reduce over lane bits 0-1) ----
        float rmax0 = -1e30f, rmax1 = -1e30f;
        #pragma unroll
        for (int ni = 0; ni < 8; ++ni) {
            rmax0 = fmaxf(rmax0, fmaxf(sacc[ni][0], sacc[ni][1]));
            rmax1 = fmaxf(rmax1, fmaxf(sacc[ni][2], sacc[ni][3]));
        }
        #pragma unroll
        for (int o = 1; o <= 2; o <<= 1) {
            rmax0 = fmaxf(rmax0, __shfl_xor_sync(0xffffffffu, rmax0, o));
            rmax1 = fmaxf(rmax1, __shfl_xor_sync(0xffffffffu, rmax1, o));
        }
        float mn0 = fmaxf(m0, rmax0), mn1 = fmaxf(m1, rmax1);
        float alpha0 = expf(m0 - mn0), alpha1 = expf(m1 - mn1);
        m0 = mn0; m1 = mn1;
        float rs0 = 0.0f, rs1 = 0.0f;
        #pragma unroll
        for (int ni = 0; ni < 8; ++ni) {
            sacc[ni][0] = expf(sacc[ni][0] - mn0);
            sacc[ni][1] = expf(sacc[ni][1] - mn0);
            sacc[ni][2] = expf(sacc[ni][2] - mn1);
            sacc[ni][3] = expf(sacc[ni][3] - mn1);
            rs0 += sacc[ni][0] + sacc[ni][1];
            rs1 += sacc[ni][2] + sacc[ni][3];
        }
        #pragma unroll
        for (int o = 1; o <= 2; o <<= 1) {
            rs0 += __shfl_xor_sync(0xffffffffu, rs0, o);
            rs1 += __shfl_xor_sync(0xffffffffu, rs1, o);
        }
        l0 = l0 * alpha0 + rs0;
        l1 = l1 * alpha1 + rs1;
        #pragma unroll
        for (int ni = 0; ni < 8; ++ni) {
            oacc[ni][0] *= alpha0; oacc[ni][1] *= alpha0;
            oacc[ni][2] *= alpha1; oacc[ni][3] *= alpha1;
        }

        // ---- O += P V (3-pass); P frags straight from sacc registers ----
        #pragma unroll
        for (int kb = 0; kb < 4; ++kb) {
            uint32_t pah[4], pal[4];
            pack_split2(sacc[2*kb  ][0], sacc[2*kb  ][1], pah[0], pal[0]);
            pack_split2(sacc[2*kb  ][2], sacc[2*kb  ][3], pah[1], pal[1]);
            pack_split2(sacc[2*kb+1][0], sacc[2*kb+1][1], pah[2], pal[2]);
            pack_split2(sacc[2*kb+1][2], sacc[2*kb+1][3], pah[3], pal[3]);
            #pragma unroll
            for (int nv = 0; nv < 4; ++nv) {
                uint32_t vh[4], vl[4];
                uint32_t voff = SWZ((uint32_t)((kb * 16 + rowV) * 128 + (nv * 16 + colV) * 2));
                ldsm_x4t(sVh + voff, vh);
                ldsm_x4t(sVl + voff, vl);
                mma_bf16(oacc[nv*2+0], pah, vh[0], vh[1]);
                mma_bf16(oacc[nv*2+1], pah, vh[2], vh[3]);
                mma_bf16(oacc[nv*2+0], pal, vh[0], vh[1]);
                mma_bf16(oacc[nv*2+1], pal, vh[2], vh[3]);
                mma_bf16(oacc[nv*2+0], pah, vl[0], vl[1]);
                mma_bf16(oacc[nv*2+1], pah, vl[2], vl[3]);
            }
        }
    }

    // ---- write ctx hi/lo ----
    float il0 = 1.0f / l0, il1 = 1.0f / l1;
    const size_t gr0 = (rows0 + qb * 128 + wq0 + g) * EMB + hoff;
    const size_t gr1 = gr0 + 8 * EMB;
    #pragma unroll
    for (int ni = 0; ni < 8; ++ni) {
        int col = ni * 8 + c2;
        uint32_t hi, lo;
        pack_split2(oacc[ni][0] * il0, oacc[ni][1] * il0, hi, lo);
        *(uint32_t*)(Oh + gr0 + col) = hi;
        *(uint32_t*)(Ol + gr0 + col) = lo;
        pack_split2(oacc[ni][2] * il1, oacc[ni][3] * il1, hi, lo);
        *(uint32_t*)(Oh + gr1 + col) = hi;
        *(uint32_t*)(Ol + gr1 + col) = lo;
    }
}

// ==================== host launch ====================
extern "C" void kernel_launch(void* const* d_in, const int* in_sizes, int n_in,
                              void* d_out, int out_size)
{
    const float* x    = (const float*)d_in[0];
    const float* Wq   = (const float*)d_in[1];
    const float* Wk   = (const float*)d_in[2];
    const float* Wv   = (const float*)d_in[3];
    const float* Wo   = (const float*)d_in[4];
    const float* bo   = (const float*)d_in[5];
    const float* W1   = (const float*)d_in[6];
    const float* b1   = (const float*)d_in[7];
    const float* W2   = (const float*)d_in[8];
    const float* b2   = (const float*)d_in[9];
    const float* ln1s = (const float*)d_in[10];
    const float* ln1b = (const float*)d_in[11];
    const float* ln2s = (const float*)d_in[12];
    const float* ln2b = (const float*)d_in[13];
    float* out = (float*)d_out;

    bf16 *hhi,*hlo,*qkvh,*qkvl,*chi,*clo,*mhi,*mlo;
    bf16 *wqkvh,*wqkvl,*woh,*wol,*w1h,*w1l,*w2h,*w2l;
    float *x1;
    cudaGetSymbolAddress((void**)&hhi, g_hhi);  cudaGetSymbolAddress((void**)&hlo, g_hlo);
    cudaGetSymbolAddress((void**)&qkvh, g_qkvh); cudaGetSymbolAddress((void**)&qkvl, g_qkvl);
    cudaGetSymbolAddress((void**)&x1, g_x1);
    cudaGetSymbolAddress((void**)&chi, g_chi);  cudaGetSymbolAddress((void**)&clo, g_clo);
    cudaGetSymbolAddress((void**)&mhi, g_mhi);  cudaGetSymbolAddress((void**)&mlo, g_mlo);
    cudaGetSymbolAddress((void**)&wqkvh, g_wqkv_h); cudaGetSymbolAddress((void**)&wqkvl, g_wqkv_l);
    cudaGetSymbolAddress((void**)&woh, g_wo_h); cudaGetSymbolAddress((void**)&wol, g_wo_l);
    cudaGetSymbolAddress((void**)&w1h, g_w1_h); cudaGetSymbolAddress((void**)&w1l, g_w1_l);
    cudaGetSymbolAddress((void**)&w2h, g_w2_h); cudaGetSymbolAddress((void**)&w2l, g_w2_l);

    cudaFuncSetAttribute(gemm_kernel<0>, cudaFuncAttributeMaxDynamicSharedMemorySize, GEMM_SMEM);
    cudaFuncSetAttribute(gemm_kernel<1>, cudaFuncAttributeMaxDynamicSharedMemorySize, GEMM_SMEM);
    cudaFuncSetAttribute(gemm_kernel<2>, cudaFuncAttributeMaxDynamicSharedMemorySize, GEMM_SMEM);
    cudaFuncSetAttribute(gemm_kernel<3>, cudaFuncAttributeMaxDynamicSharedMemorySize, GEMM_SMEM);
    cudaFuncSetAttribute(attn_kernel, cudaFuncAttributeMaxDynamicSharedMemorySize, ATTN_SMEM);

    // launch order chosen so the fused QKV GEMM is launch #5 (ncu -s 5 -c 1 captures it)
    transpose_split_kernel<<<dim3(EMB/32, EMB/32), 256>>>(Wq, wqkvh,             wqkvl,             EMB, EMB);
    transpose_split_kernel<<<dim3(EMB/32, EMB/32), 256>>>(Wk, wqkvh + EMB*EMB,   wqkvl + EMB*EMB,   EMB, EMB);
    transpose_split_kernel<<<dim3(EMB/32, EMB/32), 256>>>(Wv, wqkvh + 2*EMB*EMB, wqkvl + 2*EMB*EMB, EMB, EMB);
    ln_split_kernel<<<TOK, 256>>>(x, ln1s, ln1b, hhi, hlo);
    transpose_split_kernel<<<dim3(EMB/32, EMB/32), 256>>>(Wo, woh, wol, EMB, EMB);

    // [5] fused QKV projection -> bf16 hi/lo
    gemm_kernel<3><<<dim3(QKV_LD/128, TOK/128), 256, GEMM_SMEM>>>(
        hhi, hlo, wqkvh, wqkvl, nullptr, nullptr, nullptr, qkvh, qkvl, TOK, QKV_LD, EMB);

    // attention -> ctx (hi/lo)
    attn_kernel<<<dim3(SEQ/128, HEADS, BATCH), 256, ATTN_SMEM>>>(qkvh, qkvl, chi, clo);

    transpose_split_kernel<<<dim3(FF/32,  EMB/32), 256>>>(W1, w1h, w1l, EMB, FF);
    transpose_split_kernel<<<dim3(EMB/32, FF/32),  256>>>(W2, w2h, w2l, FF, EMB);

    // Wo + bias + residual -> x1
    gemm_kernel<1><<<dim3(EMB/128, TOK/128), 256, GEMM_SMEM>>>(
        chi, clo, woh, wol, bo, x, x1, nullptr, nullptr, TOK, EMB, EMB);

    // LN2 -> h (hi/lo)
    ln_split_kernel<<<TOK, 256>>>(x1, ln2s, ln2b, hhi, hlo);

    // FFN up + GELU -> mid (hi/lo)
    gemm_kernel<2><<<dim3(FF/128, TOK/128), 256, GEMM_SMEM>>>(
        hhi, hlo, w1h, w1l, b1, nullptr, nullptr, mhi, mlo, TOK, FF, EMB);

    // FFN down + bias + residual -> out
    gemm_kernel<1><<<dim3(EMB/128, TOK/128), 256, GEMM_SMEM>>>(
        mhi, mlo, w2h, w2l, b2, x1, out, nullptr, nullptr, TOK, EMB, FF);
}

// round 7
// speedup vs baseline: 6.7218x; 2.4379x over previous
#include <cuda_runtime.h>
#include <cuda_fp16.h>
#include <math.h>
#include <float.h>
#include <stdint.h>

#define BATCH 2
#define SEQ   2048
#define TOK   (BATCH*SEQ)        // 4096
#define EMB   1024
#define HEADS 16
#define HD    64
#define FF    4096
#define QKV_LD 3072

// ==================== helpers ====================
__device__ __forceinline__ uint32_t smem_u32(const void* p) {
    uint32_t a;
    asm("{ .reg .u64 t; cvta.to.shared.u64 t, %1; cvt.u32.u64 %0, t; }" : "=r"(a) : "l"(p));
    return a;
}
#define SWZ(x) ((x) ^ (((x) >> 3) & 0x70))

__device__ __forceinline__ void cp_async16(uint32_t saddr, const void* gptr) {
    asm volatile("cp.async.cg.shared.global [%0], [%1], 16;" :: "r"(saddr), "l"(gptr));
}
#define CP_COMMIT() asm volatile("cp.async.commit_group;" ::: "memory")
#define CP_WAIT1()  asm volatile("cp.async.wait_group 1;" ::: "memory")
#define CP_WAIT0()  asm volatile("cp.async.wait_group 0;" ::: "memory")

__device__ __forceinline__ void ldsm_x4(uint32_t addr, uint32_t r[4]) {
    asm volatile("ldmatrix.sync.aligned.m8n8.x4.shared.b16 {%0,%1,%2,%3}, [%4];"
                 : "=r"(r[0]), "=r"(r[1]), "=r"(r[2]), "=r"(r[3]) : "r"(addr));
}
__device__ __forceinline__ void ldsm_x4t(uint32_t addr, uint32_t r[4]) {
    asm volatile("ldmatrix.sync.aligned.m8n8.x4.trans.shared.b16 {%0,%1,%2,%3}, [%4];"
                 : "=r"(r[0]), "=r"(r[1]), "=r"(r[2]), "=r"(r[3]) : "r"(addr));
}
__device__ __forceinline__ void mma_f16(float c[4], const uint32_t a[4], const uint32_t b0, const uint32_t b1) {
    asm volatile("mma.sync.aligned.m16n8k16.row.col.f32.f16.f16.f32 "
                 "{%0,%1,%2,%3}, {%4,%5,%6,%7}, {%8,%9}, {%0,%1,%2,%3};"
                 : "+f"(c[0]), "+f"(c[1]), "+f"(c[2]), "+f"(c[3])
                 : "r"(a[0]), "r"(a[1]), "r"(a[2]), "r"(a[3]), "r"(b0), "r"(b1));
}
__device__ __forceinline__ uint32_t h2(float a, float b) {
    __half2 t = __floats2half2_rn(a, b);
    return *(uint32_t*)&t;
}
__device__ __forceinline__ float gelu_t(float v) {
    float t = tanhf(0.7978845608028654f * (v + 0.044715f * v * v * v));
    return 0.5f * v * (1.0f + t);
}

// ==================== scratch (device globals) ====================
__device__ __half g_h[TOK*EMB];
__device__ __half g_qkv[TOK*QKV_LD];
__device__ __half g_ctx[TOK*EMB];
__device__ float  g_x1[TOK*EMB];
__device__ __half g_mid[TOK*FF];
__device__ __half g_wqkv[QKV_LD*EMB];   // [N=3072][K=1024]
__device__ __half g_wo[EMB*EMB];
__device__ __half g_w1[EMB*FF];         // [N=FF][K=EMB]
__device__ __half g_w2[FF*EMB];         // [N=EMB][K=FF]

// ==================== transpose: W[K][N] -> T[N][K] fp16 ====================
__global__ __launch_bounds__(256) void transpose_half_kernel(
    const float* __restrict__ W, __half* __restrict__ T, int K, int N)
{
    __shared__ float t[32][33];
    int tx = threadIdx.x & 31, ty = threadIdx.x >> 5;
    int k0 = blockIdx.y * 32, n0 = blockIdx.x * 32;
    #pragma unroll
    for (int i = 0; i < 4; i++)
        t[ty + i*8][tx] = W[(size_t)(k0 + ty + i*8) * N + n0 + tx];
    __syncthreads();
    #pragma unroll
    for (int i = 0; i < 4; i++)
        T[(size_t)(n0 + ty + i*8) * K + k0 + tx] = __float2half_rn(t[tx][ty + i*8]);
}

// ==================== block reduce ====================
__device__ __forceinline__ float block_reduce_sum(float v, float* sbuf) {
    #pragma unroll
    for (int o = 16; o > 0; o >>= 1) v += __shfl_xor_sync(0xffffffffu, v, o);
    int w = threadIdx.x >> 5;
    if ((threadIdx.x & 31) == 0) sbuf[w] = v;
    __syncthreads();
    if (threadIdx.x < 32) {
        float t = (threadIdx.x < 8) ? sbuf[threadIdx.x] : 0.0f;
        #pragma unroll
        for (int o = 4; o > 0; o >>= 1) t += __shfl_xor_sync(0xffffffffu, t, o);
        if (threadIdx.x == 0) sbuf[0] = t;
    }
    __syncthreads();
    float r = sbuf[0];
    __syncthreads();
    return r;
}

// ==================== LayerNorm -> fp16 ====================
__global__ __launch_bounds__(256) void ln_half_kernel(
    const float* __restrict__ X, const float* __restrict__ scale,
    const float* __restrict__ shift, __half* __restrict__ Y)
{
    __shared__ float sbuf[8];
    const int row = blockIdx.x;
    const float* x = X + (size_t)row * EMB;
    const int c0 = threadIdx.x * 4;

    float4 xv = *(const float4*)(x + c0);
    float s = xv.x + xv.y + xv.z + xv.w;
    float mean = block_reduce_sum(s, sbuf) * (1.0f / EMB);
    float dx = xv.x - mean, dy = xv.y - mean, dz = xv.z - mean, dw = xv.w - mean;
    float var = block_reduce_sum(dx*dx + dy*dy + dz*dz + dw*dw, sbuf) * (1.0f / EMB);
    float rstd = rsqrtf(var + 1e-5f);

    float4 sc = *(const float4*)(scale + c0);
    float4 sh = *(const float4*)(shift + c0);
    size_t o = (size_t)row * EMB + c0;
    *(uint32_t*)(Y + o)     = h2(sc.x * dx * rstd + sh.x, sc.y * dy * rstd + sh.y);
    *(uint32_t*)(Y + o + 2) = h2(sc.z * dz * rstd + sh.z, sc.w * dw * rstd + sh.w);
}

// ==================== fp16 mma.sync GEMM, 3-stage cp.async, 2 CTAs/SM ====================
// C[M][N] = A[M][K] @ B[N][K]^T, fp32 accumulate. CTA tile 128x128, K-chunk 64.
// EPI: 1 +bias+res -> fp32; 2 +bias GELU -> fp16; 3 plain -> fp16
#define STAGE_BYTES 32768
#define GEMM_SMEM   (3*STAGE_BYTES)

template<int EPI>
__global__ __launch_bounds__(256, 2)
void gemm_kernel(
    const __half* __restrict__ A, const __half* __restrict__ B,
    const float* __restrict__ bias, const float* __restrict__ res,
    float* __restrict__ C, __half* __restrict__ Ch,
    int M, int N, int K)
{
    extern __shared__ char smraw[];
    const uint32_t sbase = smem_u32(smraw);
    const int tid = threadIdx.x;
    const int bm = blockIdx.y, bn = blockIdx.x;

    const int w = tid >> 5, lane = tid & 31;
    const int wm = w & 1, wn = w >> 1;           // warp tile 64x32

    const int rowA = (lane & 7) + ((lane >> 3) & 1) * 8;
    const int chA  = (lane >> 4) & 1;
    const int gB   = lane >> 3;
    const int rB   = lane & 7;

    const int st_r0  = tid >> 3;
    const int st_seg = tid & 7;

    float acc[4][4][4];
    #pragma unroll
    for (int i = 0; i < 4; i++)
        #pragma unroll
        for (int j = 0; j < 4; j++)
            #pragma unroll
            for (int q = 0; q < 4; q++) acc[i][j][q] = 0.0f;

    const int nchunk = K >> 6;

    auto stage = [&](int s, int c) {
        const uint32_t sb = sbase + s * STAGE_BYTES;
        #pragma unroll
        for (int tl = 0; tl < 2; ++tl) {
            const __half* src = tl ? B : A;
            const int rbase = tl ? bn * 128 : bm * 128;
            #pragma unroll
            for (int j = 0; j < 4; ++j) {
                int idx = tid + j * 256;
                int r = idx >> 3, seg = idx & 7;
                cp_async16(sb + tl * 16384 + SWZ((uint32_t)(r * 128 + seg * 16)),
                           src + (size_t)(rbase + r) * K + c * 64 + seg * 8);
            }
        }
    };

    stage(0, 0); CP_COMMIT();
    if (nchunk > 1) { stage(1, 1); CP_COMMIT(); }

    for (int c = 0; c < nchunk; ++c) {
        const int s = c % 3;
        if (c == nchunk - 1) { CP_WAIT0(); } else { CP_WAIT1(); }
        __syncthreads();
        if (c + 2 < nchunk) { stage((c + 2) % 3, c + 2); CP_COMMIT(); }

        const uint32_t sA = sbase + s * STAGE_BYTES;
        const uint32_t sB = sA + 16384u;

        #pragma unroll
        for (int ks = 0; ks < 4; ++ks) {
            uint32_t ah[4][4], bh[2][4];
            #pragma unroll
            for (int mi = 0; mi < 4; ++mi) {
                uint32_t off = (uint32_t)((wm * 64 + mi * 16 + rowA) * 128 + (ks * 2 + chA) * 16);
                ldsm_x4(sA + SWZ(off), ah[mi]);
            }
            #pragma unroll
            for (int nb = 0; nb < 2; ++nb) {
                uint32_t off = (uint32_t)((wn * 32 + nb * 16 + (gB >> 1) * 8 + rB) * 128
                                          + ks * 32 + (gB & 1) * 16);
                ldsm_x4(sB + SWZ(off), bh[nb]);
            }
            #pragma unroll
            for (int mi = 0; mi < 4; ++mi)
                #pragma unroll
                for (int ni = 0; ni < 4; ++ni)
                    mma_f16(acc[mi][ni], ah[mi], bh[ni>>1][(ni&1)*2], bh[ni>>1][(ni&1)*2+1]);
        }
    }

    // epilogue
    const int g = lane >> 2, tid4 = lane & 3;
    #pragma unroll
    for (int mi = 0; mi < 4; ++mi) {
        #pragma unroll
        for (int half_ = 0; half_ < 2; ++half_) {
            const size_t row = (size_t)(bm * 128 + wm * 64 + mi * 16 + g + half_ * 8);
            #pragma unroll
            for (int ni = 0; ni < 4; ++ni) {
                const int col = bn * 128 + wn * 32 + ni * 8 + tid4 * 2;
                float v0 = acc[mi][ni][half_ * 2 + 0];
                float v1 = acc[mi][ni][half_ * 2 + 1];
                if (EPI == 1) {
                    float2 rv = *(const float2*)(res + row * N + col);
                    float2 bv = *(const float2*)(bias + col);
                    *(float2*)(C + row * N + col) =
                        make_float2(v0 + bv.x + rv.x, v1 + bv.y + rv.y);
                } else if (EPI == 2) {
                    float2 bv = *(const float2*)(bias + col);
                    *(uint32_t*)(Ch + row * N + col) =
                        h2(gelu_t(v0 + bv.x), gelu_t(v1 + bv.y));
                } else {
                    *(uint32_t*)(Ch + row * N + col) = h2(v0, v1);
                }
            }
        }
    }
}

// ==================== fp16 HMMA causal flash attention ====================
// BR=128, BC=64, 8 warps (warp w owns rows w*16..+15). Single-pass fp16.
// smem: Q 16KB @0; KV stage0: K@16384 V@24576; stage1: K@32768 V@40960
#define ATTN_SMEM 49152

__global__ __launch_bounds__(256) void attn_kernel(
    const __half* __restrict__ QKV, __half* __restrict__ O)
{
    extern __shared__ char smraw[];
    const uint32_t sbase = smem_u32(smraw);
    const uint32_t sQ = sbase;

    const int qb = gridDim.x - 1 - blockIdx.x;    // heavy tiles first
    const int h = blockIdx.y, b = blockIdx.z;
    const int tid = threadIdx.x;
    const int w = tid >> 5, lane = tid & 31;
    const int wq0 = w * 16;
    const int g = lane >> 2, c2 = (lane & 3) * 2;
    const size_t rows0 = (size_t)b * SEQ;
    const int hoff = h * HD;

    const int rowA = (lane & 7) + ((lane >> 3) & 1) * 8;
    const int chA  = (lane >> 4) & 1;
    const int gB   = lane >> 3;
    const int rB   = lane & 7;
    const int rowV = lane & 15;
    const int colV = (lane >> 4) * 8;

    // stage Q (128 rows x 64 fp16)
    for (int i = tid; i < 1024; i += 256) {
        int r = i >> 3, seg = i & 7;
        *(uint4*)(smraw + SWZ((uint32_t)(r * 128 + seg * 16))) =
            *(const uint4*)(QKV + (rows0 + qb * 128 + r) * QKV_LD + hoff + seg * 8);
    }

    auto stageKV = [&](int s, int jb) {
        uint32_t sb = sbase + 16384u + (uint32_t)s * 16384u;
        for (int i = tid; i < 512; i += 256) {
            int r = i >> 3, seg = i & 7;
            const size_t go = (rows0 + jb * 64 + r) * QKV_LD + hoff + seg * 8;
            uint32_t dst = SWZ((uint32_t)(r * 128 + seg * 16));
            cp_async16(sb + dst,         QKV + go + EMB);       // K
            cp_async16(sb + 8192u + dst, QKV + go + 2 * EMB);   // V
        }
    };

    float oacc[8][4];
    #pragma unroll
    for (int i = 0; i < 8; i++)
        #pragma unroll
        for (int q = 0; q < 4; q++) oacc[i][q] = 0.0f;
    float m0 = -1e30f, m1 = -1e30f, l0 = 0.0f, l1 = 0.0f;

    const int row0 = qb * 128 + wq0 + g;
    const int row1 = row0 + 8;
    const int njb = 2 * qb + 2;

    stageKV(0, 0); CP_COMMIT();

    for (int jb = 0; jb < njb; ++jb) {
        if (jb + 1 < njb) { stageKV((jb + 1) & 1, jb + 1); CP_COMMIT(); CP_WAIT1(); }
        else              { CP_WAIT0(); }
        __syncthreads();   // stage jb visible (and Q on jb=0)

        const uint32_t sK = sbase + 16384u + (uint32_t)(jb & 1) * 16384u;
        const uint32_t sV = sK + 8192u;

        // S = Q K^T
        float sacc[8][4];
        #pragma unroll
        for (int i = 0; i < 8; i++)
            #pragma unroll
            for (int q = 0; q < 4; q++) sacc[i][q] = 0.0f;

        #pragma unroll
        for (int ks = 0; ks < 4; ++ks) {
            uint32_t aq[4];
            ldsm_x4(sQ + SWZ((uint32_t)((wq0 + rowA) * 128 + (ks * 2 + chA) * 16)), aq);
            #pragma unroll
            for (int nb = 0; nb < 4; ++nb) {
                uint32_t bk[4];
                ldsm_x4(sK + SWZ((uint32_t)((nb * 16 + (gB >> 1) * 8 + rB) * 128
                                            + ks * 32 + (gB & 1) * 16)), bk);
                mma_f16(sacc[nb*2+0], aq, bk[0], bk[1]);
                mma_f16(sacc[nb*2+1], aq, bk[2], bk[3]);
            }
        }

        // scale + causal mask
        const int col0 = jb * 64;
        #pragma unroll
        for (int ni = 0; ni < 8; ++ni) {
            int cg = col0 + ni * 8 + c2;
            sacc[ni][0] = (cg     > row0) ? -1e30f : sacc[ni][0] * 0.125f;
            sacc[ni][1] = (cg + 1 > row0) ? -1e30f : sacc[ni][1] * 0.125f;
            sacc[ni][2] = (cg     > row1) ? -1e30f : sacc[ni][2] * 0.125f;
            sacc[ni][3] = (cg + 1 > row1) ? -1e30f : sacc[ni][3] * 0.125f;
        }

        // online softmax
        float rmax0 = -1e30f, rmax1 = -1e30f;
        #pragma unroll
        for (int ni = 0; ni < 8; ++ni) {
            rmax0 = fmaxf(rmax0, fmaxf(sacc[ni][0], sacc[ni][1]));
            rmax1 = fmaxf(rmax1, fmaxf(sacc[ni][2], sacc[ni][3]));
        }
        #pragma unroll
        for (int o = 1; o <= 2; o <<= 1) {
            rmax0 = fmaxf(rmax0, __shfl_xor_sync(0xffffffffu, rmax0, o));
            rmax1 = fmaxf(rmax1, __shfl_xor_sync(0xffffffffu, rmax1, o));
        }
        float mn0 = fmaxf(m0, rmax0), mn1 = fmaxf(m1, rmax1);
        float alpha0 = expf(m0 - mn0), alpha1 = expf(m1 - mn1);
        m0 = mn0; m1 = mn1;
        float rs0 = 0.0f, rs1 = 0.0f;
        #pragma unroll
        for (int ni = 0; ni < 8; ++ni) {
            sacc[ni][0] = expf(sacc[ni][0] - mn0);
            sacc[ni][1] = expf(sacc[ni][1] - mn0);
            sacc[ni][2] = expf(sacc[ni][2] - mn1);
            sacc[ni][3] = expf(sacc[ni][3] - mn1);
            rs0 += sacc[ni][0] + sacc[ni][1];
            rs1 += sacc[ni][2] + sacc[ni][3];
        }
        #pragma unroll
        for (int o = 1; o <= 2; o <<= 1) {
            rs0 += __shfl_xor_sync(0xffffffffu, rs0, o);
            rs1 += __shfl_xor_sync(0xffffffffu, rs1, o);
        }
        l0 = l0 * alpha0 + rs0;
        l1 = l1 * alpha1 + rs1;
        #pragma unroll
        for (int ni = 0; ni < 8; ++ni) {
            oacc[ni][0] *= alpha0; oacc[ni][1] *= alpha0;
            oacc[ni][2] *= alpha1; oacc[ni][3] *= alpha1;
        }

        // O += P V  (P fragments straight from sacc registers)
        #pragma unroll
        for (int kb = 0; kb < 4; ++kb) {
            uint32_t pa[4];
            pa[0] = h2(sacc[2*kb  ][0], sacc[2*kb  ][1]);
            pa[1] = h2(sacc[2*kb  ][2], sacc[2*kb  ][3]);
            pa[2] = h2(sacc[2*kb+1][0], sacc[2*kb+1][1]);
            pa[3] = h2(sacc[2*kb+1][2], sacc[2*kb+1][3]);
            #pragma unroll
            for (int nv = 0; nv < 4; ++nv) {
                uint32_t vv[4];
                ldsm_x4t(sV + SWZ((uint32_t)((kb * 16 + rowV) * 128 + (nv * 16 + colV) * 2)), vv);
                mma_f16(oacc[nv*2+0], pa, vv[0], vv[1]);
                mma_f16(oacc[nv*2+1], pa, vv[2], vv[3]);
            }
        }
        __syncthreads();   // readers done before next prefetch overwrites this stage
    }

    // write ctx fp16
    float il0 = 1.0f / l0, il1 = 1.0f / l1;
    const size_t gr0 = (rows0 + qb * 128 + wq0 + g) * EMB + hoff;
    const size_t gr1 = gr0 + 8 * EMB;
    #pragma unroll
    for (int ni = 0; ni < 8; ++ni) {
        int col = ni * 8 + c2;
        *(uint32_t*)(O + gr0 + col) = h2(oacc[ni][0] * il0, oacc[ni][1] * il0);
        *(uint32_t*)(O + gr1 + col) = h2(oacc[ni][2] * il1, oacc[ni][3] * il1);
    }
}

// ==================== host launch ====================
extern "C" void kernel_launch(void* const* d_in, const int* in_sizes, int n_in,
                              void* d_out, int out_size)
{
    const float* x    = (const float*)d_in[0];
    const float* Wq   = (const float*)d_in[1];
    const float* Wk   = (const float*)d_in[2];
    const float* Wv   = (const float*)d_in[3];
    const float* Wo   = (const float*)d_in[4];
    const float* bo   = (const float*)d_in[5];
    const float* W1   = (const float*)d_in[6];
    const float* b1   = (const float*)d_in[7];
    const float* W2   = (const float*)d_in[8];
    const float* b2   = (const float*)d_in[9];
    const float* ln1s = (const float*)d_in[10];
    const float* ln1b = (const float*)d_in[11];
    const float* ln2s = (const float*)d_in[12];
    const float* ln2b = (const float*)d_in[13];
    float* out = (float*)d_out;

    __half *hh, *qkv, *ctx, *mid, *wqkv, *wo, *w1, *w2;
    float *x1;
    cudaGetSymbolAddress((void**)&hh,   g_h);
    cudaGetSymbolAddress((void**)&qkv,  g_qkv);
    cudaGetSymbolAddress((void**)&ctx,  g_ctx);
    cudaGetSymbolAddress((void**)&x1,   g_x1);
    cudaGetSymbolAddress((void**)&mid,  g_mid);
    cudaGetSymbolAddress((void**)&wqkv, g_wqkv);
    cudaGetSymbolAddress((void**)&wo,   g_wo);
    cudaGetSymbolAddress((void**)&w1,   g_w1);
    cudaGetSymbolAddress((void**)&w2,   g_w2);

    cudaFuncSetAttribute(gemm_kernel<1>, cudaFuncAttributeMaxDynamicSharedMemorySize, GEMM_SMEM);
    cudaFuncSetAttribute(gemm_kernel<2>, cudaFuncAttributeMaxDynamicSharedMemorySize, GEMM_SMEM);
    cudaFuncSetAttribute(gemm_kernel<3>, cudaFuncAttributeMaxDynamicSharedMemorySize, GEMM_SMEM);
    cudaFuncSetAttribute(attn_kernel, cudaFuncAttributeMaxDynamicSharedMemorySize, ATTN_SMEM);

    transpose_half_kernel<<<dim3(EMB/32, EMB/32), 256>>>(Wq, wqkv,             EMB, EMB);
    transpose_half_kernel<<<dim3(EMB/32, EMB/32), 256>>>(Wk, wqkv + EMB*EMB,   EMB, EMB);
    transpose_half_kernel<<<dim3(EMB/32, EMB/32), 256>>>(Wv, wqkv + 2*EMB*EMB, EMB, EMB);
    ln_half_kernel<<<TOK, 256>>>(x, ln1s, ln1b, hh);
    transpose_half_kernel<<<dim3(EMB/32, EMB/32), 256>>>(Wo, wo, EMB, EMB);

    // fused QKV projection -> fp16
    gemm_kernel<3><<<dim3(QKV_LD/128, TOK/128), 256, GEMM_SMEM>>>(
        hh, wqkv, nullptr, nullptr, nullptr, qkv, TOK, QKV_LD, EMB);

    // attention -> ctx fp16
    attn_kernel<<<dim3(SEQ/128, HEADS, BATCH), 256, ATTN_SMEM>>>(qkv, ctx);

    transpose_half_kernel<<<dim3(FF/32,  EMB/32), 256>>>(W1, w1, EMB, FF);
    transpose_half_kernel<<<dim3(EMB/32, FF/32),  256>>>(W2, w2, FF, EMB);

    // Wo + bias + residual -> x1 (fp32)
    gemm_kernel<1><<<dim3(EMB/128, TOK/128), 256, GEMM_SMEM>>>(
        ctx, wo, bo, x, x1, nullptr, TOK, EMB, EMB);

    // LN2 -> h fp16
    ln_half_kernel<<<TOK, 256>>>(x1, ln2s, ln2b, hh);

    // FFN up + GELU -> mid fp16
    gemm_kernel<2><<<dim3(FF/128, TOK/128), 256, GEMM_SMEM>>>(
        hh, w1, b1, nullptr, nullptr, mid, TOK, FF, EMB);

    // FFN down + bias + residual -> out fp32
    gemm_kernel<1><<<dim3(EMB/128, TOK/128), 256, GEMM_SMEM>>>(
        mid, w2, b2, x1, out, nullptr, TOK, EMB, FF);
}

// round 8
// speedup vs baseline: 6.9599x; 1.0354x over previous
#include <cuda_runtime.h>
#include <cuda_fp16.h>
#include <math.h>
#include <float.h>
#include <stdint.h>

#define BATCH 2
#define SEQ   2048
#define TOK   (BATCH*SEQ)        // 4096
#define EMB   1024
#define HEADS 16
#define HD    64
#define FF    4096
#define QKV_LD 3072

// ==================== helpers ====================
__device__ __forceinline__ uint32_t smem_u32(const void* p) {
    uint32_t a;
    asm("{ .reg .u64 t; cvta.to.shared.u64 t, %1; cvt.u32.u64 %0, t; }" : "=r"(a) : "l"(p));
    return a;
}
#define SWZ(x) ((x) ^ (((x) >> 3) & 0x70))

__device__ __forceinline__ void cp_async16(uint32_t saddr, const void* gptr) {
    asm volatile("cp.async.cg.shared.global [%0], [%1], 16;" :: "r"(saddr), "l"(gptr));
}
#define CP_COMMIT() asm volatile("cp.async.commit_group;" ::: "memory")
#define CP_WAIT2()  asm volatile("cp.async.wait_group 2;" ::: "memory")
#define CP_WAIT1()  asm volatile("cp.async.wait_group 1;" ::: "memory")
#define CP_WAIT0()  asm volatile("cp.async.wait_group 0;" ::: "memory")

__device__ __forceinline__ void ldsm_x4(uint32_t addr, uint32_t r[4]) {
    asm volatile("ldmatrix.sync.aligned.m8n8.x4.shared.b16 {%0,%1,%2,%3}, [%4];"
                 : "=r"(r[0]), "=r"(r[1]), "=r"(r[2]), "=r"(r[3]) : "r"(addr));
}
__device__ __forceinline__ void ldsm_x4t(uint32_t addr, uint32_t r[4]) {
    asm volatile("ldmatrix.sync.aligned.m8n8.x4.trans.shared.b16 {%0,%1,%2,%3}, [%4];"
                 : "=r"(r[0]), "=r"(r[1]), "=r"(r[2]), "=r"(r[3]) : "r"(addr));
}
__device__ __forceinline__ void mma_f16(float c[4], const uint32_t a[4], const uint32_t b0, const uint32_t b1) {
    asm volatile("mma.sync.aligned.m16n8k16.row.col.f32.f16.f16.f32 "
                 "{%0,%1,%2,%3}, {%4,%5,%6,%7}, {%8,%9}, {%0,%1,%2,%3};"
                 : "+f"(c[0]), "+f"(c[1]), "+f"(c[2]), "+f"(c[3])
                 : "r"(a[0]), "r"(a[1]), "r"(a[2]), "r"(a[3]), "r"(b0), "r"(b1));
}
__device__ __forceinline__ uint32_t h2(float a, float b) {
    __half2 t = __floats2half2_rn(a, b);
    return *(uint32_t*)&t;
}
__device__ __forceinline__ float gelu_t(float v) {
    float t = tanhf(0.7978845608028654f * (v + 0.044715f * v * v * v));
    return 0.5f * v * (1.0f + t);
}

// ==================== scratch (device globals) ====================
__device__ __half g_h[TOK*EMB];
__device__ __half g_qkv[TOK*QKV_LD];
__device__ __half g_ctx[TOK*EMB];
__device__ float  g_x1[TOK*EMB];
__device__ __half g_mid[TOK*FF];
__device__ __half g_wqkv[QKV_LD*EMB];   // [N=3072][K=1024]
__device__ __half g_wo[EMB*EMB];
__device__ __half g_w1[EMB*FF];         // [N=FF][K=EMB]
__device__ __half g_w2[FF*EMB];         // [N=EMB][K=FF]

// ==================== batched square transpose: 4x W[1024][1024] -> T[N][K] fp16 ====================
__global__ __launch_bounds__(256) void transpose4_kernel(
    const float* __restrict__ Wq, const float* __restrict__ Wk,
    const float* __restrict__ Wv, const float* __restrict__ Wo,
    __half* __restrict__ Tq, __half* __restrict__ Tk,
    __half* __restrict__ Tv, __half* __restrict__ To)
{
    __shared__ float t[32][33];
    const float* W = (blockIdx.z == 0) ? Wq : (blockIdx.z == 1) ? Wk : (blockIdx.z == 2) ? Wv : Wo;
    __half*      T = (blockIdx.z == 0) ? Tq : (blockIdx.z == 1) ? Tk : (blockIdx.z == 2) ? Tv : To;
    int tx = threadIdx.x & 31, ty = threadIdx.x >> 5;
    int k0 = blockIdx.y * 32, n0 = blockIdx.x * 32;
    #pragma unroll
    for (int i = 0; i < 4; i++)
        t[ty + i*8][tx] = W[(size_t)(k0 + ty + i*8) * EMB + n0 + tx];
    __syncthreads();
    #pragma unroll
    for (int i = 0; i < 4; i++)
        T[(size_t)(n0 + ty + i*8) * EMB + k0 + tx] = __float2half_rn(t[tx][ty + i*8]);
}

// ==================== rect transpose: W[K][N] -> T[N][K] fp16 ====================
__global__ __launch_bounds__(256) void transpose_half_kernel(
    const float* __restrict__ W, __half* __restrict__ T, int K, int N)
{
    __shared__ float t[32][33];
    int tx = threadIdx.x & 31, ty = threadIdx.x >> 5;
    int k0 = blockIdx.y * 32, n0 = blockIdx.x * 32;
    #pragma unroll
    for (int i = 0; i < 4; i++)
        t[ty + i*8][tx] = W[(size_t)(k0 + ty + i*8) * N + n0 + tx];
    __syncthreads();
    #pragma unroll
    for (int i = 0; i < 4; i++)
        T[(size_t)(n0 + ty + i*8) * K + k0 + tx] = __float2half_rn(t[tx][ty + i*8]);
}

// ==================== block reduce ====================
__device__ __forceinline__ float block_reduce_sum(float v, float* sbuf) {
    #pragma unroll
    for (int o = 16; o > 0; o >>= 1) v += __shfl_xor_sync(0xffffffffu, v, o);
    int w = threadIdx.x >> 5;
    if ((threadIdx.x & 31) == 0) sbuf[w] = v;
    __syncthreads();
    if (threadIdx.x < 32) {
        float t = (threadIdx.x < 8) ? sbuf[threadIdx.x] : 0.0f;
        #pragma unroll
        for (int o = 4; o > 0; o >>= 1) t += __shfl_xor_sync(0xffffffffu, t, o);
        if (threadIdx.x == 0) sbuf[0] = t;
    }
    __syncthreads();
    float r = sbuf[0];
    __syncthreads();
    return r;
}

// ==================== LayerNorm -> fp16 ====================
__global__ __launch_bounds__(256) void ln_half_kernel(
    const float* __restrict__ X, const float* __restrict__ scale,
    const float* __restrict__ shift, __half* __restrict__ Y)
{
    __shared__ float sbuf[8];
    const int row = blockIdx.x;
    const float* x = X + (size_t)row * EMB;
    const int c0 = threadIdx.x * 4;

    float4 xv = *(const float4*)(x + c0);
    float s = xv.x + xv.y + xv.z + xv.w;
    float mean = block_reduce_sum(s, sbuf) * (1.0f / EMB);
    float dx = xv.x - mean, dy = xv.y - mean, dz = xv.z - mean, dw = xv.w - mean;
    float var = block_reduce_sum(dx*dx + dy*dy + dz*dz + dw*dw, sbuf) * (1.0f / EMB);
    float rstd = rsqrtf(var + 1e-5f);

    float4 sc = *(const float4*)(scale + c0);
    float4 sh = *(const float4*)(shift + c0);
    size_t o = (size_t)row * EMB + c0;
    *(uint32_t*)(Y + o)     = h2(sc.x * dx * rstd + sh.x, sc.y * dy * rstd + sh.y);
    *(uint32_t*)(Y + o + 2) = h2(sc.z * dz * rstd + sh.z, sc.w * dw * rstd + sh.w);
}

// ==================== fp16 mma.sync GEMM, 3-stage cp.async, 2 CTAs/SM ====================
// C[M][N] = A[M][K] @ B[N][K]^T, fp32 accumulate. CTA tile 128x128, K-chunk 64.
// EPI: 1 +bias+res -> fp32; 2 +bias GELU -> fp16; 3 plain -> fp16
#define STAGE_BYTES 32768
#define GEMM_SMEM   (3*STAGE_BYTES)

template<int EPI>
__global__ __launch_bounds__(256, 2)
void gemm_kernel(
    const __half* __restrict__ A, const __half* __restrict__ B,
    const float* __restrict__ bias, const float* __restrict__ res,
    float* __restrict__ C, __half* __restrict__ Ch,
    int M, int N, int K)
{
    extern __shared__ char smraw[];
    const uint32_t sbase = smem_u32(smraw);
    const int tid = threadIdx.x;
    const int bm = blockIdx.y, bn = blockIdx.x;

    const int w = tid >> 5, lane = tid & 31;
    const int wm = w & 1, wn = w >> 1;           // warp tile 64x32

    const int rowA = (lane & 7) + ((lane >> 3) & 1) * 8;
    const int chA  = (lane >> 4) & 1;
    const int gB   = lane >> 3;
    const int rB   = lane & 7;

    float acc[4][4][4];
    #pragma unroll
    for (int i = 0; i < 4; i++)
        #pragma unroll
        for (int j = 0; j < 4; j++)
            #pragma unroll
            for (int q = 0; q < 4; q++) acc[i][j][q] = 0.0f;

    const int nchunk = K >> 6;

    auto stage = [&](int s, int c) {
        const uint32_t sb = sbase + s * STAGE_BYTES;
        #pragma unroll
        for (int tl = 0; tl < 2; ++tl) {
            const __half* src = tl ? B : A;
            const int rbase = tl ? bn * 128 : bm * 128;
            #pragma unroll
            for (int j = 0; j < 4; ++j) {
                int idx = tid + j * 256;
                int r = idx >> 3, seg = idx & 7;
                cp_async16(sb + tl * 16384 + SWZ((uint32_t)(r * 128 + seg * 16)),
                           src + (size_t)(rbase + r) * K + c * 64 + seg * 8);
            }
        }
    };

    stage(0, 0); CP_COMMIT();
    if (nchunk > 1) { stage(1, 1); CP_COMMIT(); }

    for (int c = 0; c < nchunk; ++c) {
        const int s = c % 3;
        if (c == nchunk - 1) { CP_WAIT0(); } else { CP_WAIT1(); }
        __syncthreads();
        if (c + 2 < nchunk) { stage((c + 2) % 3, c + 2); CP_COMMIT(); }

        const uint32_t sA = sbase + s * STAGE_BYTES;
        const uint32_t sB = sA + 16384u;

        #pragma unroll
        for (int ks = 0; ks < 4; ++ks) {
            uint32_t ah[4][4], bh[2][4];
            #pragma unroll
            for (int mi = 0; mi < 4; ++mi) {
                uint32_t off = (uint32_t)((wm * 64 + mi * 16 + rowA) * 128 + (ks * 2 + chA) * 16);
                ldsm_x4(sA + SWZ(off), ah[mi]);
            }
            #pragma unroll
            for (int nb = 0; nb < 2; ++nb) {
                uint32_t off = (uint32_t)((wn * 32 + nb * 16 + (gB >> 1) * 8 + rB) * 128
                                          + ks * 32 + (gB & 1) * 16);
                ldsm_x4(sB + SWZ(off), bh[nb]);
            }
            #pragma unroll
            for (int mi = 0; mi < 4; ++mi)
                #pragma unroll
                for (int ni = 0; ni < 4; ++ni)
                    mma_f16(acc[mi][ni], ah[mi], bh[ni>>1][(ni&1)*2], bh[ni>>1][(ni&1)*2+1]);
        }
    }

    // epilogue
    const int g = lane >> 2, tid4 = lane & 3;
    #pragma unroll
    for (int mi = 0; mi < 4; ++mi) {
        #pragma unroll
        for (int half_ = 0; half_ < 2; ++half_) {
            const size_t row = (size_t)(bm * 128 + wm * 64 + mi * 16 + g + half_ * 8);
            #pragma unroll
            for (int ni = 0; ni < 4; ++ni) {
                const int col = bn * 128 + wn * 32 + ni * 8 + tid4 * 2;
                float v0 = acc[mi][ni][half_ * 2 + 0];
                float v1 = acc[mi][ni][half_ * 2 + 1];
                if (EPI == 1) {
                    float2 rv = *(const float2*)(res + row * N + col);
                    float2 bv = *(const float2*)(bias + col);
                    *(float2*)(C + row * N + col) =
                        make_float2(v0 + bv.x + rv.x, v1 + bv.y + rv.y);
                } else if (EPI == 2) {
                    float2 bv = *(const float2*)(bias + col);
                    *(uint32_t*)(Ch + row * N + col) =
                        h2(gelu_t(v0 + bv.x), gelu_t(v1 + bv.y));
                } else {
                    *(uint32_t*)(Ch + row * N + col) = h2(v0, v1);
                }
            }
        }
    }
}

// ==================== fp16 HMMA causal flash attention, 3-stage KV ====================
// BR=128, BC=64, 8 warps (warp w owns rows w*16..+15). Single-pass fp16.
// smem: Q 16KB @0; KV stages s=0..2 at 16384+s*16384 (K 8KB, V 8KB each)
#define ATTN_SMEM 65536

__global__ __launch_bounds__(256, 2) void attn_kernel(
    const __half* __restrict__ QKV, __half* __restrict__ O)
{
    extern __shared__ char smraw[];
    const uint32_t sbase = smem_u32(smraw);
    const uint32_t sQ = sbase;

    const int qb = gridDim.x - 1 - blockIdx.x;    // heavy tiles first
    const int h = blockIdx.y, b = blockIdx.z;
    const int tid = threadIdx.x;
    const int w = tid >> 5, lane = tid & 31;
    const int wq0 = w * 16;
    const int g = lane >> 2, c2 = (lane & 3) * 2;
    const size_t rows0 = (size_t)b * SEQ;
    const int hoff = h * HD;

    const int rowA = (lane & 7) + ((lane >> 3) & 1) * 8;
    const int chA  = (lane >> 4) & 1;
    const int gB   = lane >> 3;
    const int rB   = lane & 7;
    const int rowV = lane & 15;
    const int colV = (lane >> 4) * 8;

    // stage Q (128 rows x 64 fp16) -- plain stores, covered by first __syncthreads
    for (int i = tid; i < 1024; i += 256) {
        int r = i >> 3, seg = i & 7;
        *(uint4*)(smraw + SWZ((uint32_t)(r * 128 + seg * 16))) =
            *(const uint4*)(QKV + (rows0 + qb * 128 + r) * QKV_LD + hoff + seg * 8);
    }

    auto stageKV = [&](int s, int jb) {
        uint32_t sb = sbase + 16384u + (uint32_t)s * 16384u;
        for (int i = tid; i < 512; i += 256) {
            int r = i >> 3, seg = i & 7;
            const size_t go = (rows0 + jb * 64 + r) * QKV_LD + hoff + seg * 8;
            uint32_t dst = SWZ((uint32_t)(r * 128 + seg * 16));
            cp_async16(sb + dst,         QKV + go + EMB);       // K
            cp_async16(sb + 8192u + dst, QKV + go + 2 * EMB);   // V
        }
    };

    float oacc[8][4];
    #pragma unroll
    for (int i = 0; i < 8; i++)
        #pragma unroll
        for (int q = 0; q < 4; q++) oacc[i][q] = 0.0f;
    float m0 = -1e30f, m1 = -1e30f, l0 = 0.0f, l1 = 0.0f;

    const int row0 = qb * 128 + wq0 + g;
    const int row1 = row0 + 8;
    const int njb = 2 * qb + 2;

    stageKV(0, 0); CP_COMMIT();
    if (njb > 1) { stageKV(1, 1); CP_COMMIT(); }

    for (int jb = 0; jb < njb; ++jb) {
        if (jb == njb - 1)      { CP_WAIT0(); }
        else if (jb == njb - 2) { CP_WAIT1(); }
        else                    { CP_WAIT2(); }
        __syncthreads();   // stage jb visible everywhere; previous readers done
        if (jb + 2 < njb) { stageKV((jb + 2) % 3, jb + 2); CP_COMMIT(); }

        const uint32_t sK = sbase + 16384u + (uint32_t)(jb % 3) * 16384u;
        const uint32_t sV = sK + 8192u;

        // S = Q K^T
        float sacc[8][4];
        #pragma unroll
        for (int i = 0; i < 8; i++)
            #pragma unroll
            for (int q = 0; q < 4; q++) sacc[i][q] = 0.0f;

        #pragma unroll
        for (int ks = 0; ks < 4; ++ks) {
            uint32_t aq[4];
            ldsm_x4(sQ + SWZ((uint32_t)((wq0 + rowA) * 128 + (ks * 2 + chA) * 16)), aq);
            #pragma unroll
            for (int nb = 0; nb < 4; ++nb) {
                uint32_t bk[4];
                ldsm_x4(sK + SWZ((uint32_t)((nb * 16 + (gB >> 1) * 8 + rB) * 128
                                            + ks * 32 + (gB & 1) * 16)), bk);
                mma_f16(sacc[nb*2+0], aq, bk[0], bk[1]);
                mma_f16(sacc[nb*2+1], aq, bk[2], bk[3]);
            }
        }

        // scale + causal mask
        const int col0 = jb * 64;
        #pragma unroll
        for (int ni = 0; ni < 8; ++ni) {
            int cg = col0 + ni * 8 + c2;
            sacc[ni][0] = (cg     > row0) ? -1e30f : sacc[ni][0] * 0.125f;
            sacc[ni][1] = (cg + 1 > row0) ? -1e30f : sacc[ni][1] * 0.125f;
            sacc[ni][2] = (cg     > row1) ? -1e30f : sacc[ni][2] * 0.125f;
            sacc[ni][3] = (cg + 1 > row1) ? -1e30f : sacc[ni][3] * 0.125f;
        }

        // online softmax (fast exp)
        float rmax0 = -1e30f, rmax1 = -1e30f;
        #pragma unroll
        for (int ni = 0; ni < 8; ++ni) {
            rmax0 = fmaxf(rmax0, fmaxf(sacc[ni][0], sacc[ni][1]));
            rmax1 = fmaxf(rmax1, fmaxf(sacc[ni][2], sacc[ni][3]));
        }
        #pragma unroll
        for (int o = 1; o <= 2; o <<= 1) {
            rmax0 = fmaxf(rmax0, __shfl_xor_sync(0xffffffffu, rmax0, o));
            rmax1 = fmaxf(rmax1, __shfl_xor_sync(0xffffffffu, rmax1, o));
        }
        float mn0 = fmaxf(m0, rmax0), mn1 = fmaxf(m1, rmax1);
        float alpha0 = __expf(m0 - mn0), alpha1 = __expf(m1 - mn1);
        m0 = mn0; m1 = mn1;
        float rs0 = 0.0f, rs1 = 0.0f;
        #pragma unroll
        for (int ni = 0; ni < 8; ++ni) {
            sacc[ni][0] = __expf(sacc[ni][0] - mn0);
            sacc[ni][1] = __expf(sacc[ni][1] - mn0);
            sacc[ni][2] = __expf(sacc[ni][2] - mn1);
            sacc[ni][3] = __expf(sacc[ni][3] - mn1);
            rs0 += sacc[ni][0] + sacc[ni][1];
            rs1 += sacc[ni][2] + sacc[ni][3];
        }
        #pragma unroll
        for (int o = 1; o <= 2; o <<= 1) {
            rs0 += __shfl_xor_sync(0xffffffffu, rs0, o);
            rs1 += __shfl_xor_sync(0xffffffffu, rs1, o);
        }
        l0 = l0 * alpha0 + rs0;
        l1 = l1 * alpha1 + rs1;
        #pragma unroll
        for (int ni = 0; ni < 8; ++ni) {
            oacc[ni][0] *= alpha0; oacc[ni][1] *= alpha0;
            oacc[ni][2] *= alpha1; oacc[ni][3] *= alpha1;
        }

        // O += P V  (P fragments straight from sacc registers)
        #pragma unroll
        for (int kb = 0; kb < 4; ++kb) {
            uint32_t pa[4];
            pa[0] = h2(sacc[2*kb  ][0], sacc[2*kb  ][1]);
            pa[1] = h2(sacc[2*kb  ][2], sacc[2*kb  ][3]);
            pa[2] = h2(sacc[2*kb+1][0], sacc[2*kb+1][1]);
            pa[3] = h2(sacc[2*kb+1][2], sacc[2*kb+1][3]);
            #pragma unroll
            for (int nv = 0; nv < 4; ++nv) {
                uint32_t vv[4];
                ldsm_x4t(sV + SWZ((uint32_t)((kb * 16 + rowV) * 128 + (nv * 16 + colV) * 2)), vv);
                mma_f16(oacc[nv*2+0], pa, vv[0], vv[1]);
                mma_f16(oacc[nv*2+1], pa, vv[2], vv[3]);
            }
        }
    }

    // write ctx fp16
    float il0 = 1.0f / l0, il1 = 1.0f / l1;
    const size_t gr0 = (rows0 + qb * 128 + wq0 + g) * EMB + hoff;
    const size_t gr1 = gr0 + 8 * EMB;
    #pragma unroll
    for (int ni = 0; ni < 8; ++ni) {
        int col = ni * 8 + c2;
        *(uint32_t*)(O + gr0 + col) = h2(oacc[ni][0] * il0, oacc[ni][1] * il0);
        *(uint32_t*)(O + gr1 + col) = h2(oacc[ni][2] * il1, oacc[ni][3] * il1);
    }
}

// ==================== host launch ====================
extern "C" void kernel_launch(void* const* d_in, const int* in_sizes, int n_in,
                              void* d_out, int out_size)
{
    const float* x    = (const float*)d_in[0];
    const float* Wq   = (const float*)d_in[1];
    const float* Wk   = (const float*)d_in[2];
    const float* Wv   = (const float*)d_in[3];
    const float* Wo   = (const float*)d_in[4];
    const float* bo   = (const float*)d_in[5];
    const float* W1   = (const float*)d_in[6];
    const float* b1   = (const float*)d_in[7];
    const float* W2   = (const float*)d_in[8];
    const float* b2   = (const float*)d_in[9];
    const float* ln1s = (const float*)d_in[10];
    const float* ln1b = (const float*)d_in[11];
    const float* ln2s = (const float*)d_in[12];
    const float* ln2b = (const float*)d_in[13];
    float* out = (float*)d_out;

    __half *hh, *qkv, *ctx, *mid, *wqkv, *wo, *w1, *w2;
    float *x1;
    cudaGetSymbolAddress((void**)&hh,   g_h);
    cudaGetSymbolAddress((void**)&qkv,  g_qkv);
    cudaGetSymbolAddress((void**)&ctx,  g_ctx);
    cudaGetSymbolAddress((void**)&x1,   g_x1);
    cudaGetSymbolAddress((void**)&mid,  g_mid);
    cudaGetSymbolAddress((void**)&wqkv, g_wqkv);
    cudaGetSymbolAddress((void**)&wo,   g_wo);
    cudaGetSymbolAddress((void**)&w1,   g_w1);
    cudaGetSymbolAddress((void**)&w2,   g_w2);

    cudaFuncSetAttribute(gemm_kernel<1>, cudaFuncAttributeMaxDynamicSharedMemorySize, GEMM_SMEM);
    cudaFuncSetAttribute(gemm_kernel<2>, cudaFuncAttributeMaxDynamicSharedMemorySize, GEMM_SMEM);
    cudaFuncSetAttribute(gemm_kernel<3>, cudaFuncAttributeMaxDynamicSharedMemorySize, GEMM_SMEM);
    cudaFuncSetAttribute(attn_kernel, cudaFuncAttributeMaxDynamicSharedMemorySize, ATTN_SMEM);

    // batched weight transpose (Wq|Wk|Wv -> fused wqkv, Wo) + LN1
    transpose4_kernel<<<dim3(EMB/32, EMB/32, 4), 256>>>(
        Wq, Wk, Wv, Wo, wqkv, wqkv + EMB*EMB, wqkv + 2*EMB*EMB, wo);
    ln_half_kernel<<<TOK, 256>>>(x, ln1s, ln1b, hh);
    transpose_half_kernel<<<dim3(FF/32,  EMB/32), 256>>>(W1, w1, EMB, FF);
    transpose_half_kernel<<<dim3(EMB/32, FF/32),  256>>>(W2, w2, FF, EMB);

    // fused QKV projection -> fp16
    gemm_kernel<3><<<dim3(QKV_LD/128, TOK/128), 256, GEMM_SMEM>>>(
        hh, wqkv, nullptr, nullptr, nullptr, qkv, TOK, QKV_LD, EMB);

    // attention -> ctx fp16
    attn_kernel<<<dim3(SEQ/128, HEADS, BATCH), 256, ATTN_SMEM>>>(qkv, ctx);

    // Wo + bias + residual -> x1 (fp32)
    gemm_kernel<1><<<dim3(EMB/128, TOK/128), 256, GEMM_SMEM>>>(
        ctx, wo, bo, x, x1, nullptr, TOK, EMB, EMB);

    // LN2 -> h fp16
    ln_half_kernel<<<TOK, 256>>>(x1, ln2s, ln2b, hh);

    // FFN up + GELU -> mid fp16
    gemm_kernel<2><<<dim3(FF/128, TOK/128), 256, GEMM_SMEM>>>(
        hh, w1, b1, nullptr, nullptr, mid, TOK, FF, EMB);

    // FFN down + bias + residual -> out fp32
    gemm_kernel<1><<<dim3(EMB/128, TOK/128), 256, GEMM_SMEM>>>(
        mid, w2, b2, x1, out, nullptr, TOK, EMB, FF);
}

// round 9
// speedup vs baseline: 7.2631x; 1.0436x over previous
#include <cuda_runtime.h>
#include <cuda_fp16.h>
#include <math.h>
#include <float.h>
#include <stdint.h>

#define BATCH 2
#define SEQ   2048
#define TOK   (BATCH*SEQ)        // 4096
#define EMB   1024
#define HEADS 16
#define HD    64
#define FF    4096
#define QKV_LD 3072

// ==================== helpers ====================
__device__ __forceinline__ uint32_t smem_u32(const void* p) {
    uint32_t a;
    asm("{ .reg .u64 t; cvta.to.shared.u64 t, %1; cvt.u32.u64 %0, t; }" : "=r"(a) : "l"(p));
    return a;
}
#define SWZ(x) ((x) ^ (((x) >> 3) & 0x70))

__device__ __forceinline__ void cp_async16(uint32_t saddr, const void* gptr) {
    asm volatile("cp.async.cg.shared.global [%0], [%1], 16;" :: "r"(saddr), "l"(gptr));
}
#define CP_COMMIT() asm volatile("cp.async.commit_group;" ::: "memory")
#define CP_WAIT2()  asm volatile("cp.async.wait_group 2;" ::: "memory")
#define CP_WAIT1()  asm volatile("cp.async.wait_group 1;" ::: "memory")
#define CP_WAIT0()  asm volatile("cp.async.wait_group 0;" ::: "memory")

__device__ __forceinline__ void ldsm_x4(uint32_t addr, uint32_t r[4]) {
    asm volatile("ldmatrix.sync.aligned.m8n8.x4.shared.b16 {%0,%1,%2,%3}, [%4];"
                 : "=r"(r[0]), "=r"(r[1]), "=r"(r[2]), "=r"(r[3]) : "r"(addr));
}
__device__ __forceinline__ void ldsm_x4t(uint32_t addr, uint32_t r[4]) {
    asm volatile("ldmatrix.sync.aligned.m8n8.x4.trans.shared.b16 {%0,%1,%2,%3}, [%4];"
                 : "=r"(r[0]), "=r"(r[1]), "=r"(r[2]), "=r"(r[3]) : "r"(addr));
}
__device__ __forceinline__ void mma_f16(float c[4], const uint32_t a[4], const uint32_t b0, const uint32_t b1) {
    asm volatile("mma.sync.aligned.m16n8k16.row.col.f32.f16.f16.f32 "
                 "{%0,%1,%2,%3}, {%4,%5,%6,%7}, {%8,%9}, {%0,%1,%2,%3};"
                 : "+f"(c[0]), "+f"(c[1]), "+f"(c[2]), "+f"(c[3])
                 : "r"(a[0]), "r"(a[1]), "r"(a[2]), "r"(a[3]), "r"(b0), "r"(b1));
}
__device__ __forceinline__ uint32_t h2(float a, float b) {
    __half2 t = __floats2half2_rn(a, b);
    return *(uint32_t*)&t;
}
__device__ __forceinline__ uint32_t ex2_f16x2(uint32_t x) {
    uint32_t r;
    asm("ex2.approx.f16x2 %0, %1;" : "=r"(r) : "r"(x));
    return r;
}
__device__ __forceinline__ float ex2f(float x) {
    float r;
    asm("ex2.approx.f32 %0, %1;" : "=f"(r) : "f"(x));
    return r;
}
__device__ __forceinline__ float gelu_t(float v) {
    float t = tanhf(0.7978845608028654f * (v + 0.044715f * v * v * v));
    return 0.5f * v * (1.0f + t);
}
#define ONES_H2 0x3C003C00u   // (1.0h, 1.0h)

// ==================== scratch (device globals) ====================
__device__ __half g_h[TOK*EMB];
__device__ __half g_qkv[TOK*QKV_LD];
__device__ __half g_ctx[TOK*EMB];
__device__ float  g_x1[TOK*EMB];
__device__ __half g_mid[TOK*FF];
__device__ __half g_wqkv[QKV_LD*EMB];   // [N=3072][K=1024]
__device__ __half g_wo[EMB*EMB];
__device__ __half g_w1[EMB*FF];         // [N=FF][K=EMB]
__device__ __half g_w2[FF*EMB];         // [N=EMB][K=FF]

// ==================== batched square transpose: 4x W[1024][1024] -> T[N][K] fp16 ====================
__global__ __launch_bounds__(256) void transpose4_kernel(
    const float* __restrict__ Wq, const float* __restrict__ Wk,
    const float* __restrict__ Wv, const float* __restrict__ Wo,
    __half* __restrict__ Tq, __half* __restrict__ Tk,
    __half* __restrict__ Tv, __half* __restrict__ To)
{
    __shared__ float t[32][33];
    const float* W = (blockIdx.z == 0) ? Wq : (blockIdx.z == 1) ? Wk : (blockIdx.z == 2) ? Wv : Wo;
    __half*      T = (blockIdx.z == 0) ? Tq : (blockIdx.z == 1) ? Tk : (blockIdx.z == 2) ? Tv : To;
    int tx = threadIdx.x & 31, ty = threadIdx.x >> 5;
    int k0 = blockIdx.y * 32, n0 = blockIdx.x * 32;
    #pragma unroll
    for (int i = 0; i < 4; i++)
        t[ty + i*8][tx] = W[(size_t)(k0 + ty + i*8) * EMB + n0 + tx];
    __syncthreads();
    #pragma unroll
    for (int i = 0; i < 4; i++)
        T[(size_t)(n0 + ty + i*8) * EMB + k0 + tx] = __float2half_rn(t[tx][ty + i*8]);
}

// ==================== rect transpose: W[K][N] -> T[N][K] fp16 ====================
__global__ __launch_bounds__(256) void transpose_half_kernel(
    const float* __restrict__ W, __half* __restrict__ T, int K, int N)
{
    __shared__ float t[32][33];
    int tx = threadIdx.x & 31, ty = threadIdx.x >> 5;
    int k0 = blockIdx.y * 32, n0 = blockIdx.x * 32;
    #pragma unroll
    for (int i = 0; i < 4; i++)
        t[ty + i*8][tx] = W[(size_t)(k0 + ty + i*8) * N + n0 + tx];
    __syncthreads();
    #pragma unroll
    for (int i = 0; i < 4; i++)
        T[(size_t)(n0 + ty + i*8) * K + k0 + tx] = __float2half_rn(t[tx][ty + i*8]);
}

// ==================== LayerNorm -> fp16, warp-per-row ====================
__global__ __launch_bounds__(256) void ln_half_kernel(
    const float* __restrict__ X, const float* __restrict__ scale,
    const float* __restrict__ shift, __half* __restrict__ Y)
{
    const int lane = threadIdx.x & 31;
    const int row  = blockIdx.x * 8 + (threadIdx.x >> 5);
    const float* x = X + (size_t)row * EMB;

    float4 v[8];
    float s = 0.0f;
    #pragma unroll
    for (int i = 0; i < 8; i++) {
        v[i] = *(const float4*)(x + (i * 32 + lane) * 4);
        s += v[i].x + v[i].y + v[i].z + v[i].w;
    }
    #pragma unroll
    for (int o = 16; o > 0; o >>= 1) s += __shfl_xor_sync(0xffffffffu, s, o);
    float mean = s * (1.0f / EMB);

    float sq = 0.0f;
    #pragma unroll
    for (int i = 0; i < 8; i++) {
        v[i].x -= mean; v[i].y -= mean; v[i].z -= mean; v[i].w -= mean;
        sq += v[i].x*v[i].x + v[i].y*v[i].y + v[i].z*v[i].z + v[i].w*v[i].w;
    }
    #pragma unroll
    for (int o = 16; o > 0; o >>= 1) sq += __shfl_xor_sync(0xffffffffu, sq, o);
    float rstd = rsqrtf(sq * (1.0f / EMB) + 1e-5f);

    #pragma unroll
    for (int i = 0; i < 8; i++) {
        int c0 = (i * 32 + lane) * 4;
        float4 sc = *(const float4*)(scale + c0);
        float4 sh = *(const float4*)(shift + c0);
        size_t o = (size_t)row * EMB + c0;
        *(uint32_t*)(Y + o)     = h2(sc.x * v[i].x * rstd + sh.x, sc.y * v[i].y * rstd + sh.y);
        *(uint32_t*)(Y + o + 2) = h2(sc.z * v[i].z * rstd + sh.z, sc.w * v[i].w * rstd + sh.w);
    }
}

// ==================== fp16 mma.sync GEMM, 3-stage cp.async, 2 CTAs/SM ====================
// C[M][N] = A[M][K] @ B[N][K]^T, fp32 accumulate. CTA tile 128x128, K-chunk 64.
// EPI: 1 +bias+res -> fp32; 2 +bias GELU -> fp16; 3 plain -> fp16
#define STAGE_BYTES 32768
#define GEMM_SMEM   (3*STAGE_BYTES)

template<int EPI>
__global__ __launch_bounds__(256, 2)
void gemm_kernel(
    const __half* __restrict__ A, const __half* __restrict__ B,
    const float* __restrict__ bias, const float* __restrict__ res,
    float* __restrict__ C, __half* __restrict__ Ch,
    int M, int N, int K)
{
    extern __shared__ char smraw[];
    const uint32_t sbase = smem_u32(smraw);
    const int tid = threadIdx.x;
    const int bm = blockIdx.y, bn = blockIdx.x;

    const int w = tid >> 5, lane = tid & 31;
    const int wm = w & 1, wn = w >> 1;           // warp tile 64x32

    const int rowA = (lane & 7) + ((lane >> 3) & 1) * 8;
    const int chA  = (lane >> 4) & 1;
    const int gB   = lane >> 3;
    const int rB   = lane & 7;

    float acc[4][4][4];
    #pragma unroll
    for (int i = 0; i < 4; i++)
        #pragma unroll
        for (int j = 0; j < 4; j++)
            #pragma unroll
            for (int q = 0; q < 4; q++) acc[i][j][q] = 0.0f;

    const int nchunk = K >> 6;

    auto stage = [&](int s, int c) {
        const uint32_t sb = sbase + s * STAGE_BYTES;
        #pragma unroll
        for (int tl = 0; tl < 2; ++tl) {
            const __half* src = tl ? B : A;
            const int rbase = tl ? bn * 128 : bm * 128;
            #pragma unroll
            for (int j = 0; j < 4; ++j) {
                int idx = tid + j * 256;
                int r = idx >> 3, seg = idx & 7;
                cp_async16(sb + tl * 16384 + SWZ((uint32_t)(r * 128 + seg * 16)),
                           src + (size_t)(rbase + r) * K + c * 64 + seg * 8);
            }
        }
    };

    stage(0, 0); CP_COMMIT();
    if (nchunk > 1) { stage(1, 1); CP_COMMIT(); }

    for (int c = 0; c < nchunk; ++c) {
        const int s = c % 3;
        if (c == nchunk - 1) { CP_WAIT0(); } else { CP_WAIT1(); }
        __syncthreads();
        if (c + 2 < nchunk) { stage((c + 2) % 3, c + 2); CP_COMMIT(); }

        const uint32_t sA = sbase + s * STAGE_BYTES;
        const uint32_t sB = sA + 16384u;

        #pragma unroll
        for (int ks = 0; ks < 4; ++ks) {
            uint32_t ah[4][4], bh[2][4];
            #pragma unroll
            for (int mi = 0; mi < 4; ++mi) {
                uint32_t off = (uint32_t)((wm * 64 + mi * 16 + rowA) * 128 + (ks * 2 + chA) * 16);
                ldsm_x4(sA + SWZ(off), ah[mi]);
            }
            #pragma unroll
            for (int nb = 0; nb < 2; ++nb) {
                uint32_t off = (uint32_t)((wn * 32 + nb * 16 + (gB >> 1) * 8 + rB) * 128
                                          + ks * 32 + (gB & 1) * 16);
                ldsm_x4(sB + SWZ(off), bh[nb]);
            }
            #pragma unroll
            for (int mi = 0; mi < 4; ++mi)
                #pragma unroll
                for (int ni = 0; ni < 4; ++ni)
                    mma_f16(acc[mi][ni], ah[mi], bh[ni>>1][(ni&1)*2], bh[ni>>1][(ni&1)*2+1]);
        }
    }

    // epilogue
    const int g = lane >> 2, tid4 = lane & 3;
    #pragma unroll
    for (int mi = 0; mi < 4; ++mi) {
        #pragma unroll
        for (int half_ = 0; half_ < 2; ++half_) {
            const size_t row = (size_t)(bm * 128 + wm * 64 + mi * 16 + g + half_ * 8);
            #pragma unroll
            for (int ni = 0; ni < 4; ++ni) {
                const int col = bn * 128 + wn * 32 + ni * 8 + tid4 * 2;
                float v0 = acc[mi][ni][half_ * 2 + 0];
                float v1 = acc[mi][ni][half_ * 2 + 1];
                if (EPI == 1) {
                    float2 rv = *(const float2*)(res + row * N + col);
                    float2 bv = *(const float2*)(bias + col);
                    *(float2*)(C + row * N + col) =
                        make_float2(v0 + bv.x + rv.x, v1 + bv.y + rv.y);
                } else if (EPI == 2) {
                    float2 bv = *(const float2*)(bias + col);
                    *(uint32_t*)(Ch + row * N + col) =
                        h2(gelu_t(v0 + bv.x), gelu_t(v1 + bv.y));
                } else {
                    *(uint32_t*)(Ch + row * N + col) = h2(v0, v1);
                }
            }
        }
    }
}

// ==================== fp16 HMMA causal flash attention, 3-stage KV ====================
// BR=128, BC=64, 8 warps. log2-domain softmax, ex2.f16x2, rowsum via ones-MMA.
#define ATTN_SMEM 65536

__global__ __launch_bounds__(256, 2) void attn_kernel(
    const __half* __restrict__ QKV, __half* __restrict__ O)
{
    extern __shared__ char smraw[];
    const uint32_t sbase = smem_u32(smraw);
    const uint32_t sQ = sbase;

    const int qb = gridDim.x - 1 - blockIdx.x;    // heavy tiles first
    const int h = blockIdx.y, b = blockIdx.z;
    const int tid = threadIdx.x;
    const int w = tid >> 5, lane = tid & 31;
    const int wq0 = w * 16;
    const int g = lane >> 2, c2 = (lane & 3) * 2;
    const size_t rows0 = (size_t)b * SEQ;
    const int hoff = h * HD;

    const int rowA = (lane & 7) + ((lane >> 3) & 1) * 8;
    const int chA  = (lane >> 4) & 1;
    const int gB   = lane >> 3;
    const int rB   = lane & 7;
    const int rowV = lane & 15;
    const int colV = (lane >> 4) * 8;

    // stage Q (128 rows x 64 fp16)
    for (int i = tid; i < 1024; i += 256) {
        int r = i >> 3, seg = i & 7;
        *(uint4*)(smraw + SWZ((uint32_t)(r * 128 + seg * 16))) =
            *(const uint4*)(QKV + (rows0 + qb * 128 + r) * QKV_LD + hoff + seg * 8);
    }

    auto stageKV = [&](int s, int jb) {
        uint32_t sb = sbase + 16384u + (uint32_t)s * 16384u;
        for (int i = tid; i < 512; i += 256) {
            int r = i >> 3, seg = i & 7;
            const size_t go = (rows0 + jb * 64 + r) * QKV_LD + hoff + seg * 8;
            uint32_t dst = SWZ((uint32_t)(r * 128 + seg * 16));
            cp_async16(sb + dst,         QKV + go + EMB);       // K
            cp_async16(sb + 8192u + dst, QKV + go + 2 * EMB);   // V
        }
    };

    float oacc[8][4];
    #pragma unroll
    for (int i = 0; i < 8; i++)
        #pragma unroll
        for (int q = 0; q < 4; q++) oacc[i][q] = 0.0f;
    float m0 = -1e30f, m1 = -1e30f, l0 = 0.0f, l1 = 0.0f;

    const int row0 = qb * 128 + wq0 + g;
    const int row1 = row0 + 8;
    const int njb = 2 * qb + 2;
    const float SCL = 0.125f * 1.44269504f;   // 1/sqrt(64) * log2(e)

    stageKV(0, 0); CP_COMMIT();
    if (njb > 1) { stageKV(1, 1); CP_COMMIT(); }

    for (int jb = 0; jb < njb; ++jb) {
        if (jb == njb - 1)      { CP_WAIT0(); }
        else if (jb == njb - 2) { CP_WAIT1(); }
        else                    { CP_WAIT2(); }
        __syncthreads();
        if (jb + 2 < njb) { stageKV((jb + 2) % 3, jb + 2); CP_COMMIT(); }

        const uint32_t sK = sbase + 16384u + (uint32_t)(jb % 3) * 16384u;
        const uint32_t sV = sK + 8192u;

        // S = Q K^T
        float sacc[8][4];
        #pragma unroll
        for (int i = 0; i < 8; i++)
            #pragma unroll
            for (int q = 0; q < 4; q++) sacc[i][q] = 0.0f;

        #pragma unroll
        for (int ks = 0; ks < 4; ++ks) {
            uint32_t aq[4];
            ldsm_x4(sQ + SWZ((uint32_t)((wq0 + rowA) * 128 + (ks * 2 + chA) * 16)), aq);
            #pragma unroll
            for (int nb = 0; nb < 4; ++nb) {
                uint32_t bk[4];
                ldsm_x4(sK + SWZ((uint32_t)((nb * 16 + (gB >> 1) * 8 + rB) * 128
                                            + ks * 32 + (gB & 1) * 16)), bk);
                mma_f16(sacc[nb*2+0], aq, bk[0], bk[1]);
                mma_f16(sacc[nb*2+1], aq, bk[2], bk[3]);
            }
        }

        // scale + causal mask, into log2 domain
        const int col0 = jb * 64;
        #pragma unroll
        for (int ni = 0; ni < 8; ++ni) {
            int cg = col0 + ni * 8 + c2;
            sacc[ni][0] = (cg     > row0) ? -1e30f : sacc[ni][0] * SCL;
            sacc[ni][1] = (cg + 1 > row0) ? -1e30f : sacc[ni][1] * SCL;
            sacc[ni][2] = (cg     > row1) ? -1e30f : sacc[ni][2] * SCL;
            sacc[ni][3] = (cg + 1 > row1) ? -1e30f : sacc[ni][3] * SCL;
        }

        // row max (log2 domain; quad reduce)
        float rmax0 = -1e30f, rmax1 = -1e30f;
        #pragma unroll
        for (int ni = 0; ni < 8; ++ni) {
            rmax0 = fmaxf(rmax0, fmaxf(sacc[ni][0], sacc[ni][1]));
            rmax1 = fmaxf(rmax1, fmaxf(sacc[ni][2], sacc[ni][3]));
        }
        #pragma unroll
        for (int o = 1; o <= 2; o <<= 1) {
            rmax0 = fmaxf(rmax0, __shfl_xor_sync(0xffffffffu, rmax0, o));
            rmax1 = fmaxf(rmax1, __shfl_xor_sync(0xffffffffu, rmax1, o));
        }
        float mn0 = fmaxf(m0, rmax0), mn1 = fmaxf(m1, rmax1);
        float alpha0 = ex2f(m0 - mn0), alpha1 = ex2f(m1 - mn1);
        m0 = mn0; m1 = mn1;
        #pragma unroll
        for (int ni = 0; ni < 8; ++ni) {
            oacc[ni][0] *= alpha0; oacc[ni][1] *= alpha0;
            oacc[ni][2] *= alpha1; oacc[ni][3] *= alpha1;
        }

        // P = 2^(s - mn) directly as packed fp16
        uint32_t pw[8][2];
        #pragma unroll
        for (int ni = 0; ni < 8; ++ni) {
            pw[ni][0] = ex2_f16x2(h2(sacc[ni][0] - mn0, sacc[ni][1] - mn0));
            pw[ni][1] = ex2_f16x2(h2(sacc[ni][2] - mn1, sacc[ni][3] - mn1));
        }

        // O += P V ; row sums via ones-MMA
        float rsum[4] = {0.0f, 0.0f, 0.0f, 0.0f};
        #pragma unroll
        for (int kb = 0; kb < 4; ++kb) {
            uint32_t pa[4] = { pw[2*kb][0], pw[2*kb][1], pw[2*kb+1][0], pw[2*kb+1][1] };
            mma_f16(rsum, pa, ONES_H2, ONES_H2);
            #pragma unroll
            for (int nv = 0; nv < 4; ++nv) {
                uint32_t vv[4];
                ldsm_x4t(sV + SWZ((uint32_t)((kb * 16 + rowV) * 128 + (nv * 16 + colV) * 2)), vv);
                mma_f16(oacc[nv*2+0], pa, vv[0], vv[1]);
                mma_f16(oacc[nv*2+1], pa, vv[2], vv[3]);
            }
        }
        l0 = l0 * alpha0 + rsum[0];
        l1 = l1 * alpha1 + rsum[2];
    }

    // write ctx fp16
    float il0 = 1.0f / l0, il1 = 1.0f / l1;
    const size_t gr0 = (rows0 + qb * 128 + wq0 + g) * EMB + hoff;
    const size_t gr1 = gr0 + 8 * EMB;
    #pragma unroll
    for (int ni = 0; ni < 8; ++ni) {
        int col = ni * 8 + c2;
        *(uint32_t*)(O + gr0 + col) = h2(oacc[ni][0] * il0, oacc[ni][1] * il0);
        *(uint32_t*)(O + gr1 + col) = h2(oacc[ni][2] * il1, oacc[ni][3] * il1);
    }
}

// ==================== host launch ====================
extern "C" void kernel_launch(void* const* d_in, const int* in_sizes, int n_in,
                              void* d_out, int out_size)
{
    const float* x    = (const float*)d_in[0];
    const float* Wq   = (const float*)d_in[1];
    const float* Wk   = (const float*)d_in[2];
    const float* Wv   = (const float*)d_in[3];
    const float* Wo   = (const float*)d_in[4];
    const float* bo   = (const float*)d_in[5];
    const float* W1   = (const float*)d_in[6];
    const float* b1   = (const float*)d_in[7];
    const float* W2   = (const float*)d_in[8];
    const float* b2   = (const float*)d_in[9];
    const float* ln1s = (const float*)d_in[10];
    const float* ln1b = (const float*)d_in[11];
    const float* ln2s = (const float*)d_in[12];
    const float* ln2b = (const float*)d_in[13];
    float* out = (float*)d_out;

    __half *hh, *qkv, *ctx, *mid, *wqkv, *wo, *w1, *w2;
    float *x1;
    cudaGetSymbolAddress((void**)&hh,   g_h);
    cudaGetSymbolAddress((void**)&qkv,  g_qkv);
    cudaGetSymbolAddress((void**)&ctx,  g_ctx);
    cudaGetSymbolAddress((void**)&x1,   g_x1);
    cudaGetSymbolAddress((void**)&mid,  g_mid);
    cudaGetSymbolAddress((void**)&wqkv, g_wqkv);
    cudaGetSymbolAddress((void**)&wo,   g_wo);
    cudaGetSymbolAddress((void**)&w1,   g_w1);
    cudaGetSymbolAddress((void**)&w2,   g_w2);

    cudaFuncSetAttribute(gemm_kernel<1>, cudaFuncAttributeMaxDynamicSharedMemorySize, GEMM_SMEM);
    cudaFuncSetAttribute(gemm_kernel<2>, cudaFuncAttributeMaxDynamicSharedMemorySize, GEMM_SMEM);
    cudaFuncSetAttribute(gemm_kernel<3>, cudaFuncAttributeMaxDynamicSharedMemorySize, GEMM_SMEM);
    cudaFuncSetAttribute(attn_kernel, cudaFuncAttributeMaxDynamicSharedMemorySize, ATTN_SMEM);

    // weight transposes + LN1
    transpose4_kernel<<<dim3(EMB/32, EMB/32, 4), 256>>>(
        Wq, Wk, Wv, Wo, wqkv, wqkv + EMB*EMB, wqkv + 2*EMB*EMB, wo);
    ln_half_kernel<<<TOK/8, 256>>>(x, ln1s, ln1b, hh);
    transpose_half_kernel<<<dim3(FF/32,  EMB/32), 256>>>(W1, w1, EMB, FF);
    transpose_half_kernel<<<dim3(EMB/32, FF/32),  256>>>(W2, w2, FF, EMB);

    // fused QKV projection -> fp16
    gemm_kernel<3><<<dim3(QKV_LD/128, TOK/128), 256, GEMM_SMEM>>>(
        hh, wqkv, nullptr, nullptr, nullptr, qkv, TOK, QKV_LD, EMB);

    // attention -> ctx fp16
    attn_kernel<<<dim3(SEQ/128, HEADS, BATCH), 256, ATTN_SMEM>>>(qkv, ctx);

    // Wo + bias + residual -> x1 (fp32)
    gemm_kernel<1><<<dim3(EMB/128, TOK/128), 256, GEMM_SMEM>>>(
        ctx, wo, bo, x, x1, nullptr, TOK, EMB, EMB);

    // LN2 -> h fp16
    ln_half_kernel<<<TOK/8, 256>>>(x1, ln2s, ln2b, hh);

    // FFN up + GELU -> mid fp16
    gemm_kernel<2><<<dim3(FF/128, TOK/128), 256, GEMM_SMEM>>>(
        hh, w1, b1, nullptr, nullptr, mid, TOK, FF, EMB);

    // FFN down + bias + residual -> out fp32
    gemm_kernel<1><<<dim3(EMB/128, TOK/128), 256, GEMM_SMEM>>>(
        mid, w2, b2, x1, out, nullptr, TOK, EMB, FF);
}

// round 10
// speedup vs baseline: 7.2790x; 1.0022x over previous
#include <cuda_runtime.h>
#include <cuda_fp16.h>
#include <math.h>
#include <float.h>
#include <stdint.h>

#define BATCH 2
#define SEQ   2048
#define TOK   (BATCH*SEQ)        // 4096
#define EMB   1024
#define HEADS 16
#define HD    64
#define FF    4096
#define QKV_LD 3072

// ==================== helpers ====================
__device__ __forceinline__ uint32_t smem_u32(const void* p) {
    uint32_t a;
    asm("{ .reg .u64 t; cvta.to.shared.u64 t, %1; cvt.u32.u64 %0, t; }" : "=r"(a) : "l"(p));
    return a;
}
#define SWZ(x) ((x) ^ (((x) >> 3) & 0x70))

__device__ __forceinline__ void cp_async16(uint32_t saddr, const void* gptr) {
    asm volatile("cp.async.cg.shared.global [%0], [%1], 16;" :: "r"(saddr), "l"(gptr));
}
#define CP_COMMIT() asm volatile("cp.async.commit_group;" ::: "memory")
#define CP_WAIT2()  asm volatile("cp.async.wait_group 2;" ::: "memory")
#define CP_WAIT1()  asm volatile("cp.async.wait_group 1;" ::: "memory")
#define CP_WAIT0()  asm volatile("cp.async.wait_group 0;" ::: "memory")

__device__ __forceinline__ void ldsm_x4(uint32_t addr, uint32_t r[4]) {
    asm volatile("ldmatrix.sync.aligned.m8n8.x4.shared.b16 {%0,%1,%2,%3}, [%4];"
                 : "=r"(r[0]), "=r"(r[1]), "=r"(r[2]), "=r"(r[3]) : "r"(addr));
}
__device__ __forceinline__ void ldsm_x4t(uint32_t addr, uint32_t r[4]) {
    asm volatile("ldmatrix.sync.aligned.m8n8.x4.trans.shared.b16 {%0,%1,%2,%3}, [%4];"
                 : "=r"(r[0]), "=r"(r[1]), "=r"(r[2]), "=r"(r[3]) : "r"(addr));
}
__device__ __forceinline__ void mma_f16(float c[4], const uint32_t a[4], const uint32_t b0, const uint32_t b1) {
    asm volatile("mma.sync.aligned.m16n8k16.row.col.f32.f16.f16.f32 "
                 "{%0,%1,%2,%3}, {%4,%5,%6,%7}, {%8,%9}, {%0,%1,%2,%3};"
                 : "+f"(c[0]), "+f"(c[1]), "+f"(c[2]), "+f"(c[3])
                 : "r"(a[0]), "r"(a[1]), "r"(a[2]), "r"(a[3]), "r"(b0), "r"(b1));
}
__device__ __forceinline__ uint32_t h2(float a, float b) {
    __half2 t = __floats2half2_rn(a, b);
    return *(uint32_t*)&t;
}
__device__ __forceinline__ uint32_t ex2_f16x2(uint32_t x) {
    uint32_t r;
    asm("ex2.approx.f16x2 %0, %1;" : "=r"(r) : "r"(x));
    return r;
}
__device__ __forceinline__ float ex2f(float x) {
    float r;
    asm("ex2.approx.f32 %0, %1;" : "=f"(r) : "f"(x));
    return r;
}
__device__ __forceinline__ float gelu_t(float v) {
    float t = tanhf(0.7978845608028654f * (v + 0.044715f * v * v * v));
    return 0.5f * v * (1.0f + t);
}
#define ONES_H2 0x3C003C00u   // (1.0h, 1.0h)

// ==================== scratch (device globals) ====================
__device__ __half g_h[TOK*EMB];
__device__ __half g_qkv[TOK*QKV_LD];
__device__ __half g_ctx[TOK*EMB];
__device__ float  g_x1[TOK*EMB];
__device__ __half g_mid[TOK*FF];
__device__ __half g_wqkv[QKV_LD*EMB];   // [N=3072][K=1024]
__device__ __half g_wo[EMB*EMB];
__device__ __half g_w1[EMB*FF];         // [N=FF][K=EMB]
__device__ __half g_w2[FF*EMB];         // [N=EMB][K=FF]

// ==================== batched square transpose: 4x W[1024][1024] -> T[N][K] fp16 ====================
__global__ __launch_bounds__(256) void transpose4_kernel(
    const float* __restrict__ Wq, const float* __restrict__ Wk,
    const float* __restrict__ Wv, const float* __restrict__ Wo,
    __half* __restrict__ Tq, __half* __restrict__ Tk,
    __half* __restrict__ Tv, __half* __restrict__ To)
{
    __shared__ float t[32][33];
    const float* W = (blockIdx.z == 0) ? Wq : (blockIdx.z == 1) ? Wk : (blockIdx.z == 2) ? Wv : Wo;
    __half*      T = (blockIdx.z == 0) ? Tq : (blockIdx.z == 1) ? Tk : (blockIdx.z == 2) ? Tv : To;
    int tx = threadIdx.x & 31, ty = threadIdx.x >> 5;
    int k0 = blockIdx.y * 32, n0 = blockIdx.x * 32;
    #pragma unroll
    for (int i = 0; i < 4; i++)
        t[ty + i*8][tx] = W[(size_t)(k0 + ty + i*8) * EMB + n0 + tx];
    __syncthreads();
    #pragma unroll
    for (int i = 0; i < 4; i++)
        T[(size_t)(n0 + ty + i*8) * EMB + k0 + tx] = __float2half_rn(t[tx][ty + i*8]);
}

// ==================== rect transpose: W[K][N] -> T[N][K] fp16 ====================
__global__ __launch_bounds__(256) void transpose_half_kernel(
    const float* __restrict__ W, __half* __restrict__ T, int K, int N)
{
    __shared__ float t[32][33];
    int tx = threadIdx.x & 31, ty = threadIdx.x >> 5;
    int k0 = blockIdx.y * 32, n0 = blockIdx.x * 32;
    #pragma unroll
    for (int i = 0; i < 4; i++)
        t[ty + i*8][tx] = W[(size_t)(k0 + ty + i*8) * N + n0 + tx];
    __syncthreads();
    #pragma unroll
    for (int i = 0; i < 4; i++)
        T[(size_t)(n0 + ty + i*8) * K + k0 + tx] = __float2half_rn(t[tx][ty + i*8]);
}

// ==================== LayerNorm -> fp16, warp-per-row ====================
__global__ __launch_bounds__(256) void ln_half_kernel(
    const float* __restrict__ X, const float* __restrict__ scale,
    const float* __restrict__ shift, __half* __restrict__ Y)
{
    const int lane = threadIdx.x & 31;
    const int row  = blockIdx.x * 8 + (threadIdx.x >> 5);
    const float* x = X + (size_t)row * EMB;

    float4 v[8];
    float s = 0.0f;
    #pragma unroll
    for (int i = 0; i < 8; i++) {
        v[i] = *(const float4*)(x + (i * 32 + lane) * 4);
        s += v[i].x + v[i].y + v[i].z + v[i].w;
    }
    #pragma unroll
    for (int o = 16; o > 0; o >>= 1) s += __shfl_xor_sync(0xffffffffu, s, o);
    float mean = s * (1.0f / EMB);

    float sq = 0.0f;
    #pragma unroll
    for (int i = 0; i < 8; i++) {
        v[i].x -= mean; v[i].y -= mean; v[i].z -= mean; v[i].w -= mean;
        sq += v[i].x*v[i].x + v[i].y*v[i].y + v[i].z*v[i].z + v[i].w*v[i].w;
    }
    #pragma unroll
    for (int o = 16; o > 0; o >>= 1) sq += __shfl_xor_sync(0xffffffffu, sq, o);
    float rstd = rsqrtf(sq * (1.0f / EMB) + 1e-5f);

    #pragma unroll
    for (int i = 0; i < 8; i++) {
        int c0 = (i * 32 + lane) * 4;
        float4 sc = *(const float4*)(scale + c0);
        float4 sh = *(const float4*)(shift + c0);
        size_t o = (size_t)row * EMB + c0;
        *(uint32_t*)(Y + o)     = h2(sc.x * v[i].x * rstd + sh.x, sc.y * v[i].y * rstd + sh.y);
        *(uint32_t*)(Y + o + 2) = h2(sc.z * v[i].z * rstd + sh.z, sc.w * v[i].w * rstd + sh.w);
    }
}

// ==================== fp16 mma.sync GEMM, 3-stage cp.async, 2 CTAs/SM ====================
// C[M][N] = A[M][K] @ B[N][K]^T, fp32 accumulate. CTA tile 128x128, K-chunk 64.
// EPI: 1 +bias+res -> fp32; 2 +bias GELU -> fp16; 3 plain -> fp16
#define STAGE_BYTES 32768
#define GEMM_SMEM   (3*STAGE_BYTES)

template<int EPI>
__global__ __launch_bounds__(256, 2)
void gemm_kernel(
    const __half* __restrict__ A, const __half* __restrict__ B,
    const float* __restrict__ bias, const float* __restrict__ res,
    float* __restrict__ C, __half* __restrict__ Ch,
    int M, int N, int K)
{
    extern __shared__ char smraw[];
    const uint32_t sbase = smem_u32(smraw);
    const int tid = threadIdx.x;
    const int bm = blockIdx.y, bn = blockIdx.x;

    const int w = tid >> 5, lane = tid & 31;
    const int wm = w & 1, wn = w >> 1;           // warp tile 64x32

    const int rowA = (lane & 7) + ((lane >> 3) & 1) * 8;
    const int chA  = (lane >> 4) & 1;
    const int gB   = lane >> 3;
    const int rB   = lane & 7;

    float acc[4][4][4];
    #pragma unroll
    for (int i = 0; i < 4; i++)
        #pragma unroll
        for (int j = 0; j < 4; j++)
            #pragma unroll
            for (int q = 0; q < 4; q++) acc[i][j][q] = 0.0f;

    const int nchunk = K >> 6;

    auto stage = [&](int s, int c) {
        const uint32_t sb = sbase + s * STAGE_BYTES;
        #pragma unroll
        for (int tl = 0; tl < 2; ++tl) {
            const __half* src = tl ? B : A;
            const int rbase = tl ? bn * 128 : bm * 128;
            #pragma unroll
            for (int j = 0; j < 4; ++j) {
                int idx = tid + j * 256;
                int r = idx >> 3, seg = idx & 7;
                cp_async16(sb + tl * 16384 + SWZ((uint32_t)(r * 128 + seg * 16)),
                           src + (size_t)(rbase + r) * K + c * 64 + seg * 8);
            }
        }
    };

    stage(0, 0); CP_COMMIT();
    if (nchunk > 1) { stage(1, 1); CP_COMMIT(); }

    for (int c = 0; c < nchunk; ++c) {
        const int s = c % 3;
        if (c == nchunk - 1) { CP_WAIT0(); } else { CP_WAIT1(); }
        __syncthreads();
        if (c + 2 < nchunk) { stage((c + 2) % 3, c + 2); CP_COMMIT(); }

        const uint32_t sA = sbase + s * STAGE_BYTES;
        const uint32_t sB = sA + 16384u;

        #pragma unroll
        for (int ks = 0; ks < 4; ++ks) {
            uint32_t ah[4][4], bh[2][4];
            #pragma unroll
            for (int mi = 0; mi < 4; ++mi) {
                uint32_t off = (uint32_t)((wm * 64 + mi * 16 + rowA) * 128 + (ks * 2 + chA) * 16);
                ldsm_x4(sA + SWZ(off), ah[mi]);
            }
            #pragma unroll
            for (int nb = 0; nb < 2; ++nb) {
                uint32_t off = (uint32_t)((wn * 32 + nb * 16 + (gB >> 1) * 8 + rB) * 128
                                          + ks * 32 + (gB & 1) * 16);
                ldsm_x4(sB + SWZ(off), bh[nb]);
            }
            #pragma unroll
            for (int mi = 0; mi < 4; ++mi)
                #pragma unroll
                for (int ni = 0; ni < 4; ++ni)
                    mma_f16(acc[mi][ni], ah[mi], bh[ni>>1][(ni&1)*2], bh[ni>>1][(ni&1)*2+1]);
        }
    }

    // epilogue
    const int g = lane >> 2, tid4 = lane & 3;
    #pragma unroll
    for (int mi = 0; mi < 4; ++mi) {
        #pragma unroll
        for (int half_ = 0; half_ < 2; ++half_) {
            const size_t row = (size_t)(bm * 128 + wm * 64 + mi * 16 + g + half_ * 8);
            #pragma unroll
            for (int ni = 0; ni < 4; ++ni) {
                const int col = bn * 128 + wn * 32 + ni * 8 + tid4 * 2;
                float v0 = acc[mi][ni][half_ * 2 + 0];
                float v1 = acc[mi][ni][half_ * 2 + 1];
                if (EPI == 1) {
                    float2 rv = *(const float2*)(res + row * N + col);
                    float2 bv = *(const float2*)(bias + col);
                    *(float2*)(C + row * N + col) =
                        make_float2(v0 + bv.x + rv.x, v1 + bv.y + rv.y);
                } else if (EPI == 2) {
                    float2 bv = *(const float2*)(bias + col);
                    *(uint32_t*)(Ch + row * N + col) =
                        h2(gelu_t(v0 + bv.x), gelu_t(v1 + bv.y));
                } else {
                    *(uint32_t*)(Ch + row * N + col) = h2(v0, v1);
                }
            }
        }
    }
}

// ==================== fp16 HMMA causal flash attention, 3-stage KV ====================
// BR=128, BC=64, 8 warps. log2 softmax, ex2.f16x2, rowsum via ones-MMA, Q frags hoisted.
#define ATTN_SMEM 65536

__global__ __launch_bounds__(256, 2) void attn_kernel(
    const __half* __restrict__ QKV, __half* __restrict__ O)
{
    extern __shared__ char smraw[];
    const uint32_t sbase = smem_u32(smraw);
    const uint32_t sQ = sbase;

    const int qb = gridDim.x - 1 - blockIdx.x;    // heavy tiles first
    const int h = blockIdx.y, b = blockIdx.z;
    const int tid = threadIdx.x;
    const int w = tid >> 5, lane = tid & 31;
    const int wq0 = w * 16;
    const int g = lane >> 2, c2 = (lane & 3) * 2;
    const size_t rows0 = (size_t)b * SEQ;
    const int hoff = h * HD;

    const int rowA = (lane & 7) + ((lane >> 3) & 1) * 8;
    const int chA  = (lane >> 4) & 1;
    const int gB   = lane >> 3;
    const int rB   = lane & 7;
    const int rowV = lane & 15;
    const int colV = (lane >> 4) * 8;

    // stage Q (128 rows x 64 fp16)
    for (int i = tid; i < 1024; i += 256) {
        int r = i >> 3, seg = i & 7;
        *(uint4*)(smraw + SWZ((uint32_t)(r * 128 + seg * 16))) =
            *(const uint4*)(QKV + (rows0 + qb * 128 + r) * QKV_LD + hoff + seg * 8);
    }

    auto stageKV = [&](int s, int jb) {
        uint32_t sb = sbase + 16384u + (uint32_t)s * 16384u;
        for (int i = tid; i < 512; i += 256) {
            int r = i >> 3, seg = i & 7;
            const size_t go = (rows0 + jb * 64 + r) * QKV_LD + hoff + seg * 8;
            uint32_t dst = SWZ((uint32_t)(r * 128 + seg * 16));
            cp_async16(sb + dst,         QKV + go + EMB);       // K
            cp_async16(sb + 8192u + dst, QKV + go + 2 * EMB);   // V
        }
    };

    float oacc[8][4];
    #pragma unroll
    for (int i = 0; i < 8; i++)
        #pragma unroll
        for (int q = 0; q < 4; q++) oacc[i][q] = 0.0f;
    float m0 = -1e30f, m1 = -1e30f, l0 = 0.0f, l1 = 0.0f;

    uint32_t qfrag[4][4];   // Q fragments, loop-invariant

    const int row0 = qb * 128 + wq0 + g;
    const int row1 = row0 + 8;
    const int njb = 2 * qb + 2;
    const float SCL = 0.125f * 1.44269504f;   // 1/sqrt(64) * log2(e)

    stageKV(0, 0); CP_COMMIT();
    if (njb > 1) { stageKV(1, 1); CP_COMMIT(); }

    for (int jb = 0; jb < njb; ++jb) {
        if (jb == njb - 1)      { CP_WAIT0(); }
        else if (jb == njb - 2) { CP_WAIT1(); }
        else                    { CP_WAIT2(); }
        __syncthreads();
        if (jb + 2 < njb) { stageKV((jb + 2) % 3, jb + 2); CP_COMMIT(); }

        if (jb == 0) {
            #pragma unroll
            for (int ks = 0; ks < 4; ++ks)
                ldsm_x4(sQ + SWZ((uint32_t)((wq0 + rowA) * 128 + (ks * 2 + chA) * 16)), qfrag[ks]);
        }

        const uint32_t sK = sbase + 16384u + (uint32_t)(jb % 3) * 16384u;
        const uint32_t sV = sK + 8192u;

        // S = Q K^T
        float sacc[8][4];
        #pragma unroll
        for (int i = 0; i < 8; i++)
            #pragma unroll
            for (int q = 0; q < 4; q++) sacc[i][q] = 0.0f;

        #pragma unroll
        for (int ks = 0; ks < 4; ++ks) {
            #pragma unroll
            for (int nb = 0; nb < 4; ++nb) {
                uint32_t bk[4];
                ldsm_x4(sK + SWZ((uint32_t)((nb * 16 + (gB >> 1) * 8 + rB) * 128
                                            + ks * 32 + (gB & 1) * 16)), bk);
                mma_f16(sacc[nb*2+0], qfrag[ks], bk[0], bk[1]);
                mma_f16(sacc[nb*2+1], qfrag[ks], bk[2], bk[3]);
            }
        }

        // scale + causal mask, into log2 domain
        const int col0 = jb * 64;
        #pragma unroll
        for (int ni = 0; ni < 8; ++ni) {
            int cg = col0 + ni * 8 + c2;
            sacc[ni][0] = (cg     > row0) ? -1e30f : sacc[ni][0] * SCL;
            sacc[ni][1] = (cg + 1 > row0) ? -1e30f : sacc[ni][1] * SCL;
            sacc[ni][2] = (cg     > row1) ? -1e30f : sacc[ni][2] * SCL;
            sacc[ni][3] = (cg + 1 > row1) ? -1e30f : sacc[ni][3] * SCL;
        }

        // row max (log2 domain; quad reduce)
        float rmax0 = -1e30f, rmax1 = -1e30f;
        #pragma unroll
        for (int ni = 0; ni < 8; ++ni) {
            rmax0 = fmaxf(rmax0, fmaxf(sacc[ni][0], sacc[ni][1]));
            rmax1 = fmaxf(rmax1, fmaxf(sacc[ni][2], sacc[ni][3]));
        }
        #pragma unroll
        for (int o = 1; o <= 2; o <<= 1) {
            rmax0 = fmaxf(rmax0, __shfl_xor_sync(0xffffffffu, rmax0, o));
            rmax1 = fmaxf(rmax1, __shfl_xor_sync(0xffffffffu, rmax1, o));
        }
        float mn0 = fmaxf(m0, rmax0), mn1 = fmaxf(m1, rmax1);
        float alpha0 = ex2f(m0 - mn0), alpha1 = ex2f(m1 - mn1);
        m0 = mn0; m1 = mn1;
        #pragma unroll
        for (int ni = 0; ni < 8; ++ni) {
            oacc[ni][0] *= alpha0; oacc[ni][1] *= alpha0;
            oacc[ni][2] *= alpha1; oacc[ni][3] *= alpha1;
        }

        // P = 2^(s - mn) directly as packed fp16
        uint32_t pw[8][2];
        #pragma unroll
        for (int ni = 0; ni < 8; ++ni) {
            pw[ni][0] = ex2_f16x2(h2(sacc[ni][0] - mn0, sacc[ni][1] - mn0));
            pw[ni][1] = ex2_f16x2(h2(sacc[ni][2] - mn1, sacc[ni][3] - mn1));
        }

        // O += P V ; row sums via ones-MMA
        float rsum[4] = {0.0f, 0.0f, 0.0f, 0.0f};
        #pragma unroll
        for (int kb = 0; kb < 4; ++kb) {
            uint32_t pa[4] = { pw[2*kb][0], pw[2*kb][1], pw[2*kb+1][0], pw[2*kb+1][1] };
            mma_f16(rsum, pa, ONES_H2, ONES_H2);
            #pragma unroll
            for (int nv = 0; nv < 4; ++nv) {
                uint32_t vv[4];
                ldsm_x4t(sV + SWZ((uint32_t)((kb * 16 + rowV) * 128 + (nv * 16 + colV) * 2)), vv);
                mma_f16(oacc[nv*2+0], pa, vv[0], vv[1]);
                mma_f16(oacc[nv*2+1], pa, vv[2], vv[3]);
            }
        }
        l0 = l0 * alpha0 + rsum[0];
        l1 = l1 * alpha1 + rsum[2];
    }

    // write ctx fp16
    float il0 = 1.0f / l0, il1 = 1.0f / l1;
    const size_t gr0 = (rows0 + qb * 128 + wq0 + g) * EMB + hoff;
    const size_t gr1 = gr0 + 8 * EMB;
    #pragma unroll
    for (int ni = 0; ni < 8; ++ni) {
        int col = ni * 8 + c2;
        *(uint32_t*)(O + gr0 + col) = h2(oacc[ni][0] * il0, oacc[ni][1] * il0);
        *(uint32_t*)(O + gr1 + col) = h2(oacc[ni][2] * il1, oacc[ni][3] * il1);
    }
}

// ==================== host launch ====================
extern "C" void kernel_launch(void* const* d_in, const int* in_sizes, int n_in,
                              void* d_out, int out_size)
{
    const float* x    = (const float*)d_in[0];
    const float* Wq   = (const float*)d_in[1];
    const float* Wk   = (const float*)d_in[2];
    const float* Wv   = (const float*)d_in[3];
    const float* Wo   = (const float*)d_in[4];
    const float* bo   = (const float*)d_in[5];
    const float* W1   = (const float*)d_in[6];
    const float* b1   = (const float*)d_in[7];
    const float* W2   = (const float*)d_in[8];
    const float* b2   = (const float*)d_in[9];
    const float* ln1s = (const float*)d_in[10];
    const float* ln1b = (const float*)d_in[11];
    const float* ln2s = (const float*)d_in[12];
    const float* ln2b = (const float*)d_in[13];
    float* out = (float*)d_out;

    __half *hh, *qkv, *ctx, *mid, *wqkv, *wo, *w1, *w2;
    float *x1;
    cudaGetSymbolAddress((void**)&hh,   g_h);
    cudaGetSymbolAddress((void**)&qkv,  g_qkv);
    cudaGetSymbolAddress((void**)&ctx,  g_ctx);
    cudaGetSymbolAddress((void**)&x1,   g_x1);
    cudaGetSymbolAddress((void**)&mid,  g_mid);
    cudaGetSymbolAddress((void**)&wqkv, g_wqkv);
    cudaGetSymbolAddress((void**)&wo,   g_wo);
    cudaGetSymbolAddress((void**)&w1,   g_w1);
    cudaGetSymbolAddress((void**)&w2,   g_w2);

    cudaFuncSetAttribute(gemm_kernel<1>, cudaFuncAttributeMaxDynamicSharedMemorySize, GEMM_SMEM);
    cudaFuncSetAttribute(gemm_kernel<2>, cudaFuncAttributeMaxDynamicSharedMemorySize, GEMM_SMEM);
    cudaFuncSetAttribute(gemm_kernel<3>, cudaFuncAttributeMaxDynamicSharedMemorySize, GEMM_SMEM);
    cudaFuncSetAttribute(attn_kernel, cudaFuncAttributeMaxDynamicSharedMemorySize, ATTN_SMEM);

    // side stream + events, created once on the first (non-capture) call
    static cudaStream_t s_side = []{
        cudaStream_t s; cudaStreamCreateWithFlags(&s, cudaStreamNonBlocking); return s; }();
    static cudaEvent_t ev_fork = []{
        cudaEvent_t e; cudaEventCreateWithFlags(&e, cudaEventDisableTiming); return e; }();
    static cudaEvent_t ev_join = []{
        cudaEvent_t e; cudaEventCreateWithFlags(&e, cudaEventDisableTiming); return e; }();

    // fork: W1/W2 transposes overlap the QKV GEMM + attention (orthogonal pipes)
    cudaEventRecord(ev_fork, 0);
    cudaStreamWaitEvent(s_side, ev_fork, 0);
    transpose_half_kernel<<<dim3(FF/32,  EMB/32), 256, 0, s_side>>>(W1, w1, EMB, FF);
    transpose_half_kernel<<<dim3(EMB/32, FF/32),  256, 0, s_side>>>(W2, w2, FF, EMB);
    cudaEventRecord(ev_join, s_side);

    // main stream
    transpose4_kernel<<<dim3(EMB/32, EMB/32, 4), 256>>>(
        Wq, Wk, Wv, Wo, wqkv, wqkv + EMB*EMB, wqkv + 2*EMB*EMB, wo);
    ln_half_kernel<<<TOK/8, 256>>>(x, ln1s, ln1b, hh);

    // fused QKV projection -> fp16
    gemm_kernel<3><<<dim3(QKV_LD/128, TOK/128), 256, GEMM_SMEM>>>(
        hh, wqkv, nullptr, nullptr, nullptr, qkv, TOK, QKV_LD, EMB);

    // attention -> ctx fp16
    attn_kernel<<<dim3(SEQ/128, HEADS, BATCH), 256, ATTN_SMEM>>>(qkv, ctx);

    // Wo + bias + residual -> x1 (fp32)
    gemm_kernel<1><<<dim3(EMB/128, TOK/128), 256, GEMM_SMEM>>>(
        ctx, wo, bo, x, x1, nullptr, TOK, EMB, EMB);

    // LN2 -> h fp16
    ln_half_kernel<<<TOK/8, 256>>>(x1, ln2s, ln2b, hh);

    // join: FFN-up needs w1 (and w2 follows)
    cudaStreamWaitEvent(0, ev_join, 0);

    // FFN up + GELU -> mid fp16
    gemm_kernel<2><<<dim3(FF/128, TOK/128), 256, GEMM_SMEM>>>(
        hh, w1, b1, nullptr, nullptr, mid, TOK, FF, EMB);

    // FFN down + bias + residual -> out fp32
    gemm_kernel<1><<<dim3(EMB/128, TOK/128), 256, GEMM_SMEM>>>(
        mid, w2, b2, x1, out, nullptr, TOK, EMB, FF);
}

// round 11
// speedup vs baseline: 7.3798x; 1.0139x over previous
#include <cuda_runtime.h>
#include <cuda_fp16.h>
#include <math.h>
#include <float.h>
#include <stdint.h>

#define BATCH 2
#define SEQ   2048
#define TOK   (BATCH*SEQ)        // 4096
#define EMB   1024
#define HEADS 16
#define HD    64
#define FF    4096
#define QKV_LD 3072

// ==================== helpers ====================
__device__ __forceinline__ uint32_t smem_u32(const void* p) {
    uint32_t a;
    asm("{ .reg .u64 t; cvta.to.shared.u64 t, %1; cvt.u32.u64 %0, t; }" : "=r"(a) : "l"(p));
    return a;
}
#define SWZ(x) ((x) ^ (((x) >> 3) & 0x70))

__device__ __forceinline__ void cp_async16(uint32_t saddr, const void* gptr) {
    asm volatile("cp.async.cg.shared.global [%0], [%1], 16;" :: "r"(saddr), "l"(gptr));
}
#define CP_COMMIT() asm volatile("cp.async.commit_group;" ::: "memory")
#define CP_WAIT2()  asm volatile("cp.async.wait_group 2;" ::: "memory")
#define CP_WAIT1()  asm volatile("cp.async.wait_group 1;" ::: "memory")
#define CP_WAIT0()  asm volatile("cp.async.wait_group 0;" ::: "memory")

__device__ __forceinline__ void ldsm_x4(uint32_t addr, uint32_t r[4]) {
    asm volatile("ldmatrix.sync.aligned.m8n8.x4.shared.b16 {%0,%1,%2,%3}, [%4];"
                 : "=r"(r[0]), "=r"(r[1]), "=r"(r[2]), "=r"(r[3]) : "r"(addr));
}
__device__ __forceinline__ void ldsm_x4t(uint32_t addr, uint32_t r[4]) {
    asm volatile("ldmatrix.sync.aligned.m8n8.x4.trans.shared.b16 {%0,%1,%2,%3}, [%4];"
                 : "=r"(r[0]), "=r"(r[1]), "=r"(r[2]), "=r"(r[3]) : "r"(addr));
}
__device__ __forceinline__ void mma_f16(float c[4], const uint32_t a[4], const uint32_t b0, const uint32_t b1) {
    asm volatile("mma.sync.aligned.m16n8k16.row.col.f32.f16.f16.f32 "
                 "{%0,%1,%2,%3}, {%4,%5,%6,%7}, {%8,%9}, {%0,%1,%2,%3};"
                 : "+f"(c[0]), "+f"(c[1]), "+f"(c[2]), "+f"(c[3])
                 : "r"(a[0]), "r"(a[1]), "r"(a[2]), "r"(a[3]), "r"(b0), "r"(b1));
}
__device__ __forceinline__ uint32_t h2(float a, float b) {
    __half2 t = __floats2half2_rn(a, b);
    return *(uint32_t*)&t;
}
__device__ __forceinline__ uint32_t ex2_f16x2(uint32_t x) {
    uint32_t r;
    asm("ex2.approx.f16x2 %0, %1;" : "=r"(r) : "r"(x));
    return r;
}
__device__ __forceinline__ float ex2f(float x) {
    float r;
    asm("ex2.approx.f32 %0, %1;" : "=f"(r) : "f"(x));
    return r;
}
__device__ __forceinline__ float gelu_t(float v) {
    float t = tanhf(0.7978845608028654f * (v + 0.044715f * v * v * v));
    return 0.5f * v * (1.0f + t);
}
#define ONES_H2 0x3C003C00u   // (1.0h, 1.0h)

// ==================== scratch (device globals) ====================
__device__ __half g_h[TOK*EMB];
__device__ __half g_qkv[TOK*QKV_LD];
__device__ __half g_ctx[TOK*EMB];
__device__ float  g_x1[TOK*EMB];
__device__ __half g_mid[TOK*FF];
__device__ __half g_wqkv[QKV_LD*EMB];   // [N=3072][K=1024]
__device__ __half g_wo[EMB*EMB];
__device__ __half g_w1[EMB*FF];         // [N=FF][K=EMB]
__device__ __half g_w2[FF*EMB];         // [N=EMB][K=FF]

// ==================== batched square transpose: 4x W[1024][1024] -> T[N][K] fp16 ====================
__global__ __launch_bounds__(256) void transpose4_kernel(
    const float* __restrict__ Wq, const float* __restrict__ Wk,
    const float* __restrict__ Wv, const float* __restrict__ Wo,
    __half* __restrict__ Tq, __half* __restrict__ Tk,
    __half* __restrict__ Tv, __half* __restrict__ To)
{
    __shared__ float t[32][33];
    const float* W = (blockIdx.z == 0) ? Wq : (blockIdx.z == 1) ? Wk : (blockIdx.z == 2) ? Wv : Wo;
    __half*      T = (blockIdx.z == 0) ? Tq : (blockIdx.z == 1) ? Tk : (blockIdx.z == 2) ? Tv : To;
    int tx = threadIdx.x & 31, ty = threadIdx.x >> 5;
    int k0 = blockIdx.y * 32, n0 = blockIdx.x * 32;
    #pragma unroll
    for (int i = 0; i < 4; i++)
        t[ty + i*8][tx] = W[(size_t)(k0 + ty + i*8) * EMB + n0 + tx];
    __syncthreads();
    #pragma unroll
    for (int i = 0; i < 4; i++)
        T[(size_t)(n0 + ty + i*8) * EMB + k0 + tx] = __float2half_rn(t[tx][ty + i*8]);
}

// ==================== rect transpose: W[K][N] -> T[N][K] fp16 ====================
__global__ __launch_bounds__(256) void transpose_half_kernel(
    const float* __restrict__ W, __half* __restrict__ T, int K, int N)
{
    __shared__ float t[32][33];
    int tx = threadIdx.x & 31, ty = threadIdx.x >> 5;
    int k0 = blockIdx.y * 32, n0 = blockIdx.x * 32;
    #pragma unroll
    for (int i = 0; i < 4; i++)
        t[ty + i*8][tx] = W[(size_t)(k0 + ty + i*8) * N + n0 + tx];
    __syncthreads();
    #pragma unroll
    for (int i = 0; i < 4; i++)
        T[(size_t)(n0 + ty + i*8) * K + k0 + tx] = __float2half_rn(t[tx][ty + i*8]);
}

// ==================== LayerNorm -> fp16, warp-per-row, 4 rows / 128-thread CTA ====================
__global__ __launch_bounds__(128) void ln_half_kernel(
    const float* __restrict__ X, const float* __restrict__ scale,
    const float* __restrict__ shift, __half* __restrict__ Y)
{
    const int lane = threadIdx.x & 31;
    const int row  = blockIdx.x * 4 + (threadIdx.x >> 5);
    const float* x = X + (size_t)row * EMB;

    float4 v[8];
    float s = 0.0f;
    #pragma unroll
    for (int i = 0; i < 8; i++) {
        v[i] = *(const float4*)(x + (i * 32 + lane) * 4);
        s += v[i].x + v[i].y + v[i].z + v[i].w;
    }
    #pragma unroll
    for (int o = 16; o > 0; o >>= 1) s += __shfl_xor_sync(0xffffffffu, s, o);
    float mean = s * (1.0f / EMB);

    float sq = 0.0f;
    #pragma unroll
    for (int i = 0; i < 8; i++) {
        v[i].x -= mean; v[i].y -= mean; v[i].z -= mean; v[i].w -= mean;
        sq += v[i].x*v[i].x + v[i].y*v[i].y + v[i].z*v[i].z + v[i].w*v[i].w;
    }
    #pragma unroll
    for (int o = 16; o > 0; o >>= 1) sq += __shfl_xor_sync(0xffffffffu, sq, o);
    float rstd = rsqrtf(sq * (1.0f / EMB) + 1e-5f);

    #pragma unroll
    for (int i = 0; i < 8; i++) {
        int c0 = (i * 32 + lane) * 4;
        float4 sc = *(const float4*)(scale + c0);
        float4 sh = *(const float4*)(shift + c0);
        size_t o = (size_t)row * EMB + c0;
        *(uint32_t*)(Y + o)     = h2(sc.x * v[i].x * rstd + sh.x, sc.y * v[i].y * rstd + sh.y);
        *(uint32_t*)(Y + o + 2) = h2(sc.z * v[i].z * rstd + sh.z, sc.w * v[i].w * rstd + sh.w);
    }
}

// ==================== fp16 mma.sync GEMM, 3-stage cp.async, 2 CTAs/SM ====================
// C[M][N] = A[M][K] @ B[N][K]^T, fp32 accumulate. CTA tile 128x128, K-chunk 64.
// EPI: 1 +bias+res -> fp32; 2 +bias GELU -> fp16; 3 plain -> fp16
#define STAGE_BYTES 32768
#define GEMM_SMEM   (3*STAGE_BYTES)

template<int EPI>
__global__ __launch_bounds__(256, 2)
void gemm_kernel(
    const __half* __restrict__ A, const __half* __restrict__ B,
    const float* __restrict__ bias, const float* __restrict__ res,
    float* __restrict__ C, __half* __restrict__ Ch,
    int M, int N, int K)
{
    extern __shared__ char smraw[];
    const uint32_t sbase = smem_u32(smraw);
    const int tid = threadIdx.x;
    const int bm = blockIdx.y, bn = blockIdx.x;

    const int w = tid >> 5, lane = tid & 31;
    const int wm = w & 1, wn = w >> 1;           // warp tile 64x32

    const int rowA = (lane & 7) + ((lane >> 3) & 1) * 8;
    const int chA  = (lane >> 4) & 1;
    const int gB   = lane >> 3;
    const int rB   = lane & 7;

    float acc[4][4][4];
    #pragma unroll
    for (int i = 0; i < 4; i++)
        #pragma unroll
        for (int j = 0; j < 4; j++)
            #pragma unroll
            for (int q = 0; q < 4; q++) acc[i][j][q] = 0.0f;

    const int nchunk = K >> 6;

    auto stage = [&](int s, int c) {
        const uint32_t sb = sbase + s * STAGE_BYTES;
        #pragma unroll
        for (int tl = 0; tl < 2; ++tl) {
            const __half* src = tl ? B : A;
            const int rbase = tl ? bn * 128 : bm * 128;
            #pragma unroll
            for (int j = 0; j < 4; ++j) {
                int idx = tid + j * 256;
                int r = idx >> 3, seg = idx & 7;
                cp_async16(sb + tl * 16384 + SWZ((uint32_t)(r * 128 + seg * 16)),
                           src + (size_t)(rbase + r) * K + c * 64 + seg * 8);
            }
        }
    };

    stage(0, 0); CP_COMMIT();
    if (nchunk > 1) { stage(1, 1); CP_COMMIT(); }

    for (int c = 0; c < nchunk; ++c) {
        const int s = c % 3;
        if (c == nchunk - 1) { CP_WAIT0(); } else { CP_WAIT1(); }
        __syncthreads();
        if (c + 2 < nchunk) { stage((c + 2) % 3, c + 2); CP_COMMIT(); }

        const uint32_t sA = sbase + s * STAGE_BYTES;
        const uint32_t sB = sA + 16384u;

        #pragma unroll
        for (int ks = 0; ks < 4; ++ks) {
            uint32_t ah[4][4], bh[2][4];
            #pragma unroll
            for (int mi = 0; mi < 4; ++mi) {
                uint32_t off = (uint32_t)((wm * 64 + mi * 16 + rowA) * 128 + (ks * 2 + chA) * 16);
                ldsm_x4(sA + SWZ(off), ah[mi]);
            }
            #pragma unroll
            for (int nb = 0; nb < 2; ++nb) {
                uint32_t off = (uint32_t)((wn * 32 + nb * 16 + (gB >> 1) * 8 + rB) * 128
                                          + ks * 32 + (gB & 1) * 16);
                ldsm_x4(sB + SWZ(off), bh[nb]);
            }
            #pragma unroll
            for (int mi = 0; mi < 4; ++mi)
                #pragma unroll
                for (int ni = 0; ni < 4; ++ni)
                    mma_f16(acc[mi][ni], ah[mi], bh[ni>>1][(ni&1)*2], bh[ni>>1][(ni&1)*2+1]);
        }
    }

    // epilogue
    const int g = lane >> 2, tid4 = lane & 3;
    #pragma unroll
    for (int mi = 0; mi < 4; ++mi) {
        #pragma unroll
        for (int half_ = 0; half_ < 2; ++half_) {
            const size_t row = (size_t)(bm * 128 + wm * 64 + mi * 16 + g + half_ * 8);
            #pragma unroll
            for (int ni = 0; ni < 4; ++ni) {
                const int col = bn * 128 + wn * 32 + ni * 8 + tid4 * 2;
                float v0 = acc[mi][ni][half_ * 2 + 0];
                float v1 = acc[mi][ni][half_ * 2 + 1];
                if (EPI == 1) {
                    float2 rv = *(const float2*)(res + row * N + col);
                    float2 bv = *(const float2*)(bias + col);
                    *(float2*)(C + row * N + col) =
                        make_float2(v0 + bv.x + rv.x, v1 + bv.y + rv.y);
                } else if (EPI == 2) {
                    float2 bv = *(const float2*)(bias + col);
                    *(uint32_t*)(Ch + row * N + col) =
                        h2(gelu_t(v0 + bv.x), gelu_t(v1 + bv.y));
                } else {
                    *(uint32_t*)(Ch + row * N + col) = h2(v0, v1);
                }
            }
        }
    }
}

// ==================== fp16 HMMA causal flash attention, 3-stage KV ====================
// BR=128, BC=64, 8 warps. log2 softmax, ex2.f16x2, ones-MMA rowsum, Q frags hoisted,
// mask applied only on diagonal KV blocks (jb >= 2*qb).
#define ATTN_SMEM 65536

__global__ __launch_bounds__(256, 2) void attn_kernel(
    const __half* __restrict__ QKV, __half* __restrict__ O)
{
    extern __shared__ char smraw[];
    const uint32_t sbase = smem_u32(smraw);
    const uint32_t sQ = sbase;

    const int qb = gridDim.x - 1 - blockIdx.x;    // heavy tiles first
    const int h = blockIdx.y, b = blockIdx.z;
    const int tid = threadIdx.x;
    const int w = tid >> 5, lane = tid & 31;
    const int wq0 = w * 16;
    const int g = lane >> 2, c2 = (lane & 3) * 2;
    const size_t rows0 = (size_t)b * SEQ;
    const int hoff = h * HD;

    const int rowA = (lane & 7) + ((lane >> 3) & 1) * 8;
    const int chA  = (lane >> 4) & 1;
    const int gB   = lane >> 3;
    const int rB   = lane & 7;
    const int rowV = lane & 15;
    const int colV = (lane >> 4) * 8;

    // stage Q (128 rows x 64 fp16)
    for (int i = tid; i < 1024; i += 256) {
        int r = i >> 3, seg = i & 7;
        *(uint4*)(smraw + SWZ((uint32_t)(r * 128 + seg * 16))) =
            *(const uint4*)(QKV + (rows0 + qb * 128 + r) * QKV_LD + hoff + seg * 8);
    }

    auto stageKV = [&](int s, int jb) {
        uint32_t sb = sbase + 16384u + (uint32_t)s * 16384u;
        for (int i = tid; i < 512; i += 256) {
            int r = i >> 3, seg = i & 7;
            const size_t go = (rows0 + jb * 64 + r) * QKV_LD + hoff + seg * 8;
            uint32_t dst = SWZ((uint32_t)(r * 128 + seg * 16));
            cp_async16(sb + dst,         QKV + go + EMB);       // K
            cp_async16(sb + 8192u + dst, QKV + go + 2 * EMB);   // V
        }
    };

    float oacc[8][4];
    #pragma unroll
    for (int i = 0; i < 8; i++)
        #pragma unroll
        for (int q = 0; q < 4; q++) oacc[i][q] = 0.0f;
    float m0 = -1e30f, m1 = -1e30f, l0 = 0.0f, l1 = 0.0f;

    uint32_t qfrag[4][4];   // Q fragments, loop-invariant

    const int row0 = qb * 128 + wq0 + g;
    const int row1 = row0 + 8;
    const int njb = 2 * qb + 2;
    const float SCL = 0.125f * 1.44269504f;   // 1/sqrt(64) * log2(e)

    stageKV(0, 0); CP_COMMIT();
    if (njb > 1) { stageKV(1, 1); CP_COMMIT(); }

    for (int jb = 0; jb < njb; ++jb) {
        if (jb == njb - 1)      { CP_WAIT0(); }
        else if (jb == njb - 2) { CP_WAIT1(); }
        else                    { CP_WAIT2(); }
        __syncthreads();
        if (jb + 2 < njb) { stageKV((jb + 2) % 3, jb + 2); CP_COMMIT(); }

        if (jb == 0) {
            #pragma unroll
            for (int ks = 0; ks < 4; ++ks)
                ldsm_x4(sQ + SWZ((uint32_t)((wq0 + rowA) * 128 + (ks * 2 + chA) * 16)), qfrag[ks]);
        }

        const uint32_t sK = sbase + 16384u + (uint32_t)(jb % 3) * 16384u;
        const uint32_t sV = sK + 8192u;

        // S = Q K^T
        float sacc[8][4];
        #pragma unroll
        for (int i = 0; i < 8; i++)
            #pragma unroll
            for (int q = 0; q < 4; q++) sacc[i][q] = 0.0f;

        #pragma unroll
        for (int ks = 0; ks < 4; ++ks) {
            #pragma unroll
            for (int nb = 0; nb < 4; ++nb) {
                uint32_t bk[4];
                ldsm_x4(sK + SWZ((uint32_t)((nb * 16 + (gB >> 1) * 8 + rB) * 128
                                            + ks * 32 + (gB & 1) * 16)), bk);
                mma_f16(sacc[nb*2+0], qfrag[ks], bk[0], bk[1]);
                mma_f16(sacc[nb*2+1], qfrag[ks], bk[2], bk[3]);
            }
        }

        // scale (+ causal mask only on diagonal blocks), into log2 domain
        if (jb >= 2 * qb) {
            const int col0 = jb * 64;
            #pragma unroll
            for (int ni = 0; ni < 8; ++ni) {
                int cg = col0 + ni * 8 + c2;
                sacc[ni][0] = (cg     > row0) ? -1e30f : sacc[ni][0] * SCL;
                sacc[ni][1] = (cg + 1 > row0) ? -1e30f : sacc[ni][1] * SCL;
                sacc[ni][2] = (cg     > row1) ? -1e30f : sacc[ni][2] * SCL;
                sacc[ni][3] = (cg + 1 > row1) ? -1e30f : sacc[ni][3] * SCL;
            }
        } else {
            #pragma unroll
            for (int ni = 0; ni < 8; ++ni) {
                sacc[ni][0] *= SCL; sacc[ni][1] *= SCL;
                sacc[ni][2] *= SCL; sacc[ni][3] *= SCL;
            }
        }

        // row max (log2 domain; quad reduce)
        float rmax0 = -1e30f, rmax1 = -1e30f;
        #pragma unroll
        for (int ni = 0; ni < 8; ++ni) {
            rmax0 = fmaxf(rmax0, fmaxf(sacc[ni][0], sacc[ni][1]));
            rmax1 = fmaxf(rmax1, fmaxf(sacc[ni][2], sacc[ni][3]));
        }
        #pragma unroll
        for (int o = 1; o <= 2; o <<= 1) {
            rmax0 = fmaxf(rmax0, __shfl_xor_sync(0xffffffffu, rmax0, o));
            rmax1 = fmaxf(rmax1, __shfl_xor_sync(0xffffffffu, rmax1, o));
        }
        float mn0 = fmaxf(m0, rmax0), mn1 = fmaxf(m1, rmax1);
        float alpha0 = ex2f(m0 - mn0), alpha1 = ex2f(m1 - mn1);
        m0 = mn0; m1 = mn1;
        #pragma unroll
        for (int ni = 0; ni < 8; ++ni) {
            oacc[ni][0] *= alpha0; oacc[ni][1] *= alpha0;
            oacc[ni][2] *= alpha1; oacc[ni][3] *= alpha1;
        }

        // P = 2^(s - mn) directly as packed fp16
        uint32_t pw[8][2];
        #pragma unroll
        for (int ni = 0; ni < 8; ++ni) {
            pw[ni][0] = ex2_f16x2(h2(sacc[ni][0] - mn0, sacc[ni][1] - mn0));
            pw[ni][1] = ex2_f16x2(h2(sacc[ni][2] - mn1, sacc[ni][3] - mn1));
        }

        // O += P V ; row sums via ones-MMA
        float rsum[4] = {0.0f, 0.0f, 0.0f, 0.0f};
        #pragma unroll
        for (int kb = 0; kb < 4; ++kb) {
            uint32_t pa[4] = { pw[2*kb][0], pw[2*kb][1], pw[2*kb+1][0], pw[2*kb+1][1] };
            mma_f16(rsum, pa, ONES_H2, ONES_H2);
            #pragma unroll
            for (int nv = 0; nv < 4; ++nv) {
                uint32_t vv[4];
                ldsm_x4t(sV + SWZ((uint32_t)((kb * 16 + rowV) * 128 + (nv * 16 + colV) * 2)), vv);
                mma_f16(oacc[nv*2+0], pa, vv[0], vv[1]);
                mma_f16(oacc[nv*2+1], pa, vv[2], vv[3]);
            }
        }
        l0 = l0 * alpha0 + rsum[0];
        l1 = l1 * alpha1 + rsum[2];
    }

    // write ctx fp16
    float il0 = 1.0f / l0, il1 = 1.0f / l1;
    const size_t gr0 = (rows0 + qb * 128 + wq0 + g) * EMB + hoff;
    const size_t gr1 = gr0 + 8 * EMB;
    #pragma unroll
    for (int ni = 0; ni < 8; ++ni) {
        int col = ni * 8 + c2;
        *(uint32_t*)(O + gr0 + col) = h2(oacc[ni][0] * il0, oacc[ni][1] * il0);
        *(uint32_t*)(O + gr1 + col) = h2(oacc[ni][2] * il1, oacc[ni][3] * il1);
    }
}

// ==================== host launch ====================
extern "C" void kernel_launch(void* const* d_in, const int* in_sizes, int n_in,
                              void* d_out, int out_size)
{
    const float* x    = (const float*)d_in[0];
    const float* Wq   = (const float*)d_in[1];
    const float* Wk   = (const float*)d_in[2];
    const float* Wv   = (const float*)d_in[3];
    const float* Wo   = (const float*)d_in[4];
    const float* bo   = (const float*)d_in[5];
    const float* W1   = (const float*)d_in[6];
    const float* b1   = (const float*)d_in[7];
    const float* W2   = (const float*)d_in[8];
    const float* b2   = (const float*)d_in[9];
    const float* ln1s = (const float*)d_in[10];
    const float* ln1b = (const float*)d_in[11];
    const float* ln2s = (const float*)d_in[12];
    const float* ln2b = (const float*)d_in[13];
    float* out = (float*)d_out;

    __half *hh, *qkv, *ctx, *mid, *wqkv, *wo, *w1, *w2;
    float *x1;
    cudaGetSymbolAddress((void**)&hh,   g_h);
    cudaGetSymbolAddress((void**)&qkv,  g_qkv);
    cudaGetSymbolAddress((void**)&ctx,  g_ctx);
    cudaGetSymbolAddress((void**)&x1,   g_x1);
    cudaGetSymbolAddress((void**)&mid,  g_mid);
    cudaGetSymbolAddress((void**)&wqkv, g_wqkv);
    cudaGetSymbolAddress((void**)&wo,   g_wo);
    cudaGetSymbolAddress((void**)&w1,   g_w1);
    cudaGetSymbolAddress((void**)&w2,   g_w2);

    cudaFuncSetAttribute(gemm_kernel<1>, cudaFuncAttributeMaxDynamicSharedMemorySize, GEMM_SMEM);
    cudaFuncSetAttribute(gemm_kernel<2>, cudaFuncAttributeMaxDynamicSharedMemorySize, GEMM_SMEM);
    cudaFuncSetAttribute(gemm_kernel<3>, cudaFuncAttributeMaxDynamicSharedMemorySize, GEMM_SMEM);
    cudaFuncSetAttribute(attn_kernel, cudaFuncAttributeMaxDynamicSharedMemorySize, ATTN_SMEM);

    // side stream + events, created once
    static cudaStream_t s_side = []{
        cudaStream_t s; cudaStreamCreateWithFlags(&s, cudaStreamNonBlocking); return s; }();
    static cudaEvent_t ev_fork = []{
        cudaEvent_t e; cudaEventCreateWithFlags(&e, cudaEventDisableTiming); return e; }();
    static cudaEvent_t ev_a = []{
        cudaEvent_t e; cudaEventCreateWithFlags(&e, cudaEventDisableTiming); return e; }();
    static cudaEvent_t ev_b = []{
        cudaEvent_t e; cudaEventCreateWithFlags(&e, cudaEventDisableTiming); return e; }();

    // fork: all weight transposes on side stream (concurrent with LN1 — both latency-bound)
    cudaEventRecord(ev_fork, 0);
    cudaStreamWaitEvent(s_side, ev_fork, 0);
    transpose4_kernel<<<dim3(EMB/32, EMB/32, 4), 256, 0, s_side>>>(
        Wq, Wk, Wv, Wo, wqkv, wqkv + EMB*EMB, wqkv + 2*EMB*EMB, wo);
    cudaEventRecord(ev_a, s_side);
    transpose_half_kernel<<<dim3(FF/32,  EMB/32), 256, 0, s_side>>>(W1, w1, EMB, FF);
    transpose_half_kernel<<<dim3(EMB/32, FF/32),  256, 0, s_side>>>(W2, w2, FF, EMB);
    cudaEventRecord(ev_b, s_side);

    // main: LN1 concurrent with transpose4
    ln_half_kernel<<<TOK/4, 128>>>(x, ln1s, ln1b, hh);
    cudaStreamWaitEvent(0, ev_a, 0);

    // fused QKV projection -> fp16
    gemm_kernel<3><<<dim3(QKV_LD/128, TOK/128), 256, GEMM_SMEM>>>(
        hh, wqkv, nullptr, nullptr, nullptr, qkv, TOK, QKV_LD, EMB);

    // attention -> ctx fp16
    attn_kernel<<<dim3(SEQ/128, HEADS, BATCH), 256, ATTN_SMEM>>>(qkv, ctx);

    // Wo + bias + residual -> x1 (fp32)
    gemm_kernel<1><<<dim3(EMB/128, TOK/128), 256, GEMM_SMEM>>>(
        ctx, wo, bo, x, x1, nullptr, TOK, EMB, EMB);

    // LN2 -> h fp16
    ln_half_kernel<<<TOK/4, 128>>>(x1, ln2s, ln2b, hh);

    // join: FFN-up needs w1/w2
    cudaStreamWaitEvent(0, ev_b, 0);

    // FFN up + GELU -> mid fp16
    gemm_kernel<2><<<dim3(FF/128, TOK/128), 256, GEMM_SMEM>>>(
        hh, w1, b1, nullptr, nullptr, mid, TOK, FF, EMB);

    // FFN down + bias + residual -> out fp32
    gemm_kernel<1><<<dim3(EMB/128, TOK/128), 256, GEMM_SMEM>>>(
        mid, w2, b2, x1, out, nullptr, TOK, EMB, FF);
}

// round 12
// speedup vs baseline: 7.4857x; 1.0143x over previous
#include <cuda_runtime.h>
#include <cuda_fp16.h>
#include <math.h>
#include <float.h>
#include <stdint.h>

#define BATCH 2
#define SEQ   2048
#define TOK   (BATCH*SEQ)        // 4096
#define EMB   1024
#define HEADS 16
#define HD    64
#define FF    4096
#define QKV_LD 3072

// ==================== helpers ====================
__device__ __forceinline__ uint32_t smem_u32(const void* p) {
    uint32_t a;
    asm("{ .reg .u64 t; cvta.to.shared.u64 t, %1; cvt.u32.u64 %0, t; }" : "=r"(a) : "l"(p));
    return a;
}
#define SWZ(x) ((x) ^ (((x) >> 3) & 0x70))

__device__ __forceinline__ void cp_async16(uint32_t saddr, const void* gptr) {
    asm volatile("cp.async.cg.shared.global [%0], [%1], 16;" :: "r"(saddr), "l"(gptr));
}
#define CP_COMMIT() asm volatile("cp.async.commit_group;" ::: "memory")
#define CP_WAIT2()  asm volatile("cp.async.wait_group 2;" ::: "memory")
#define CP_WAIT1()  asm volatile("cp.async.wait_group 1;" ::: "memory")
#define CP_WAIT0()  asm volatile("cp.async.wait_group 0;" ::: "memory")

__device__ __forceinline__ void ldsm_x4(uint32_t addr, uint32_t r[4]) {
    asm volatile("ldmatrix.sync.aligned.m8n8.x4.shared.b16 {%0,%1,%2,%3}, [%4];"
                 : "=r"(r[0]), "=r"(r[1]), "=r"(r[2]), "=r"(r[3]) : "r"(addr));
}
__device__ __forceinline__ void ldsm_x4t(uint32_t addr, uint32_t r[4]) {
    asm volatile("ldmatrix.sync.aligned.m8n8.x4.trans.shared.b16 {%0,%1,%2,%3}, [%4];"
                 : "=r"(r[0]), "=r"(r[1]), "=r"(r[2]), "=r"(r[3]) : "r"(addr));
}
__device__ __forceinline__ void mma_f16(float c[4], const uint32_t a[4], const uint32_t b0, const uint32_t b1) {
    asm volatile("mma.sync.aligned.m16n8k16.row.col.f32.f16.f16.f32 "
                 "{%0,%1,%2,%3}, {%4,%5,%6,%7}, {%8,%9}, {%0,%1,%2,%3};"
                 : "+f"(c[0]), "+f"(c[1]), "+f"(c[2]), "+f"(c[3])
                 : "r"(a[0]), "r"(a[1]), "r"(a[2]), "r"(a[3]), "r"(b0), "r"(b1));
}
__device__ __forceinline__ uint32_t h2(float a, float b) {
    __half2 t = __floats2half2_rn(a, b);
    return *(uint32_t*)&t;
}
__device__ __forceinline__ uint32_t ex2_f16x2(uint32_t x) {
    uint32_t r;
    asm("ex2.approx.f16x2 %0, %1;" : "=r"(r) : "r"(x));
    return r;
}
__device__ __forceinline__ float ex2f(float x) {
    float r;
    asm("ex2.approx.f32 %0, %1;" : "=f"(r) : "f"(x));
    return r;
}
__device__ __forceinline__ float tanh_ap(float x) {
    float r;
    asm("tanh.approx.f32 %0, %1;" : "=f"(r) : "f"(x));
    return r;
}
__device__ __forceinline__ float gelu_t(float v) {
    float t = tanh_ap(0.7978845608028654f * (v + 0.044715f * v * v * v));
    return 0.5f * v * (1.0f + t);
}
#define ONES_H2 0x3C003C00u   // (1.0h, 1.0h)

// ==================== scratch (device globals) ====================
__device__ __half g_h[TOK*EMB];
__device__ __half g_qkv[TOK*QKV_LD];
__device__ __half g_ctx[TOK*EMB];
__device__ float  g_x1[TOK*EMB];
__device__ __half g_mid[TOK*FF];
__device__ __half g_wqkv[QKV_LD*EMB];   // [N=3072][K=1024]
__device__ __half g_wo[EMB*EMB];
__device__ __half g_w1[EMB*FF];         // [N=FF][K=EMB]
__device__ __half g_w2[FF*EMB];         // [N=EMB][K=FF]

// ==================== batched square transpose ====================
__global__ __launch_bounds__(256) void transpose4_kernel(
    const float* __restrict__ Wq, const float* __restrict__ Wk,
    const float* __restrict__ Wv, const float* __restrict__ Wo,
    __half* __restrict__ Tq, __half* __restrict__ Tk,
    __half* __restrict__ Tv, __half* __restrict__ To)
{
    __shared__ float t[32][33];
    const float* W = (blockIdx.z == 0) ? Wq : (blockIdx.z == 1) ? Wk : (blockIdx.z == 2) ? Wv : Wo;
    __half*      T = (blockIdx.z == 0) ? Tq : (blockIdx.z == 1) ? Tk : (blockIdx.z == 2) ? Tv : To;
    int tx = threadIdx.x & 31, ty = threadIdx.x >> 5;
    int k0 = blockIdx.y * 32, n0 = blockIdx.x * 32;
    #pragma unroll
    for (int i = 0; i < 4; i++)
        t[ty + i*8][tx] = W[(size_t)(k0 + ty + i*8) * EMB + n0 + tx];
    __syncthreads();
    #pragma unroll
    for (int i = 0; i < 4; i++)
        T[(size_t)(n0 + ty + i*8) * EMB + k0 + tx] = __float2half_rn(t[tx][ty + i*8]);
}

// ==================== rect transpose ====================
__global__ __launch_bounds__(256) void transpose_half_kernel(
    const float* __restrict__ W, __half* __restrict__ T, int K, int N)
{
    __shared__ float t[32][33];
    int tx = threadIdx.x & 31, ty = threadIdx.x >> 5;
    int k0 = blockIdx.y * 32, n0 = blockIdx.x * 32;
    #pragma unroll
    for (int i = 0; i < 4; i++)
        t[ty + i*8][tx] = W[(size_t)(k0 + ty + i*8) * N + n0 + tx];
    __syncthreads();
    #pragma unroll
    for (int i = 0; i < 4; i++)
        T[(size_t)(n0 + ty + i*8) * K + k0 + tx] = __float2half_rn(t[tx][ty + i*8]);
}

// ==================== LayerNorm -> fp16, warp-per-row ====================
__global__ __launch_bounds__(128) void ln_half_kernel(
    const float* __restrict__ X, const float* __restrict__ scale,
    const float* __restrict__ shift, __half* __restrict__ Y)
{
    const int lane = threadIdx.x & 31;
    const int row  = blockIdx.x * 4 + (threadIdx.x >> 5);
    const float* x = X + (size_t)row * EMB;

    float4 v[8];
    float s = 0.0f;
    #pragma unroll
    for (int i = 0; i < 8; i++) {
        v[i] = *(const float4*)(x + (i * 32 + lane) * 4);
        s += v[i].x + v[i].y + v[i].z + v[i].w;
    }
    #pragma unroll
    for (int o = 16; o > 0; o >>= 1) s += __shfl_xor_sync(0xffffffffu, s, o);
    float mean = s * (1.0f / EMB);

    float sq = 0.0f;
    #pragma unroll
    for (int i = 0; i < 8; i++) {
        v[i].x -= mean; v[i].y -= mean; v[i].z -= mean; v[i].w -= mean;
        sq += v[i].x*v[i].x + v[i].y*v[i].y + v[i].z*v[i].z + v[i].w*v[i].w;
    }
    #pragma unroll
    for (int o = 16; o > 0; o >>= 1) sq += __shfl_xor_sync(0xffffffffu, sq, o);
    float rstd = rsqrtf(sq * (1.0f / EMB) + 1e-5f);

    #pragma unroll
    for (int i = 0; i < 8; i++) {
        int c0 = (i * 32 + lane) * 4;
        float4 sc = *(const float4*)(scale + c0);
        float4 sh = *(const float4*)(shift + c0);
        size_t o = (size_t)row * EMB + c0;
        *(uint32_t*)(Y + o)     = h2(sc.x * v[i].x * rstd + sh.x, sc.y * v[i].y * rstd + sh.y);
        *(uint32_t*)(Y + o + 2) = h2(sc.z * v[i].z * rstd + sh.z, sc.w * v[i].w * rstd + sh.w);
    }
}

// ==================== fp16 mma.sync GEMM, 3-stage cp.async, 2 CTAs/SM ====================
// C[M][N] = A[M][K] @ B[N][K]^T. CTA tile MT x 128 (MT = 128 or 64), K-chunk 64.
// 8 warps: 2(M) x 4(N); warp tile (MT/2) x 32.
// EPI: 1 +bias+res -> fp32; 2 +bias GELU -> fp16; 3 plain -> fp16
template<int EPI, int MT>
__global__ __launch_bounds__(256, 2)
void gemm_kernel(
    const __half* __restrict__ A, const __half* __restrict__ B,
    const float* __restrict__ bias, const float* __restrict__ res,
    float* __restrict__ C, __half* __restrict__ Ch,
    int M, int N, int K)
{
    constexpr int MI = MT / 32;                 // m16 frags per warp (4 or 2)
    constexpr int A_BYTES = MT * 128;           // A tile bytes per stage
    constexpr int STG = A_BYTES + 16384;        // stage bytes (A + B)

    extern __shared__ char smraw[];
    const uint32_t sbase = smem_u32(smraw);
    const int tid = threadIdx.x;
    const int bm = blockIdx.y, bn = blockIdx.x;

    const int w = tid >> 5, lane = tid & 31;
    const int wm = w & 1, wn = w >> 1;

    const int rowA = (lane & 7) + ((lane >> 3) & 1) * 8;
    const int chA  = (lane >> 4) & 1;
    const int gB   = lane >> 3;
    const int rB   = lane & 7;

    float acc[MI][4][4];
    #pragma unroll
    for (int i = 0; i < MI; i++)
        #pragma unroll
        for (int j = 0; j < 4; j++)
            #pragma unroll
            for (int q = 0; q < 4; q++) acc[i][j][q] = 0.0f;

    const int nchunk = K >> 6;

    auto stage = [&](int s, int c) {
        const uint32_t sb = sbase + s * STG;
        // A tile: MT rows x 64 halfs
        #pragma unroll
        for (int j = 0; j < MT / 32; ++j) {
            int idx = tid + j * 256;
            int r = idx >> 3, seg = idx & 7;
            cp_async16(sb + SWZ((uint32_t)(r * 128 + seg * 16)),
                       A + (size_t)(bm * MT + r) * K + c * 64 + seg * 8);
        }
        // B tile: 128 rows x 64 halfs
        #pragma unroll
        for (int j = 0; j < 4; ++j) {
            int idx = tid + j * 256;
            int r = idx >> 3, seg = idx & 7;
            cp_async16(sb + A_BYTES + SWZ((uint32_t)(r * 128 + seg * 16)),
                       B + (size_t)(bn * 128 + r) * K + c * 64 + seg * 8);
        }
    };

    stage(0, 0); CP_COMMIT();
    if (nchunk > 1) { stage(1, 1); CP_COMMIT(); }

    for (int c = 0; c < nchunk; ++c) {
        const int s = c % 3;
        if (c == nchunk - 1) { CP_WAIT0(); } else { CP_WAIT1(); }
        __syncthreads();
        if (c + 2 < nchunk) { stage((c + 2) % 3, c + 2); CP_COMMIT(); }

        const uint32_t sA = sbase + s * STG;
        const uint32_t sB = sA + A_BYTES;

        #pragma unroll
        for (int ks = 0; ks < 4; ++ks) {
            uint32_t ah[MI][4], bh[2][4];
            #pragma unroll
            for (int mi = 0; mi < MI; ++mi) {
                uint32_t off = (uint32_t)((wm * (MT/2) + mi * 16 + rowA) * 128 + (ks * 2 + chA) * 16);
                ldsm_x4(sA + SWZ(off), ah[mi]);
            }
            #pragma unroll
            for (int nb = 0; nb < 2; ++nb) {
                uint32_t off = (uint32_t)((wn * 32 + nb * 16 + (gB >> 1) * 8 + rB) * 128
                                          + ks * 32 + (gB & 1) * 16);
                ldsm_x4(sB + SWZ(off), bh[nb]);
            }
            #pragma unroll
            for (int mi = 0; mi < MI; ++mi)
                #pragma unroll
                for (int ni = 0; ni < 4; ++ni)
                    mma_f16(acc[mi][ni], ah[mi], bh[ni>>1][(ni&1)*2], bh[ni>>1][(ni&1)*2+1]);
        }
    }

    // epilogue
    const int g = lane >> 2, tid4 = lane & 3;
    #pragma unroll
    for (int mi = 0; mi < MI; ++mi) {
        #pragma unroll
        for (int half_ = 0; half_ < 2; ++half_) {
            const size_t row = (size_t)(bm * MT + wm * (MT/2) + mi * 16 + g + half_ * 8);
            #pragma unroll
            for (int ni = 0; ni < 4; ++ni) {
                const int col = bn * 128 + wn * 32 + ni * 8 + tid4 * 2;
                float v0 = acc[mi][ni][half_ * 2 + 0];
                float v1 = acc[mi][ni][half_ * 2 + 1];
                if (EPI == 1) {
                    float2 rv = *(const float2*)(res + row * N + col);
                    float2 bv = *(const float2*)(bias + col);
                    *(float2*)(C + row * N + col) =
                        make_float2(v0 + bv.x + rv.x, v1 + bv.y + rv.y);
                } else if (EPI == 2) {
                    float2 bv = *(const float2*)(bias + col);
                    *(uint32_t*)(Ch + row * N + col) =
                        h2(gelu_t(v0 + bv.x), gelu_t(v1 + bv.y));
                } else {
                    *(uint32_t*)(Ch + row * N + col) = h2(v0, v1);
                }
            }
        }
    }
}

#define GEMM_SMEM_128 (3 * (128*128 + 16384))
#define GEMM_SMEM_64  (3 * ( 64*128 + 16384))

// ==================== fp16 HMMA causal flash attention, 3-stage KV ====================
#define ATTN_SMEM 65536

__global__ __launch_bounds__(256, 2) void attn_kernel(
    const __half* __restrict__ QKV, __half* __restrict__ O)
{
    extern __shared__ char smraw[];
    const uint32_t sbase = smem_u32(smraw);
    const uint32_t sQ = sbase;

    const int qb = gridDim.x - 1 - blockIdx.x;    // heavy tiles first
    const int h = blockIdx.y, b = blockIdx.z;
    const int tid = threadIdx.x;
    const int w = tid >> 5, lane = tid & 31;
    const int wq0 = w * 16;
    const int g = lane >> 2, c2 = (lane & 3) * 2;
    const size_t rows0 = (size_t)b * SEQ;
    const int hoff = h * HD;

    const int rowA = (lane & 7) + ((lane >> 3) & 1) * 8;
    const int chA  = (lane >> 4) & 1;
    const int gB   = lane >> 3;
    const int rB   = lane & 7;
    const int rowV = lane & 15;
    const int colV = (lane >> 4) * 8;

    for (int i = tid; i < 1024; i += 256) {
        int r = i >> 3, seg = i & 7;
        *(uint4*)(smraw + SWZ((uint32_t)(r * 128 + seg * 16))) =
            *(const uint4*)(QKV + (rows0 + qb * 128 + r) * QKV_LD + hoff + seg * 8);
    }

    auto stageKV = [&](int s, int jb) {
        uint32_t sb = sbase + 16384u + (uint32_t)s * 16384u;
        for (int i = tid; i < 512; i += 256) {
            int r = i >> 3, seg = i & 7;
            const size_t go = (rows0 + jb * 64 + r) * QKV_LD + hoff + seg * 8;
            uint32_t dst = SWZ((uint32_t)(r * 128 + seg * 16));
            cp_async16(sb + dst,         QKV + go + EMB);
            cp_async16(sb + 8192u + dst, QKV + go + 2 * EMB);
        }
    };

    float oacc[8][4];
    #pragma unroll
    for (int i = 0; i < 8; i++)
        #pragma unroll
        for (int q = 0; q < 4; q++) oacc[i][q] = 0.0f;
    float m0 = -1e30f, m1 = -1e30f, l0 = 0.0f, l1 = 0.0f;

    uint32_t qfrag[4][4];

    const int row0 = qb * 128 + wq0 + g;
    const int row1 = row0 + 8;
    const int njb = 2 * qb + 2;
    const float SCL = 0.125f * 1.44269504f;

    stageKV(0, 0); CP_COMMIT();
    if (njb > 1) { stageKV(1, 1); CP_COMMIT(); }

    for (int jb = 0; jb < njb; ++jb) {
        if (jb == njb - 1)      { CP_WAIT0(); }
        else if (jb == njb - 2) { CP_WAIT1(); }
        else                    { CP_WAIT2(); }
        __syncthreads();
        if (jb + 2 < njb) { stageKV((jb + 2) % 3, jb + 2); CP_COMMIT(); }

        if (jb == 0) {
            #pragma unroll
            for (int ks = 0; ks < 4; ++ks)
                ldsm_x4(sQ + SWZ((uint32_t)((wq0 + rowA) * 128 + (ks * 2 + chA) * 16)), qfrag[ks]);
        }

        const uint32_t sK = sbase + 16384u + (uint32_t)(jb % 3) * 16384u;
        const uint32_t sV = sK + 8192u;

        float sacc[8][4];
        #pragma unroll
        for (int i = 0; i < 8; i++)
            #pragma unroll
            for (int q = 0; q < 4; q++) sacc[i][q] = 0.0f;

        #pragma unroll
        for (int ks = 0; ks < 4; ++ks) {
            #pragma unroll
            for (int nb = 0; nb < 4; ++nb) {
                uint32_t bk[4];
                ldsm_x4(sK + SWZ((uint32_t)((nb * 16 + (gB >> 1) * 8 + rB) * 128
                                            + ks * 32 + (gB & 1) * 16)), bk);
                mma_f16(sacc[nb*2+0], qfrag[ks], bk[0], bk[1]);
                mma_f16(sacc[nb*2+1], qfrag[ks], bk[2], bk[3]);
            }
        }

        if (jb >= 2 * qb) {
            const int col0 = jb * 64;
            #pragma unroll
            for (int ni = 0; ni < 8; ++ni) {
                int cg = col0 + ni * 8 + c2;
                sacc[ni][0] = (cg     > row0) ? -1e30f : sacc[ni][0] * SCL;
                sacc[ni][1] = (cg + 1 > row0) ? -1e30f : sacc[ni][1] * SCL;
                sacc[ni][2] = (cg     > row1) ? -1e30f : sacc[ni][2] * SCL;
                sacc[ni][3] = (cg + 1 > row1) ? -1e30f : sacc[ni][3] * SCL;
            }
        } else {
            #pragma unroll
            for (int ni = 0; ni < 8; ++ni) {
                sacc[ni][0] *= SCL; sacc[ni][1] *= SCL;
                sacc[ni][2] *= SCL; sacc[ni][3] *= SCL;
            }
        }

        float rmax0 = -1e30f, rmax1 = -1e30f;
        #pragma unroll
        for (int ni = 0; ni < 8; ++ni) {
            rmax0 = fmaxf(rmax0, fmaxf(sacc[ni][0], sacc[ni][1]));
            rmax1 = fmaxf(rmax1, fmaxf(sacc[ni][2], sacc[ni][3]));
        }
        #pragma unroll
        for (int o = 1; o <= 2; o <<= 1) {
            rmax0 = fmaxf(rmax0, __shfl_xor_sync(0xffffffffu, rmax0, o));
            rmax1 = fmaxf(rmax1, __shfl_xor_sync(0xffffffffu, rmax1, o));
        }
        float mn0 = fmaxf(m0, rmax0), mn1 = fmaxf(m1, rmax1);
        float alpha0 = ex2f(m0 - mn0), alpha1 = ex2f(m1 - mn1);
        m0 = mn0; m1 = mn1;
        #pragma unroll
        for (int ni = 0; ni < 8; ++ni) {
            oacc[ni][0] *= alpha0; oacc[ni][1] *= alpha0;
            oacc[ni][2] *= alpha1; oacc[ni][3] *= alpha1;
        }

        uint32_t pw[8][2];
        #pragma unroll
        for (int ni = 0; ni < 8; ++ni) {
            pw[ni][0] = ex2_f16x2(h2(sacc[ni][0] - mn0, sacc[ni][1] - mn0));
            pw[ni][1] = ex2_f16x2(h2(sacc[ni][2] - mn1, sacc[ni][3] - mn1));
        }

        float rsum[4] = {0.0f, 0.0f, 0.0f, 0.0f};
        #pragma unroll
        for (int kb = 0; kb < 4; ++kb) {
            uint32_t pa[4] = { pw[2*kb][0], pw[2*kb][1], pw[2*kb+1][0], pw[2*kb+1][1] };
            mma_f16(rsum, pa, ONES_H2, ONES_H2);
            #pragma unroll
            for (int nv = 0; nv < 4; ++nv) {
                uint32_t vv[4];
                ldsm_x4t(sV + SWZ((uint32_t)((kb * 16 + rowV) * 128 + (nv * 16 + colV) * 2)), vv);
                mma_f16(oacc[nv*2+0], pa, vv[0], vv[1]);
                mma_f16(oacc[nv*2+1], pa, vv[2], vv[3]);
            }
        }
        l0 = l0 * alpha0 + rsum[0];
        l1 = l1 * alpha1 + rsum[2];
    }

    float il0 = 1.0f / l0, il1 = 1.0f / l1;
    const size_t gr0 = (rows0 + qb * 128 + wq0 + g) * EMB + hoff;
    const size_t gr1 = gr0 + 8 * EMB;
    #pragma unroll
    for (int ni = 0; ni < 8; ++ni) {
        int col = ni * 8 + c2;
        *(uint32_t*)(O + gr0 + col) = h2(oacc[ni][0] * il0, oacc[ni][1] * il0);
        *(uint32_t*)(O + gr1 + col) = h2(oacc[ni][2] * il1, oacc[ni][3] * il1);
    }
}

// ==================== host launch ====================
extern "C" void kernel_launch(void* const* d_in, const int* in_sizes, int n_in,
                              void* d_out, int out_size)
{
    const float* x    = (const float*)d_in[0];
    const float* Wq   = (const float*)d_in[1];
    const float* Wk   = (const float*)d_in[2];
    const float* Wv   = (const float*)d_in[3];
    const float* Wo   = (const float*)d_in[4];
    const float* bo   = (const float*)d_in[5];
    const float* W1   = (const float*)d_in[6];
    const float* b1   = (const float*)d_in[7];
    const float* W2   = (const float*)d_in[8];
    const float* b2   = (const float*)d_in[9];
    const float* ln1s = (const float*)d_in[10];
    const float* ln1b = (const float*)d_in[11];
    const float* ln2s = (const float*)d_in[12];
    const float* ln2b = (const float*)d_in[13];
    float* out = (float*)d_out;

    __half *hh, *qkv, *ctx, *mid, *wqkv, *wo, *w1, *w2;
    float *x1;
    cudaGetSymbolAddress((void**)&hh,   g_h);
    cudaGetSymbolAddress((void**)&qkv,  g_qkv);
    cudaGetSymbolAddress((void**)&ctx,  g_ctx);
    cudaGetSymbolAddress((void**)&x1,   g_x1);
    cudaGetSymbolAddress((void**)&mid,  g_mid);
    cudaGetSymbolAddress((void**)&wqkv, g_wqkv);
    cudaGetSymbolAddress((void**)&wo,   g_wo);
    cudaGetSymbolAddress((void**)&w1,   g_w1);
    cudaGetSymbolAddress((void**)&w2,   g_w2);

    cudaFuncSetAttribute(gemm_kernel<1,64>,  cudaFuncAttributeMaxDynamicSharedMemorySize, GEMM_SMEM_64);
    cudaFuncSetAttribute(gemm_kernel<2,128>, cudaFuncAttributeMaxDynamicSharedMemorySize, GEMM_SMEM_128);
    cudaFuncSetAttribute(gemm_kernel<3,128>, cudaFuncAttributeMaxDynamicSharedMemorySize, GEMM_SMEM_128);
    cudaFuncSetAttribute(attn_kernel, cudaFuncAttributeMaxDynamicSharedMemorySize, ATTN_SMEM);

    static cudaStream_t s_side = []{
        cudaStream_t s; cudaStreamCreateWithFlags(&s, cudaStreamNonBlocking); return s; }();
    static cudaEvent_t ev_fork = []{
        cudaEvent_t e; cudaEventCreateWithFlags(&e, cudaEventDisableTiming); return e; }();
    static cudaEvent_t ev_a = []{
        cudaEvent_t e; cudaEventCreateWithFlags(&e, cudaEventDisableTiming); return e; }();
    static cudaEvent_t ev_b = []{
        cudaEvent_t e; cudaEventCreateWithFlags(&e, cudaEventDisableTiming); return e; }();

    // fork: weight transposes on side stream, concurrent with LN1
    cudaEventRecord(ev_fork, 0);
    cudaStreamWaitEvent(s_side, ev_fork, 0);
    transpose4_kernel<<<dim3(EMB/32, EMB/32, 4), 256, 0, s_side>>>(
        Wq, Wk, Wv, Wo, wqkv, wqkv + EMB*EMB, wqkv + 2*EMB*EMB, wo);
    cudaEventRecord(ev_a, s_side);
    transpose_half_kernel<<<dim3(FF/32,  EMB/32), 256, 0, s_side>>>(W1, w1, EMB, FF);
    transpose_half_kernel<<<dim3(EMB/32, FF/32),  256, 0, s_side>>>(W2, w2, FF, EMB);
    cudaEventRecord(ev_b, s_side);

    // main: LN1 concurrent with transpose4
    ln_half_kernel<<<TOK/4, 128>>>(x, ln1s, ln1b, hh);
    cudaStreamWaitEvent(0, ev_a, 0);

    // fused QKV projection -> fp16 (MT=128)
    gemm_kernel<3,128><<<dim3(QKV_LD/128, TOK/128), 256, GEMM_SMEM_128>>>(
        hh, wqkv, nullptr, nullptr, nullptr, qkv, TOK, QKV_LD, EMB);

    // attention -> ctx fp16
    attn_kernel<<<dim3(SEQ/128, HEADS, BATCH), 256, ATTN_SMEM>>>(qkv, ctx);

    // Wo + bias + residual -> x1 (MT=64 for better SM fill: 512 CTAs)
    gemm_kernel<1,64><<<dim3(EMB/128, TOK/64), 256, GEMM_SMEM_64>>>(
        ctx, wo, bo, x, x1, nullptr, TOK, EMB, EMB);

    // LN2 -> h fp16
    ln_half_kernel<<<TOK/4, 128>>>(x1, ln2s, ln2b, hh);

    cudaStreamWaitEvent(0, ev_b, 0);

    // FFN up + GELU -> mid fp16 (MT=128)
    gemm_kernel<2,128><<<dim3(FF/128, TOK/128), 256, GEMM_SMEM_128>>>(
        hh, w1, b1, nullptr, nullptr, mid, TOK, FF, EMB);

    // FFN down + bias + residual -> out (MT=64: 512 CTAs)
    gemm_kernel<1,64><<<dim3(EMB/128, TOK/64), 256, GEMM_SMEM_64>>>(
        mid, w2, b2, x1, out, nullptr, TOK, EMB, FF);
}